// round 1
// baseline (speedup 1.0000x reference)
#include <cuda_runtime.h>
#include <float.h>
#include <math.h>

// ---------------- problem constants ----------------
constexpr int BB   = 16;
constexpr int TT   = 750;
constexpr int CC   = 2048;   // embed channels
constexpr int CIN  = 1024;   // per-stream input channels
constexpr int CLS  = 20;
constexpr int NPOS = BB * TT;          // 12000
constexpr int KNB  = 150;              // T // 5
constexpr int KB2  = 37;               // T // 20
constexpr int KDIM = CIN * 3;          // 3072 per stream

// output layout (concatenated f32)
constexpr long OFF_VS  = 0;
constexpr long OFF_EA  = OFF_VS  + (long)BB * CLS;             // 320
constexpr long OFF_EB  = OFF_EA  + (long)BB * KNB * CC;
constexpr long OFF_HA  = OFF_EB  + (long)BB * KNB * CC;
constexpr long OFF_HB  = OFF_HA  + (long)BB * KB2 * CC;
constexpr long OFF_IDX = OFF_HB  + (long)BB * KB2 * CC;
constexpr long OFF_ACT = OFF_IDX + (long)BB * KNB;
constexpr long OFF_CAS = OFF_ACT + (long)NPOS;
constexpr long OFF_EMB = OFF_CAS + (long)NPOS * CLS;

// ---------------- device scratch ----------------
__device__ float g_wt_rgb[(long)KDIM * CC];    // [k=tau*1024+i][c]
__device__ float g_wt_flow[(long)KDIM * CC];
__device__ int   g_sel_idx[4 * BB * KNB];      // EA, EB, HA, HB indices
__device__ float g_cls_mean[BB * CLS];

// ---------------- weight repack: w[c][i][tau] -> wt[tau*1024+i][c] ----------------
__global__ void repack_kernel(const float* __restrict__ w, float* __restrict__ wt) {
    __shared__ float tile[32][33];
    int kp0 = blockIdx.x * 32;   // source col base, k' = i*3+tau
    int c0  = blockIdx.y * 32;
    int tx = threadIdx.x, ty = threadIdx.y;   // 32 x 8
    #pragma unroll
    for (int j = 0; j < 32; j += 8) {
        int c = c0 + ty + j;
        tile[ty + j][tx] = w[(long)c * KDIM + kp0 + tx];
    }
    __syncthreads();
    #pragma unroll
    for (int j = 0; j < 32; j += 8) {
        int kp = kp0 + ty + j;
        int k  = (kp % 3) * CIN + (kp / 3);
        wt[(long)k * CC + c0 + tx] = tile[tx][ty + j];
    }
}

// ---------------- conv-as-GEMM (fp32 SIMT, 128x128 tile, BK=16) ----------------
// emb[n][c] (op) relu( sum_{tau,i} wt[tau*1024+i][c] * x[n+tau-1][chanOff+i] + bias[c] )
__global__ __launch_bounds__(256)
void conv_gemm_kernel(const float* __restrict__ x, const float* __restrict__ wt,
                      const float* __restrict__ bias, float* __restrict__ emb,
                      int chanOff, int addMode) {
    __shared__ float As[16][128];
    __shared__ float Bs[16][128];

    const int tid = threadIdx.x;
    const int n0 = blockIdx.x * 128;
    const int c0 = blockIdx.y * 128;
    const int tx = tid & 15;       // position group
    const int ty = tid >> 4;       // channel group

    // B-load descriptors: each thread loads float4 along i for 2 positions
    const int nlA = tid >> 2;          // 0..63
    const int nlB = nlA + 64;          // 64..127
    const int i4  = (tid & 3) * 4;
    const int nA = n0 + nlA, nB = n0 + nlB;
    const bool vA = nA < NPOS, vB = nB < NPOS;
    const int tA = nA % TT, tB = nB % TT;

    // A-load descriptors
    const int arow = tid >> 5;          // 0..7 (+8)
    const int acol = (tid & 31) * 4;

    float acc[8][8];
    #pragma unroll
    for (int i = 0; i < 8; ++i)
        #pragma unroll
        for (int j = 0; j < 8; ++j) acc[i][j] = 0.f;

    for (int tau = 0; tau < 3; ++tau) {
        const bool rvA = vA && (tA + tau - 1 >= 0) && (tA + tau - 1 < TT);
        const bool rvB = vB && (tB + tau - 1 >= 0) && (tB + tau - 1 < TT);
        const int rowA = max(nA + tau - 1, 0);
        const int rowB = max(nB + tau - 1, 0);
        const float* xA = x + (long)rowA * CC + chanOff + i4;
        const float* xB = x + (long)rowB * CC + chanOff + i4;
        const float* wbase = wt + (long)(tau * CIN) * CC + c0;

        for (int i0 = 0; i0 < CIN; i0 += 16) {
            float4 a0 = *(const float4*)(wbase + (long)(i0 + arow) * CC + acol);
            float4 a1 = *(const float4*)(wbase + (long)(i0 + arow + 8) * CC + acol);
            float4 f0 = make_float4(0.f, 0.f, 0.f, 0.f);
            float4 f1 = make_float4(0.f, 0.f, 0.f, 0.f);
            if (rvA) f0 = *(const float4*)(xA + i0);
            if (rvB) f1 = *(const float4*)(xB + i0);

            *(float4*)&As[arow][acol]     = a0;
            *(float4*)&As[arow + 8][acol] = a1;
            Bs[i4 + 0][nlA] = f0.x; Bs[i4 + 1][nlA] = f0.y;
            Bs[i4 + 2][nlA] = f0.z; Bs[i4 + 3][nlA] = f0.w;
            Bs[i4 + 0][nlB] = f1.x; Bs[i4 + 1][nlB] = f1.y;
            Bs[i4 + 2][nlB] = f1.z; Bs[i4 + 3][nlB] = f1.w;
            __syncthreads();

            #pragma unroll
            for (int kk = 0; kk < 16; ++kk) {
                float4 t0 = *(const float4*)&As[kk][ty * 8];
                float4 t1 = *(const float4*)&As[kk][ty * 8 + 4];
                float4 u0 = *(const float4*)&Bs[kk][tx * 8];
                float4 u1 = *(const float4*)&Bs[kk][tx * 8 + 4];
                float ar[8] = {t0.x, t0.y, t0.z, t0.w, t1.x, t1.y, t1.z, t1.w};
                float br[8] = {u0.x, u0.y, u0.z, u0.w, u1.x, u1.y, u1.z, u1.w};
                #pragma unroll
                for (int i = 0; i < 8; ++i)
                    #pragma unroll
                    for (int j = 0; j < 8; ++j)
                        acc[i][j] = fmaf(ar[i], br[j], acc[i][j]);
            }
            __syncthreads();
        }
    }

    float bv[8];
    #pragma unroll
    for (int i = 0; i < 8; ++i) bv[i] = bias[c0 + ty * 8 + i];

    #pragma unroll
    for (int j = 0; j < 8; ++j) {
        int n = n0 + tx * 8 + j;
        if (n >= NPOS) continue;
        float* dst = emb + (long)n * CC + c0 + ty * 8;
        float4 r0, r1;
        r0.x = fmaxf(acc[0][j] + bv[0], 0.f);
        r0.y = fmaxf(acc[1][j] + bv[1], 0.f);
        r0.z = fmaxf(acc[2][j] + bv[2], 0.f);
        r0.w = fmaxf(acc[3][j] + bv[3], 0.f);
        r1.x = fmaxf(acc[4][j] + bv[4], 0.f);
        r1.y = fmaxf(acc[5][j] + bv[5], 0.f);
        r1.z = fmaxf(acc[6][j] + bv[6], 0.f);
        r1.w = fmaxf(acc[7][j] + bv[7], 0.f);
        if (addMode) {
            float4 o0 = *(const float4*)dst;
            float4 o1 = *(const float4*)(dst + 4);
            r0.x += o0.x; r0.y += o0.y; r0.z += o0.z; r0.w += o0.w;
            r1.x += o1.x; r1.y += o1.y; r1.z += o1.z; r1.w += o1.w;
        }
        *(float4*)dst = r0;
        *(float4*)(dst + 4) = r1;
    }
}

// ---------------- cas + actionness: cas[n][cls] = relu(<emb[n], wcls[cls]>) ----------------
__global__ void cas_kernel(const float* __restrict__ wcls, float* __restrict__ out) {
    __shared__ float sm[CLS];
    const int n = blockIdx.x;
    const int tid = threadIdx.x;
    const int w = tid >> 5, lane = tid & 31;   // 20 warps
    const float* er = out + OFF_EMB + (long)n * CC;
    const float* wr = wcls + (long)w * CC;
    float s = 0.f;
    for (int j = lane; j < CC; j += 32) s += er[j] * wr[j];
    #pragma unroll
    for (int o = 16; o > 0; o >>= 1) s += __shfl_down_sync(0xffffffffu, s, o);
    if (lane == 0) {
        float cv = fmaxf(s, 0.f);
        out[OFF_CAS + (long)n * CLS + w] = cv;
        sm[w] = cv;
    }
    __syncthreads();
    if (tid == 0) {
        float a = 0.f;
        #pragma unroll
        for (int c = 0; c < CLS; ++c) a += sm[c];
        out[OFF_ACT + n] = a;
    }
}

// ---------------- in-block bitonic sort (ascending, 1024 elems, 256 threads) ----------------
__device__ inline void bitonic1024(float* s, int tid) {
    for (int k = 2; k <= 1024; k <<= 1) {
        for (int j = k >> 1; j > 0; j >>= 1) {
            __syncthreads();
            for (int i = tid; i < 1024; i += 256) {
                int ixj = i ^ j;
                if (ixj > i) {
                    bool up = ((i & k) == 0);
                    float a = s[i], c = s[ixj];
                    if ((a > c) == up) { s[i] = c; s[ixj] = a; }
                }
            }
        }
    }
    __syncthreads();
}

// ---------------- block top-k (value desc, index asc tie-break, matches lax.top_k) ----------------
__device__ inline void block_topk(float* work, float* rv, int* ri, int k,
                                  int* dst_idx, float* dst_idx_f, int tid) {
    for (int r = 0; r < k; ++r) {
        float bv = -FLT_MAX; int bi = 0x7fffffff;
        for (int t = tid; t < TT; t += 256) {
            float v = work[t];
            if (v > bv) { bv = v; bi = t; }  // ascending t => ties keep smaller index
        }
        rv[tid] = bv; ri[tid] = bi;
        __syncthreads();
        for (int s = 128; s > 0; s >>= 1) {
            if (tid < s) {
                float ov = rv[tid + s]; int oi = ri[tid + s];
                if (ov > rv[tid] || (ov == rv[tid] && oi < ri[tid])) {
                    rv[tid] = ov; ri[tid] = oi;
                }
            }
            __syncthreads();
        }
        int win = ri[0];
        if (tid == 0) {
            dst_idx[r] = win;
            if (dst_idx_f) dst_idx_f[r] = (float)win;
            work[win] = -FLT_MAX;
        }
        __syncthreads();
    }
}

// ---------------- per-batch: median, morphology, 4 top-k selections ----------------
__global__ void analysis_kernel(float* __restrict__ out) {
    __shared__ float act[TT];
    __shared__ float binv[TT];
    __shared__ float work[TT];
    __shared__ float sbuf[1024];
    __shared__ float rv[256];
    __shared__ int   ri[256];
    __shared__ float s_med, s_max;

    const int b = blockIdx.x, tid = threadIdx.x;
    const float* actg = out + OFF_ACT + (long)b * TT;
    for (int t = tid; t < TT; t += 256) act[t] = actg[t];
    for (int i = tid; i < 1024; i += 256) sbuf[i] = (i < TT) ? actg[i] : FLT_MAX;
    __syncthreads();
    bitonic1024(sbuf, tid);
    if (tid == 0) {
        s_med = 0.5f * (sbuf[374] + sbuf[375]);  // jnp.median of 750
        s_max = sbuf[TT - 1];
    }
    __syncthreads();
    const float med = s_med, mx = s_max;
    for (int t = tid; t < TT; t += 256) binv[t] = (act[t] > med) ? 1.f : 0.f;

    // (0) top-k actionness -> EA + idx output
    for (int t = tid; t < TT; t += 256) work[t] = act[t];
    __syncthreads();
    block_topk(work, rv, ri, KNB, &g_sel_idx[(0 * BB + b) * KNB],
               out + OFF_IDX + (long)b * KNB, tid);

    // (1) top-k (max - actionness) -> EB
    for (int t = tid; t < TT; t += 256) work[t] = mx - act[t];
    __syncthreads();
    block_topk(work, rv, ri, KNB, &g_sel_idx[(1 * BB + b) * KNB], nullptr, tid);

    // (2) inner = erode3 - erode6 ; top-k act*inner -> HA
    for (int t = tid; t < TT; t += 256) {
        float e3 = 0.f, e6 = 0.f;
        if (t >= 1 && t <= TT - 2)
            e3 = fminf(binv[t - 1], fminf(binv[t], binv[t + 1]));
        if (t >= 3 && t <= TT - 3) {
            float m = binv[t - 3];
            m = fminf(m, binv[t - 2]); m = fminf(m, binv[t - 1]);
            m = fminf(m, binv[t]);     m = fminf(m, binv[t + 1]);
            m = fminf(m, binv[t + 2]);
            e6 = m;
        }
        work[t] = act[t] * (e3 - e6);
    }
    __syncthreads();
    block_topk(work, rv, ri, KB2, &g_sel_idx[(2 * BB + b) * KNB], nullptr, tid);

    // (3) outer = dilate6 - dilate3 ; top-k act*outer -> HB
    for (int t = tid; t < TT; t += 256) {
        float d3 = 0.f, d6 = 0.f;
        #pragma unroll
        for (int dt = -1; dt <= 1; ++dt) {
            int u = t + dt;
            if (u >= 0 && u < TT) d3 = fmaxf(d3, binv[u]);
        }
        #pragma unroll
        for (int dt = -2; dt <= 3; ++dt) {
            int u = t + dt;
            if (u >= 0 && u < TT) d6 = fmaxf(d6, binv[u]);
        }
        work[t] = act[t] * (d6 - d3);
    }
    __syncthreads();
    block_topk(work, rv, ri, KB2, &g_sel_idx[(3 * BB + b) * KNB], nullptr, tid);
}

// ---------------- gather EA / EB / HA / HB rows from embeddings ----------------
__global__ void gather_kernel(float* __restrict__ out) {
    const int rowsPerB = KNB + KNB + KB2 + KB2;  // 374
    const int b = blockIdx.x / rowsPerB;
    int r = blockIdx.x % rowsPerB;
    int arr, rr; long dstOff; int kcnt;
    if (r < KNB)            { arr = 0; rr = r;              dstOff = OFF_EA; kcnt = KNB; }
    else if (r < 2 * KNB)   { arr = 1; rr = r - KNB;        dstOff = OFF_EB; kcnt = KNB; }
    else if (r < 2*KNB+KB2) { arr = 2; rr = r - 2 * KNB;    dstOff = OFF_HA; kcnt = KB2; }
    else                    { arr = 3; rr = r - 2*KNB - KB2; dstOff = OFF_HB; kcnt = KB2; }
    const int tsel = g_sel_idx[(arr * BB + b) * KNB + rr];
    const float* src = out + OFF_EMB + ((long)b * TT + tsel) * CC;
    float* dst = out + dstOff + ((long)b * kcnt + rr) * CC;
    const int tid = threadIdx.x;
    for (int i = tid * 4; i < CC; i += 256 * 4) {
        *(float4*)(dst + i) = *(const float4*)(src + i);
    }
}

// ---------------- per-(b,cls) top-150 mean over time ----------------
__global__ void cls_topk_kernel(const float* __restrict__ out) {
    __shared__ float sbuf[1024];
    __shared__ float rv[256];
    const int b = blockIdx.x / CLS, cls = blockIdx.x % CLS;
    const int tid = threadIdx.x;
    for (int i = tid; i < 1024; i += 256)
        sbuf[i] = (i < TT) ? out[OFF_CAS + ((long)(b * TT + i)) * CLS + cls] : -FLT_MAX;
    __syncthreads();
    bitonic1024(sbuf, tid);
    // top KNB values are at indices [1024-KNB, 1024)
    float s = 0.f;
    for (int i = 1024 - KNB + tid; i < 1024; i += 256) s += sbuf[i];
    rv[tid] = s;
    __syncthreads();
    for (int st = 128; st > 0; st >>= 1) {
        if (tid < st) rv[tid] += rv[tid + st];
        __syncthreads();
    }
    if (tid == 0) g_cls_mean[b * CLS + cls] = rv[0] / (float)KNB;
}

// ---------------- softmax over classes ----------------
__global__ void softmax_kernel(float* __restrict__ out) {
    const int b = blockIdx.x;
    const int lane = threadIdx.x;   // 32 threads
    float v = (lane < CLS) ? g_cls_mean[b * CLS + lane] : -FLT_MAX;
    float m = v;
    #pragma unroll
    for (int o = 16; o > 0; o >>= 1) m = fmaxf(m, __shfl_xor_sync(0xffffffffu, m, o));
    float e = (lane < CLS) ? expf(v - m) : 0.f;
    float s = e;
    #pragma unroll
    for (int o = 16; o > 0; o >>= 1) s += __shfl_xor_sync(0xffffffffu, s, o);
    if (lane < CLS) out[OFF_VS + b * CLS + lane] = e / s;
}

// ---------------- launch ----------------
extern "C" void kernel_launch(void* const* d_in, const int* in_sizes, int n_in,
                              void* d_out, int out_size) {
    const float* x      = (const float*)d_in[0];
    const float* w_rgb  = (const float*)d_in[1];
    const float* b_rgb  = (const float*)d_in[2];
    const float* w_flow = (const float*)d_in[3];
    const float* b_flow = (const float*)d_in[4];
    const float* w_cls  = (const float*)d_in[5];
    float* out = (float*)d_out;

    float* wt_rgb;  cudaGetSymbolAddress((void**)&wt_rgb,  g_wt_rgb);
    float* wt_flow; cudaGetSymbolAddress((void**)&wt_flow, g_wt_flow);

    dim3 rg(KDIM / 32, CC / 32);
    dim3 rb(32, 8);
    repack_kernel<<<rg, rb>>>(w_rgb,  wt_rgb);
    repack_kernel<<<rg, rb>>>(w_flow, wt_flow);

    dim3 gg((NPOS + 127) / 128, CC / 128);   // 94 x 16
    conv_gemm_kernel<<<gg, 256>>>(x, wt_rgb,  b_rgb,  out + OFF_EMB, 0,    0);
    conv_gemm_kernel<<<gg, 256>>>(x, wt_flow, b_flow, out + OFF_EMB, CIN,  1);

    cas_kernel<<<NPOS, CLS * 32>>>(w_cls, out);
    analysis_kernel<<<BB, 256>>>(out);
    gather_kernel<<<BB * (KNB + KNB + KB2 + KB2), 256>>>(out);
    cls_topk_kernel<<<BB * CLS, 256>>>(out);
    softmax_kernel<<<BB, 32>>>(out);
}

// round 8
// speedup vs baseline: 1.1095x; 1.1095x over previous
#include <cuda_runtime.h>
#include <float.h>
#include <math.h>
#include <stdint.h>

// ---------------- problem constants ----------------
constexpr int BB   = 16;
constexpr int TT   = 750;
constexpr int CC   = 2048;
constexpr int CIN  = 1024;
constexpr int CLS  = 20;
constexpr int NPOS = BB * TT;          // 12000
constexpr int KNB  = 150;
constexpr int KB2  = 37;
constexpr int KW   = 3 * CIN;          // 3072
constexpr int TPAD = 768;              // 6 tiles of 128
constexpr int NPAD = BB * TPAD;        // 12288

// output layout (concatenated f32)
constexpr long OFF_VS  = 0;
constexpr long OFF_EA  = OFF_VS  + (long)BB * CLS;
constexpr long OFF_EB  = OFF_EA  + (long)BB * KNB * CC;
constexpr long OFF_HA  = OFF_EB  + (long)BB * KNB * CC;
constexpr long OFF_HB  = OFF_HA  + (long)BB * KB2 * CC;
constexpr long OFF_IDX = OFF_HB  + (long)BB * KB2 * CC;
constexpr long OFF_ACT = OFF_IDX + (long)BB * KNB;
constexpr long OFF_CAS = OFF_ACT + (long)NPOS;
constexpr long OFF_EMB = OFF_CAS + (long)NPOS * CLS;

// ---------------- device scratch ----------------
__device__ float g_wt_rgb[(long)KW * CC];      // [k=tau*1024+i][c]
__device__ float g_wt_flow[(long)KW * CC];
// im2col x: [stream][k=tau*1024+i][n = b*TPAD + t]; zero-init pads persist
__device__ float g_xim[2][(long)KW * NPAD];
__device__ int   g_sel_idx[4 * BB * KNB];
__device__ float g_cls_mean[BB * CLS];

// ---------------- PTX helpers ----------------
__device__ __forceinline__ uint32_t s2u(const void* p) {
    uint32_t a;
    asm("{ .reg .u64 t; cvta.to.shared.u64 t, %1; cvt.u32.u64 %0, t; }" : "=r"(a) : "l"(p));
    return a;
}
__device__ __forceinline__ void cp16(uint32_t dst, const void* src) {
    asm volatile("cp.async.cg.shared.global [%0], [%1], 16;"
                 :: "r"(dst), "l"(src) : "memory");
}

// ---------------- weight repack: w[c][i][tau] -> wt[tau*1024+i][c] ---------
__global__ void repack_kernel(const float* __restrict__ w, float* __restrict__ wt) {
    __shared__ float tile[32][33];
    int kp0 = blockIdx.x * 32;
    int c0  = blockIdx.y * 32;
    int tx = threadIdx.x, ty = threadIdx.y;   // 32 x 8
    #pragma unroll
    for (int j = 0; j < 32; j += 8) {
        int c = c0 + ty + j;
        tile[ty + j][tx] = w[(long)c * KW + kp0 + tx];
    }
    __syncthreads();
    #pragma unroll
    for (int j = 0; j < 32; j += 8) {
        int kp = kp0 + ty + j;
        int k  = (kp % 3) * CIN + (kp / 3);
        wt[(long)k * CC + c0 + tx] = tile[tx][ty + j];
    }
}

// ---------------- pack x -> im2col planes, coalesced via smem transpose ----
// grid 256 = (str 2) x (b 16) x (ichunk 8); 256 threads
// tile stride 132 floats = 528 B = 33 x 16 B -> float4 rows stay 16B-aligned
__global__ __launch_bounds__(256)
void pack_xim_kernel(const float* __restrict__ x) {
    __shared__ float tile[32][132];
    const int blk = blockIdx.x;
    const int str = blk >> 7, rem = blk & 127, b = rem >> 3, ic = rem & 7;
    const int i0 = ic * 128;
    const int tid = threadIdx.x, w = tid >> 5, lane = tid & 31;
    float* xout = &g_xim[str][0];

    for (int tc = 0; tc < 24; ++tc) {
        #pragma unroll
        for (int rr = 0; rr < 4; ++rr) {
            int r = w + rr * 8;
            int tt = tc * 32 + r;
            float4 v = make_float4(0.f, 0.f, 0.f, 0.f);
            if (tt < TT)
                v = *(const float4*)&x[((long)(b * TT + tt)) * CC + str * CIN + i0 + lane * 4];
            *(float4*)&tile[r][lane * 4] = v;
        }
        __syncthreads();
        const int tt = tc * 32 + lane;
        #pragma unroll
        for (int tau = 0; tau < 3; ++tau) {
            const int t = tt + 1 - tau;       // xim[tau*1024+i][b*TPAD+t] = x[t+tau-1][i]
            const bool ok = (t >= 0 && t < TPAD && tt < TT);
            #pragma unroll
            for (int q = 0; q < 16; ++q) {
                int ii = w * 16 + q;
                if (ok)
                    xout[((long)(tau * CIN + i0 + ii)) * NPAD + b * TPAD + t] = tile[lane][ii];
            }
        }
        __syncthreads();
    }
}

// ---------------- conv GEMM: fp32, round-1 FMA order, cp.async pipelined ---
// grid (96, 16), 256 threads; CTA tile 128 pos x 128 chan, BK=16, 192 stages.
__global__ __launch_bounds__(256, 2)
void conv_fp32_kernel(const float* __restrict__ wt, const float* __restrict__ xim,
                      const float* __restrict__ bias, float* __restrict__ emb,
                      int addMode) {
    __shared__ float As[2][16][128];
    __shared__ float Bs[2][16][128];
    const int tid = threadIdx.x;
    const int tx = tid & 15;       // position group
    const int ty = tid >> 4;       // channel group
    const int n0 = blockIdx.x * 128;
    const int c0 = blockIdx.y * 128;

    // loader: 512 16B-chunks per array per stage; 2 A + 2 B chunks per thread
    const int r0 = tid >> 5, g0 = (tid & 31) * 4;          // chunk tid
    const int r1 = (tid + 256) >> 5, g1 = g0;              // chunk tid+256

    float acc[8][8];
    #pragma unroll
    for (int i = 0; i < 8; ++i)
        #pragma unroll
        for (int j = 0; j < 8; ++j) acc[i][j] = 0.f;

    auto load = [&](int s, int k0) {
        cp16(s2u(&As[s][r0][g0]), wt + (long)(k0 + r0) * CC + c0 + g0);
        cp16(s2u(&As[s][r1][g1]), wt + (long)(k0 + r1) * CC + c0 + g1);
        cp16(s2u(&Bs[s][r0][g0]), xim + (long)(k0 + r0) * NPAD + n0 + g0);
        cp16(s2u(&Bs[s][r1][g1]), xim + (long)(k0 + r1) * NPAD + n0 + g1);
        asm volatile("cp.async.commit_group;" ::: "memory");
    };

    load(0, 0);
    load(1, 16);

    for (int st = 0; st < KW / 16; ++st) {
        if (st < KW / 16 - 1) asm volatile("cp.async.wait_group 1;" ::: "memory");
        else                  asm volatile("cp.async.wait_group 0;" ::: "memory");
        __syncthreads();
        const int s = st & 1;
        #pragma unroll
        for (int kk = 0; kk < 16; ++kk) {
            float4 t0 = *(const float4*)&As[s][kk][ty * 8];
            float4 t1 = *(const float4*)&As[s][kk][ty * 8 + 4];
            float4 u0 = *(const float4*)&Bs[s][kk][tx * 8];
            float4 u1 = *(const float4*)&Bs[s][kk][tx * 8 + 4];
            float ar[8] = {t0.x, t0.y, t0.z, t0.w, t1.x, t1.y, t1.z, t1.w};
            float br[8] = {u0.x, u0.y, u0.z, u0.w, u1.x, u1.y, u1.z, u1.w};
            #pragma unroll
            for (int i = 0; i < 8; ++i)
                #pragma unroll
                for (int j = 0; j < 8; ++j)
                    acc[i][j] = fmaf(ar[i], br[j], acc[i][j]);
        }
        __syncthreads();
        if (st + 2 < KW / 16) load(st & 1, (st + 2) * 16);
    }

    float bv[8];
    #pragma unroll
    for (int i = 0; i < 8; ++i) bv[i] = bias[c0 + ty * 8 + i];

    #pragma unroll
    for (int j = 0; j < 8; ++j) {
        const int n = n0 + tx * 8 + j;
        const int b = n / TPAD, t = n % TPAD;
        if (t >= TT) continue;
        float* dst = emb + ((long)(b * TT + t)) * CC + c0 + ty * 8;
        float4 v0, v1;
        v0.x = fmaxf(acc[0][j] + bv[0], 0.f);
        v0.y = fmaxf(acc[1][j] + bv[1], 0.f);
        v0.z = fmaxf(acc[2][j] + bv[2], 0.f);
        v0.w = fmaxf(acc[3][j] + bv[3], 0.f);
        v1.x = fmaxf(acc[4][j] + bv[4], 0.f);
        v1.y = fmaxf(acc[5][j] + bv[5], 0.f);
        v1.z = fmaxf(acc[6][j] + bv[6], 0.f);
        v1.w = fmaxf(acc[7][j] + bv[7], 0.f);
        if (addMode) {
            float4 o0 = *(const float4*)dst;
            float4 o1 = *(const float4*)(dst + 4);
            v0.x += o0.x; v0.y += o0.y; v0.z += o0.z; v0.w += o0.w;
            v1.x += o1.x; v1.y += o1.y; v1.z += o1.z; v1.w += o1.w;
        }
        *(float4*)dst = v0;
        *(float4*)(dst + 4) = v1;
    }
}

// ---------------- cas mini-GEMM: fp32 chunks + fp64 combine ----------------
constexpr int SE_S = 257, SW_S = 261;
__global__ __launch_bounds__(320)
void cas_gemm_kernel(const float* __restrict__ wcls, float* __restrict__ out) {
    __shared__ float se[16][SE_S];
    __shared__ float sw[CLS][SW_S];
    __shared__ float sc[16][CLS];
    const int tid = threadIdx.x;
    const int n0 = blockIdx.x * 16;
    const int p = tid / CLS, c = tid % CLS;
    const float* embg = out + OFF_EMB;

    double dacc = 0.0;
    for (int kc = 0; kc < 8; ++kc) {
        for (int i = tid; i < 16 * 256; i += 320) {
            int r = i >> 8, k = i & 255;
            se[r][k] = embg[(long)(n0 + r) * CC + kc * 256 + k];
        }
        for (int i = tid; i < CLS * 256; i += 320) {
            int r = i >> 8, k = i & 255;
            sw[r][k] = wcls[(long)r * CC + kc * 256 + k];
        }
        __syncthreads();
        #pragma unroll
        for (int sub = 0; sub < 8; ++sub) {
            float part = 0.f;
            #pragma unroll
            for (int k = 0; k < 32; ++k)
                part += se[p][sub * 32 + k] * sw[c][sub * 32 + k];
            dacc += (double)part;
        }
        __syncthreads();
    }
    float cv = (float)fmax(dacc, 0.0);
    out[OFF_CAS + (long)(n0 + p) * CLS + c] = cv;
    sc[p][c] = cv;
    __syncthreads();
    if (tid < 16) {
        double a = 0.0;
        #pragma unroll
        for (int j = 0; j < CLS; ++j) a += (double)sc[tid][j];
        out[OFF_ACT + n0 + tid] = (float)a;
    }
}

// ---------------- monotonic float <-> uint ----------------
__device__ __forceinline__ unsigned monof(float v) {
    unsigned b = __float_as_uint(v);
    return (b & 0x80000000u) ? ~b : (b | 0x80000000u);
}
__device__ __forceinline__ float unmonof(unsigned m) {
    unsigned b = (m & 0x80000000u) ? (m ^ 0x80000000u) : ~m;
    return __uint_as_float(b);
}

__device__ void sortkeys_desc(unsigned long long* s, int tid) {
    for (int k = 2; k <= 1024; k <<= 1) {
        for (int j = k >> 1; j > 0; j >>= 1) {
            __syncthreads();
            for (int i = tid; i < 1024; i += 256) {
                int ixj = i ^ j;
                if (ixj > i) {
                    bool up = ((i & k) == 0);
                    unsigned long long a = s[i], c = s[ixj];
                    if ((a < c) == up) { s[i] = c; s[ixj] = a; }
                }
            }
        }
    }
    __syncthreads();
}

// ---------------- per-batch analysis (exact given act) ----------------
__global__ void analysis_kernel(float* __restrict__ out) {
    __shared__ float act[TT];
    __shared__ float binv[TT];
    __shared__ unsigned long long keys[1024];
    __shared__ float s_med, s_max;

    const int b = blockIdx.x, tid = threadIdx.x;
    const float* actg = out + OFF_ACT + (long)b * TT;
    for (int t = tid; t < TT; t += 256) act[t] = actg[t];
    __syncthreads();

    for (int i = tid; i < 1024; i += 256)
        keys[i] = (i < TT) ? (((unsigned long long)monof(act[i]) << 32) | (unsigned)(1023 - i)) : 0ull;
    __syncthreads();
    sortkeys_desc(keys, tid);
    if (tid == 0) {
        s_max = unmonof((unsigned)(keys[0] >> 32));
        s_med = 0.5f * (unmonof((unsigned)(keys[374] >> 32)) +
                        unmonof((unsigned)(keys[375] >> 32)));
    }
    for (int r = tid; r < KNB; r += 256) {
        int t = 1023 - (int)(keys[r] & 1023u);
        g_sel_idx[(0 * BB + b) * KNB + r] = t;
        out[OFF_IDX + (long)b * KNB + r] = (float)t;
    }
    __syncthreads();
    const float med = s_med, mx = s_max;
    for (int t = tid; t < TT; t += 256) binv[t] = (act[t] > med) ? 1.f : 0.f;

    for (int i = tid; i < 1024; i += 256)
        keys[i] = (i < TT) ? (((unsigned long long)monof(mx - act[i]) << 32) | (unsigned)(1023 - i)) : 0ull;
    __syncthreads();
    sortkeys_desc(keys, tid);
    for (int r = tid; r < KNB; r += 256)
        g_sel_idx[(1 * BB + b) * KNB + r] = 1023 - (int)(keys[r] & 1023u);
    __syncthreads();

    for (int i = tid; i < 1024; i += 256) {
        float v = 0.f;
        if (i < TT) {
            int t = i;
            float e3 = 0.f, e6 = 0.f;
            if (t >= 1 && t <= TT - 2)
                e3 = fminf(binv[t - 1], fminf(binv[t], binv[t + 1]));
            if (t >= 3 && t <= TT - 3) {
                float m = binv[t - 3];
                m = fminf(m, binv[t - 2]); m = fminf(m, binv[t - 1]);
                m = fminf(m, binv[t]);     m = fminf(m, binv[t + 1]);
                m = fminf(m, binv[t + 2]);
                e6 = m;
            }
            v = act[t] * (e3 - e6);
        }
        keys[i] = (i < TT) ? (((unsigned long long)monof(v) << 32) | (unsigned)(1023 - i)) : 0ull;
    }
    __syncthreads();
    sortkeys_desc(keys, tid);
    for (int r = tid; r < KB2; r += 256)
        g_sel_idx[(2 * BB + b) * KNB + r] = 1023 - (int)(keys[r] & 1023u);
    __syncthreads();

    for (int i = tid; i < 1024; i += 256) {
        float v = 0.f;
        if (i < TT) {
            int t = i;
            float d3 = 0.f, d6 = 0.f;
            #pragma unroll
            for (int dt = -1; dt <= 1; ++dt) {
                int u = t + dt;
                if (u >= 0 && u < TT) d3 = fmaxf(d3, binv[u]);
            }
            #pragma unroll
            for (int dt = -2; dt <= 3; ++dt) {
                int u = t + dt;
                if (u >= 0 && u < TT) d6 = fmaxf(d6, binv[u]);
            }
            v = act[t] * (d6 - d3);
        }
        keys[i] = (i < TT) ? (((unsigned long long)monof(v) << 32) | (unsigned)(1023 - i)) : 0ull;
    }
    __syncthreads();
    sortkeys_desc(keys, tid);
    for (int r = tid; r < KB2; r += 256)
        g_sel_idx[(3 * BB + b) * KNB + r] = 1023 - (int)(keys[r] & 1023u);
}

// ---------------- gathers ----------------
__global__ void gather_kernel(float* __restrict__ out) {
    const int rowsPerB = KNB + KNB + KB2 + KB2;
    const int b = blockIdx.x / rowsPerB;
    int r = blockIdx.x % rowsPerB;
    int arr, rr; long dstOff; int kcnt;
    if (r < KNB)                { arr = 0; rr = r;                 dstOff = OFF_EA; kcnt = KNB; }
    else if (r < 2 * KNB)       { arr = 1; rr = r - KNB;           dstOff = OFF_EB; kcnt = KNB; }
    else if (r < 2 * KNB + KB2) { arr = 2; rr = r - 2 * KNB;       dstOff = OFF_HA; kcnt = KB2; }
    else                        { arr = 3; rr = r - 2 * KNB - KB2; dstOff = OFF_HB; kcnt = KB2; }
    const int tsel = g_sel_idx[(arr * BB + b) * KNB + rr];
    const float* src = out + OFF_EMB + ((long)b * TT + tsel) * CC;
    float* dst = out + dstOff + ((long)b * kcnt + rr) * CC;
    const int tid = threadIdx.x;
    for (int i = tid * 4; i < CC; i += 256 * 4) {
        *(float4*)(dst + i) = *(const float4*)(src + i);
    }
}

// ---------------- ascending bitonic float sort ----------------
__device__ inline void bitonic1024(float* s, int tid) {
    for (int k = 2; k <= 1024; k <<= 1) {
        for (int j = k >> 1; j > 0; j >>= 1) {
            __syncthreads();
            for (int i = tid; i < 1024; i += 256) {
                int ixj = i ^ j;
                if (ixj > i) {
                    bool up = ((i & k) == 0);
                    float a = s[i], c = s[ixj];
                    if ((a > c) == up) { s[i] = c; s[ixj] = a; }
                }
            }
        }
    }
    __syncthreads();
}

__global__ void cls_topk_kernel(const float* __restrict__ out) {
    __shared__ float sbuf[1024];
    __shared__ float rv[256];
    const int b = blockIdx.x / CLS, cls = blockIdx.x % CLS;
    const int tid = threadIdx.x;
    for (int i = tid; i < 1024; i += 256)
        sbuf[i] = (i < TT) ? out[OFF_CAS + ((long)(b * TT + i)) * CLS + cls] : -FLT_MAX;
    __syncthreads();
    bitonic1024(sbuf, tid);
    float s = 0.f;
    for (int i = 1024 - KNB + tid; i < 1024; i += 256) s += sbuf[i];
    rv[tid] = s;
    __syncthreads();
    for (int st = 128; st > 0; st >>= 1) {
        if (tid < st) rv[tid] += rv[tid + st];
        __syncthreads();
    }
    if (tid == 0) g_cls_mean[b * CLS + cls] = rv[0] / (float)KNB;
}

__global__ void softmax_kernel(float* __restrict__ out) {
    const int b = blockIdx.x;
    const int lane = threadIdx.x;
    float v = (lane < CLS) ? g_cls_mean[b * CLS + lane] : -FLT_MAX;
    float m = v;
    #pragma unroll
    for (int o = 16; o > 0; o >>= 1) m = fmaxf(m, __shfl_xor_sync(0xffffffffu, m, o));
    float e = (lane < CLS) ? expf(v - m) : 0.f;
    float s = e;
    #pragma unroll
    for (int o = 16; o > 0; o >>= 1) s += __shfl_xor_sync(0xffffffffu, s, o);
    if (lane < CLS) out[OFF_VS + b * CLS + lane] = e / s;
}

// ---------------- launch ----------------
extern "C" void kernel_launch(void* const* d_in, const int* in_sizes, int n_in,
                              void* d_out, int out_size) {
    const float* x      = (const float*)d_in[0];
    const float* w_rgb  = (const float*)d_in[1];
    const float* b_rgb  = (const float*)d_in[2];
    const float* w_flow = (const float*)d_in[3];
    const float* b_flow = (const float*)d_in[4];
    const float* w_cls  = (const float*)d_in[5];
    float* out = (float*)d_out;

    float* wt_rgb;  cudaGetSymbolAddress((void**)&wt_rgb,  g_wt_rgb);
    float* wt_flow; cudaGetSymbolAddress((void**)&wt_flow, g_wt_flow);
    float* xim;     cudaGetSymbolAddress((void**)&xim,     g_xim);

    dim3 rg(KW / 32, CC / 32);
    dim3 rb(32, 8);
    repack_kernel<<<rg, rb>>>(w_rgb,  wt_rgb);
    repack_kernel<<<rg, rb>>>(w_flow, wt_flow);
    pack_xim_kernel<<<256, 256>>>(x);

    dim3 cg(NPAD / 128, CC / 128);   // 96 x 16
    conv_fp32_kernel<<<cg, 256>>>(wt_rgb,  xim,                     b_rgb,  out + OFF_EMB, 0);
    conv_fp32_kernel<<<cg, 256>>>(wt_flow, xim + (long)KW * NPAD,   b_flow, out + OFF_EMB, 1);

    cas_gemm_kernel<<<NPOS / 16, 320>>>(w_cls, out);
    analysis_kernel<<<BB, 256>>>(out);
    gather_kernel<<<BB * (KNB + KNB + KB2 + KB2), 256>>>(out);
    cls_topk_kernel<<<BB * CLS, 256>>>(out);
    softmax_kernel<<<BB, 32>>>(out);
}

// round 9
// speedup vs baseline: 1.3688x; 1.2338x over previous
#include <cuda_runtime.h>
#include <cuda_bf16.h>
#include <float.h>
#include <math.h>
#include <stdint.h>

// ---------------- problem constants ----------------
constexpr int BB   = 16;
constexpr int TT   = 750;
constexpr int CC   = 2048;
constexpr int CIN  = 1024;
constexpr int CLS  = 20;
constexpr int NPOS = BB * TT;
constexpr int KNB  = 150;
constexpr int KB2  = 37;
constexpr int KW   = 3 * CIN;          // 3072
constexpr int TPAD = 768;
constexpr int XROWS = BB * TPAD;       // 12288

// output layout (concatenated f32)
constexpr long OFF_VS  = 0;
constexpr long OFF_EA  = OFF_VS  + (long)BB * CLS;
constexpr long OFF_EB  = OFF_EA  + (long)BB * KNB * CC;
constexpr long OFF_HA  = OFF_EB  + (long)BB * KNB * CC;
constexpr long OFF_HB  = OFF_HA  + (long)BB * KB2 * CC;
constexpr long OFF_IDX = OFF_HB  + (long)BB * KB2 * CC;
constexpr long OFF_ACT = OFF_IDX + (long)BB * KNB;
constexpr long OFF_CAS = OFF_ACT + (long)NPOS;
constexpr long OFF_EMB = OFF_CAS + (long)NPOS * CLS;

// ---------------- device scratch ----------------
// x planes: [stream*3 + p][padded row][1024], p = 0(hi),1(mid),2(lo)
__device__ __nv_bfloat16 g_xb[6][XROWS][CIN];
// w planes: [stream*3 + p][c][tau*1024+i]
__device__ __nv_bfloat16 g_wb[6][CC][KW];
__device__ int   g_sel_idx[4 * BB * KNB];
__device__ float g_cls_mean[BB * CLS];

// ---------------- PTX helpers ----------------
__device__ __forceinline__ uint32_t s2u(const void* p) {
    uint32_t a;
    asm("{ .reg .u64 t; cvta.to.shared.u64 t, %1; cvt.u32.u64 %0, t; }" : "=r"(a) : "l"(p));
    return a;
}
__device__ __forceinline__ void cp16(uint32_t dst, const void* src, int srcsz) {
    asm volatile("cp.async.cg.shared.global [%0], [%1], 16, %2;"
                 :: "r"(dst), "l"(src), "r"(srcsz) : "memory");
}

#define LDSM4(r0, r1, r2, r3, addr)                                          \
    asm volatile("ldmatrix.sync.aligned.m8n8.x4.shared.b16 {%0,%1,%2,%3}, [%4];" \
        : "=r"(r0), "=r"(r1), "=r"(r2), "=r"(r3) : "r"(addr))

#define MMA16816(D, A, B)                                                    \
    asm volatile("mma.sync.aligned.m16n8k16.row.col.f32.bf16.bf16.f32 "      \
        "{%0,%1,%2,%3}, {%4,%5,%6,%7}, {%8,%9}, {%0,%1,%2,%3};"              \
        : "+f"((D)[0]), "+f"((D)[1]), "+f"((D)[2]), "+f"((D)[3])             \
        : "r"((A)[0]), "r"((A)[1]), "r"((A)[2]), "r"((A)[3]),                \
          "r"((B)[0]), "r"((B)[1]))

// fresh accumulator: C = 0
#define MMA16816Z(D, A, B)                                                   \
    asm volatile("mma.sync.aligned.m16n8k16.row.col.f32.bf16.bf16.f32 "      \
        "{%0,%1,%2,%3}, {%4,%5,%6,%7}, {%8,%9}, {%10,%10,%10,%10};"          \
        : "=f"((D)[0]), "=f"((D)[1]), "=f"((D)[2]), "=f"((D)[3])             \
        : "r"((A)[0]), "r"((A)[1]), "r"((A)[2]), "r"((A)[3]),                \
          "r"((B)[0]), "r"((B)[1]), "f"(0.f))

// BK=32 swizzle: 64B rows, 4 chunks of 16B, conflict-free for 8-row ldmatrix
#define SWZ(r, g) (((((g) ^ (((r) >> 1) & 3)) & 3) << 4))

// ---------------- split helpers ----------------
__device__ __forceinline__ void split3(float v, __nv_bfloat16& h0,
                                       __nv_bfloat16& h1, __nv_bfloat16& h2) {
    h0 = __float2bfloat16(v);
    float r1 = v - __bfloat162float(h0);
    h1 = __float2bfloat16(r1);
    float r2 = r1 - __bfloat162float(h1);
    h2 = __float2bfloat16(r2);
}

// ---------------- pack x into 3 bf16 planes per stream ----------------
__global__ void pack_x_kernel(const float* __restrict__ x) {
    const int row = blockIdx.x;               // 0..12287
    const int b = row / TPAD, p = row % TPAD;
    const int t = p - 1;
    const bool valid = (t >= 0 && t < TT);
    const int c0 = threadIdx.x * 8;
    const int s = c0 >> 10, i0 = c0 & 1023;

    __nv_bfloat16 v0[8], v1[8], v2[8];
    if (valid) {
        const float* src = x + ((long)(b * TT + t)) * CC + c0;
        float4 a = *(const float4*)src;
        float4 bb = *(const float4*)(src + 4);
        float v[8] = {a.x, a.y, a.z, a.w, bb.x, bb.y, bb.z, bb.w};
        #pragma unroll
        for (int j = 0; j < 8; ++j) split3(v[j], v0[j], v1[j], v2[j]);
    } else {
        #pragma unroll
        for (int j = 0; j < 8; ++j) {
            v0[j] = __float2bfloat16(0.f); v1[j] = v0[j]; v2[j] = v0[j];
        }
    }
    *(uint4*)&g_xb[s * 3 + 0][row][i0] = *(uint4*)v0;
    *(uint4*)&g_xb[s * 3 + 1][row][i0] = *(uint4*)v1;
    *(uint4*)&g_xb[s * 3 + 2][row][i0] = *(uint4*)v2;
}

// ---------------- pack w: w[c][i][tau] -> planes [c][tau*1024+i] -----------
__global__ void pack_w_kernel(const float* __restrict__ w, int str) {
    const int c = blockIdx.x;
    const float* src = w + (long)c * KW;
    for (int idx = threadIdx.x; idx < KW; idx += blockDim.x) {
        int tau = idx / CIN, i = idx % CIN;
        float v = src[i * 3 + tau];
        __nv_bfloat16 h0, h1, h2;
        split3(v, h0, h1, h2);
        g_wb[str * 3 + 0][c][idx] = h0;
        g_wb[str * 3 + 1][c][idx] = h1;
        g_wb[str * 3 + 2][c][idx] = h2;
    }
}

// ---------------- HMMA conv kernel: 6-term split-bf16, per-k16 drain -------
// grid (96, 16), 256 threads. CTA tile: 128 pos x 128 chan, BK=32.
// Per k16, per output frag: 6 term-MMAs into a FRESH accumulator, ordered
// smallest term first and dominant x0*w0 LAST; then RN FADD into main acc.
constexpr int A_PLANE = 8192;             // 128*64B
constexpr int B_PLANE = 8192;             // 128*64B
constexpr int B_OFF   = 3 * A_PLANE;      // 24576
constexpr int STG     = B_OFF + 3 * B_PLANE;  // 49152
constexpr int NKB     = 96;               // 3 tau * 32 kblocks of 32

__device__ __forceinline__ void load_stage(uint32_t st, int kb, int b, int itile,
                                           int c0, int str, int tid) {
    const int tau = kb >> 5;
    const int k0  = (kb & 31) * 32;
    const int row0 = b * TPAD + itile * 128 + tau;
    #pragma unroll
    for (int p = 0; p < 3; ++p) {
        const __nv_bfloat16* xp = &g_xb[str * 3 + p][0][0];
        #pragma unroll
        for (int n = 0; n < 2; ++n) {
            int q = n * 256 + tid;           // 0..511
            int r = q >> 2, g = q & 3;
            uint32_t dst = st + p * A_PLANE + r * 64 + SWZ(r, g);
            int grow = row0 + r;
            cp16(dst, xp + (long)grow * CIN + k0 + g * 8, grow < XROWS ? 16 : 0);
        }
    }
    #pragma unroll
    for (int p = 0; p < 3; ++p) {
        const __nv_bfloat16* wp = &g_wb[str * 3 + p][0][0];
        #pragma unroll
        for (int n = 0; n < 2; ++n) {
            int q = n * 256 + tid;           // 0..511
            int r = q >> 2, g = q & 3;
            uint32_t dst = st + B_OFF + p * B_PLANE + r * 64 + SWZ(r, g);
            cp16(dst, wp + (long)(c0 + r) * KW + tau * CIN + k0 + g * 8, 16);
        }
    }
    asm volatile("cp.async.commit_group;" ::: "memory");
}

__global__ __launch_bounds__(256, 1)
void conv_mma_kernel(const float* __restrict__ bias, float* __restrict__ emb,
                     int str, int addMode) {
    extern __shared__ char dsm[];
    const uint32_t sb = (s2u(dsm) + 1023u) & ~1023u;

    const int tid = threadIdx.x, lane = tid & 31, wid = tid >> 5;
    const int ptile = blockIdx.x;          // 0..95
    const int b = ptile / 6, itile = ptile % 6;
    const int c0 = blockIdx.y * 128;
    const int m0 = (wid >> 2) * 64;        // warp tile: 64 x 32
    const int n0 = (wid & 3) * 32;

    float acc[4][4][4];
    #pragma unroll
    for (int i = 0; i < 4; ++i)
        #pragma unroll
        for (int j = 0; j < 4; ++j)
            #pragma unroll
            for (int k = 0; k < 4; ++k) acc[i][j][k] = 0.f;

    load_stage(sb, 0, b, itile, c0, str, tid);
    load_stage(sb + STG, 1, b, itile, c0, str, tid);

    for (int kb = 0; kb < NKB; ++kb) {
        const int s = kb & 1;
        if (kb < NKB - 1) asm volatile("cp.async.wait_group 1;" ::: "memory");
        else              asm volatile("cp.async.wait_group 0;" ::: "memory");
        __syncthreads();

        const uint32_t St = sb + s * STG;
        #pragma unroll
        for (int ks = 0; ks < 2; ++ks) {
            uint32_t a[3][4][4], bf[3][4][2];
            #pragma unroll
            for (int p = 0; p < 3; ++p) {
                #pragma unroll
                for (int f = 0; f < 4; ++f) {
                    int r = m0 + f * 16 + (lane & 15);
                    int g = ks * 2 + (lane >> 4);
                    uint32_t ad = St + p * A_PLANE + r * 64 + SWZ(r, g);
                    LDSM4(a[p][f][0], a[p][f][1], a[p][f][2], a[p][f][3], ad);
                }
                #pragma unroll
                for (int j = 0; j < 2; ++j) {
                    int r = n0 + (lane & 7) + ((lane >> 4) << 3) + j * 16;
                    int g = ks * 2 + ((lane >> 3) & 1);
                    uint32_t ad = St + B_OFF + p * B_PLANE + r * 64 + SWZ(r, g);
                    LDSM4(bf[p][j * 2][0], bf[p][j * 2][1],
                          bf[p][j * 2 + 1][0], bf[p][j * 2 + 1][1], ad);
                }
            }
            #pragma unroll
            for (int mi = 0; mi < 4; ++mi) {
                float accd[4][4];
                #pragma unroll
                for (int ni = 0; ni < 4; ++ni) {
                    // smallest terms first, dominant last (bias control)
                    MMA16816Z(accd[ni], a[1][mi], bf[1][ni]);   // x1*w1
                    MMA16816 (accd[ni], a[2][mi], bf[0][ni]);   // x2*w0
                    MMA16816 (accd[ni], a[0][mi], bf[2][ni]);   // x0*w2
                    MMA16816 (accd[ni], a[1][mi], bf[0][ni]);   // x1*w0
                    MMA16816 (accd[ni], a[0][mi], bf[1][ni]);   // x0*w1
                    MMA16816 (accd[ni], a[0][mi], bf[0][ni]);   // x0*w0 LAST
                }
                #pragma unroll
                for (int ni = 0; ni < 4; ++ni)
                    #pragma unroll
                    for (int q = 0; q < 4; ++q)
                        acc[mi][ni][q] += accd[ni][q];          // RN drain
            }
        }
        __syncthreads();
        if (kb + 2 < NKB) load_stage(sb + s * STG, kb + 2, b, itile, c0, str, tid);
    }

    // epilogue: C frag m16n8 -> rows lane/4 (+8), cols (lane&3)*2 (+1)
    #pragma unroll
    for (int ni = 0; ni < 4; ++ni) {
        const int col = c0 + n0 + ni * 8 + (lane & 3) * 2;
        const float b0v = bias[col], b1v = bias[col + 1];
        #pragma unroll
        for (int mi = 0; mi < 4; ++mi) {
            const int t0 = itile * 128 + m0 + mi * 16 + (lane >> 2);
            if (t0 < TT) {
                float2* p = (float2*)(emb + ((long)(b * TT + t0)) * CC + col);
                float2 v;
                v.x = fmaxf(acc[mi][ni][0] + b0v, 0.f);
                v.y = fmaxf(acc[mi][ni][1] + b1v, 0.f);
                if (addMode) { float2 o = *p; v.x += o.x; v.y += o.y; }
                *p = v;
            }
            const int t1 = t0 + 8;
            if (t1 < TT) {
                float2* p = (float2*)(emb + ((long)(b * TT + t1)) * CC + col);
                float2 v;
                v.x = fmaxf(acc[mi][ni][2] + b0v, 0.f);
                v.y = fmaxf(acc[mi][ni][3] + b1v, 0.f);
                if (addMode) { float2 o = *p; v.x += o.x; v.y += o.y; }
                *p = v;
            }
        }
    }
}

// ---------------- cas mini-GEMM: fp32 chunks + fp64 combine ----------------
constexpr int SE_S = 257, SW_S = 261;
__global__ __launch_bounds__(320)
void cas_gemm_kernel(const float* __restrict__ wcls, float* __restrict__ out) {
    __shared__ float se[16][SE_S];
    __shared__ float sw[CLS][SW_S];
    __shared__ float sc[16][CLS];
    const int tid = threadIdx.x;
    const int n0 = blockIdx.x * 16;
    const int p = tid / CLS, c = tid % CLS;
    const float* embg = out + OFF_EMB;

    double dacc = 0.0;
    for (int kc = 0; kc < 8; ++kc) {
        for (int i = tid; i < 16 * 256; i += 320) {
            int r = i >> 8, k = i & 255;
            se[r][k] = embg[(long)(n0 + r) * CC + kc * 256 + k];
        }
        for (int i = tid; i < CLS * 256; i += 320) {
            int r = i >> 8, k = i & 255;
            sw[r][k] = wcls[(long)r * CC + kc * 256 + k];
        }
        __syncthreads();
        #pragma unroll
        for (int sub = 0; sub < 8; ++sub) {
            float part = 0.f;
            #pragma unroll
            for (int k = 0; k < 32; ++k)
                part += se[p][sub * 32 + k] * sw[c][sub * 32 + k];
            dacc += (double)part;
        }
        __syncthreads();
    }
    float cv = (float)fmax(dacc, 0.0);
    out[OFF_CAS + (long)(n0 + p) * CLS + c] = cv;
    sc[p][c] = cv;
    __syncthreads();
    if (tid < 16) {
        double a = 0.0;
        #pragma unroll
        for (int j = 0; j < CLS; ++j) a += (double)sc[tid][j];
        out[OFF_ACT + n0 + tid] = (float)a;
    }
}

// ---------------- monotonic float <-> uint ----------------
__device__ __forceinline__ unsigned monof(float v) {
    unsigned b = __float_as_uint(v);
    return (b & 0x80000000u) ? ~b : (b | 0x80000000u);
}
__device__ __forceinline__ float unmonof(unsigned m) {
    unsigned b = (m & 0x80000000u) ? (m ^ 0x80000000u) : ~m;
    return __uint_as_float(b);
}

__device__ void sortkeys_desc(unsigned long long* s, int tid) {
    for (int k = 2; k <= 1024; k <<= 1) {
        for (int j = k >> 1; j > 0; j >>= 1) {
            __syncthreads();
            for (int i = tid; i < 1024; i += 256) {
                int ixj = i ^ j;
                if (ixj > i) {
                    bool up = ((i & k) == 0);
                    unsigned long long a = s[i], c = s[ixj];
                    if ((a < c) == up) { s[i] = c; s[ixj] = a; }
                }
            }
        }
    }
    __syncthreads();
}

// ---------------- per-batch analysis ----------------
__global__ void analysis_kernel(float* __restrict__ out) {
    __shared__ float act[TT];
    __shared__ float binv[TT];
    __shared__ unsigned long long keys[1024];
    __shared__ float s_med, s_max;

    const int b = blockIdx.x, tid = threadIdx.x;
    const float* actg = out + OFF_ACT + (long)b * TT;
    for (int t = tid; t < TT; t += 256) act[t] = actg[t];
    __syncthreads();

    for (int i = tid; i < 1024; i += 256)
        keys[i] = (i < TT) ? (((unsigned long long)monof(act[i]) << 32) | (unsigned)(1023 - i)) : 0ull;
    __syncthreads();
    sortkeys_desc(keys, tid);
    if (tid == 0) {
        s_max = unmonof((unsigned)(keys[0] >> 32));
        s_med = 0.5f * (unmonof((unsigned)(keys[374] >> 32)) +
                        unmonof((unsigned)(keys[375] >> 32)));
    }
    for (int r = tid; r < KNB; r += 256) {
        int t = 1023 - (int)(keys[r] & 1023u);
        g_sel_idx[(0 * BB + b) * KNB + r] = t;
        out[OFF_IDX + (long)b * KNB + r] = (float)t;
    }
    __syncthreads();
    const float med = s_med, mx = s_max;
    for (int t = tid; t < TT; t += 256) binv[t] = (act[t] > med) ? 1.f : 0.f;

    for (int i = tid; i < 1024; i += 256)
        keys[i] = (i < TT) ? (((unsigned long long)monof(mx - act[i]) << 32) | (unsigned)(1023 - i)) : 0ull;
    __syncthreads();
    sortkeys_desc(keys, tid);
    for (int r = tid; r < KNB; r += 256)
        g_sel_idx[(1 * BB + b) * KNB + r] = 1023 - (int)(keys[r] & 1023u);
    __syncthreads();

    for (int i = tid; i < 1024; i += 256) {
        float v = 0.f;
        if (i < TT) {
            int t = i;
            float e3 = 0.f, e6 = 0.f;
            if (t >= 1 && t <= TT - 2)
                e3 = fminf(binv[t - 1], fminf(binv[t], binv[t + 1]));
            if (t >= 3 && t <= TT - 3) {
                float m = binv[t - 3];
                m = fminf(m, binv[t - 2]); m = fminf(m, binv[t - 1]);
                m = fminf(m, binv[t]);     m = fminf(m, binv[t + 1]);
                m = fminf(m, binv[t + 2]);
                e6 = m;
            }
            v = act[t] * (e3 - e6);
        }
        keys[i] = (i < TT) ? (((unsigned long long)monof(v) << 32) | (unsigned)(1023 - i)) : 0ull;
    }
    __syncthreads();
    sortkeys_desc(keys, tid);
    for (int r = tid; r < KB2; r += 256)
        g_sel_idx[(2 * BB + b) * KNB + r] = 1023 - (int)(keys[r] & 1023u);
    __syncthreads();

    for (int i = tid; i < 1024; i += 256) {
        float v = 0.f;
        if (i < TT) {
            int t = i;
            float d3 = 0.f, d6 = 0.f;
            #pragma unroll
            for (int dt = -1; dt <= 1; ++dt) {
                int u = t + dt;
                if (u >= 0 && u < TT) d3 = fmaxf(d3, binv[u]);
            }
            #pragma unroll
            for (int dt = -2; dt <= 3; ++dt) {
                int u = t + dt;
                if (u >= 0 && u < TT) d6 = fmaxf(d6, binv[u]);
            }
            v = act[t] * (d6 - d3);
        }
        keys[i] = (i < TT) ? (((unsigned long long)monof(v) << 32) | (unsigned)(1023 - i)) : 0ull;
    }
    __syncthreads();
    sortkeys_desc(keys, tid);
    for (int r = tid; r < KB2; r += 256)
        g_sel_idx[(3 * BB + b) * KNB + r] = 1023 - (int)(keys[r] & 1023u);
}

// ---------------- gathers ----------------
__global__ void gather_kernel(float* __restrict__ out) {
    const int rowsPerB = KNB + KNB + KB2 + KB2;
    const int b = blockIdx.x / rowsPerB;
    int r = blockIdx.x % rowsPerB;
    int arr, rr; long dstOff; int kcnt;
    if (r < KNB)                { arr = 0; rr = r;                 dstOff = OFF_EA; kcnt = KNB; }
    else if (r < 2 * KNB)       { arr = 1; rr = r - KNB;           dstOff = OFF_EB; kcnt = KNB; }
    else if (r < 2 * KNB + KB2) { arr = 2; rr = r - 2 * KNB;       dstOff = OFF_HA; kcnt = KB2; }
    else                        { arr = 3; rr = r - 2 * KNB - KB2; dstOff = OFF_HB; kcnt = KB2; }
    const int tsel = g_sel_idx[(arr * BB + b) * KNB + rr];
    const float* src = out + OFF_EMB + ((long)b * TT + tsel) * CC;
    float* dst = out + dstOff + ((long)b * kcnt + rr) * CC;
    const int tid = threadIdx.x;
    for (int i = tid * 4; i < CC; i += 256 * 4) {
        *(float4*)(dst + i) = *(const float4*)(src + i);
    }
}

// ---------------- ascending bitonic float sort ----------------
__device__ inline void bitonic1024(float* s, int tid) {
    for (int k = 2; k <= 1024; k <<= 1) {
        for (int j = k >> 1; j > 0; j >>= 1) {
            __syncthreads();
            for (int i = tid; i < 1024; i += 256) {
                int ixj = i ^ j;
                if (ixj > i) {
                    bool up = ((i & k) == 0);
                    float a = s[i], c = s[ixj];
                    if ((a > c) == up) { s[i] = c; s[ixj] = a; }
                }
            }
        }
    }
    __syncthreads();
}

__global__ void cls_topk_kernel(const float* __restrict__ out) {
    __shared__ float sbuf[1024];
    __shared__ float rv[256];
    const int b = blockIdx.x / CLS, cls = blockIdx.x % CLS;
    const int tid = threadIdx.x;
    for (int i = tid; i < 1024; i += 256)
        sbuf[i] = (i < TT) ? out[OFF_CAS + ((long)(b * TT + i)) * CLS + cls] : -FLT_MAX;
    __syncthreads();
    bitonic1024(sbuf, tid);
    float s = 0.f;
    for (int i = 1024 - KNB + tid; i < 1024; i += 256) s += sbuf[i];
    rv[tid] = s;
    __syncthreads();
    for (int st = 128; st > 0; st >>= 1) {
        if (tid < st) rv[tid] += rv[tid + st];
        __syncthreads();
    }
    if (tid == 0) g_cls_mean[b * CLS + cls] = rv[0] / (float)KNB;
}

__global__ void softmax_kernel(float* __restrict__ out) {
    const int b = blockIdx.x;
    const int lane = threadIdx.x;
    float v = (lane < CLS) ? g_cls_mean[b * CLS + lane] : -FLT_MAX;
    float m = v;
    #pragma unroll
    for (int o = 16; o > 0; o >>= 1) m = fmaxf(m, __shfl_xor_sync(0xffffffffu, m, o));
    float e = (lane < CLS) ? expf(v - m) : 0.f;
    float s = e;
    #pragma unroll
    for (int o = 16; o > 0; o >>= 1) s += __shfl_xor_sync(0xffffffffu, s, o);
    if (lane < CLS) out[OFF_VS + b * CLS + lane] = e / s;
}

// ---------------- launch ----------------
extern "C" void kernel_launch(void* const* d_in, const int* in_sizes, int n_in,
                              void* d_out, int out_size) {
    const float* x      = (const float*)d_in[0];
    const float* w_rgb  = (const float*)d_in[1];
    const float* b_rgb  = (const float*)d_in[2];
    const float* w_flow = (const float*)d_in[3];
    const float* b_flow = (const float*)d_in[4];
    const float* w_cls  = (const float*)d_in[5];
    float* out = (float*)d_out;

    const int smem = 2 * STG + 1024;   // 99328
    cudaFuncSetAttribute(conv_mma_kernel,
                         cudaFuncAttributeMaxDynamicSharedMemorySize, smem);

    pack_x_kernel<<<XROWS, 256>>>(x);
    pack_w_kernel<<<CC, 256>>>(w_rgb, 0);
    pack_w_kernel<<<CC, 256>>>(w_flow, 1);

    dim3 cg(BB * 6, CC / 128);   // 96 x 16
    conv_mma_kernel<<<cg, 256, smem>>>(b_rgb,  out + OFF_EMB, 0, 0);
    conv_mma_kernel<<<cg, 256, smem>>>(b_flow, out + OFF_EMB, 1, 1);

    cas_gemm_kernel<<<NPOS / 16, 320>>>(w_cls, out);
    analysis_kernel<<<BB, 256>>>(out);
    gather_kernel<<<BB * (KNB + KNB + KB2 + KB2), 256>>>(out);
    cls_topk_kernel<<<BB * CLS, 256>>>(out);
    softmax_kernel<<<BB, 32>>>(out);
}

// round 10
// speedup vs baseline: 2.1903x; 1.6001x over previous
#include <cuda_runtime.h>
#include <cuda_fp16.h>
#include <float.h>
#include <math.h>
#include <stdint.h>

// ---------------- problem constants ----------------
constexpr int BB   = 16;
constexpr int TT   = 750;
constexpr int CC   = 2048;
constexpr int CIN  = 1024;
constexpr int CLS  = 20;
constexpr int NPOS = BB * TT;
constexpr int KNB  = 150;
constexpr int KB2  = 37;
constexpr int KW   = 3 * CIN;          // 3072
constexpr int TPAD = 768;
constexpr int XROWS = BB * TPAD;       // 12288

// output layout (concatenated f32)
constexpr long OFF_VS  = 0;
constexpr long OFF_EA  = OFF_VS  + (long)BB * CLS;
constexpr long OFF_EB  = OFF_EA  + (long)BB * KNB * CC;
constexpr long OFF_HA  = OFF_EB  + (long)BB * KNB * CC;
constexpr long OFF_HB  = OFF_HA  + (long)BB * KB2 * CC;
constexpr long OFF_IDX = OFF_HB  + (long)BB * KB2 * CC;
constexpr long OFF_ACT = OFF_IDX + (long)BB * KNB;
constexpr long OFF_CAS = OFF_ACT + (long)NPOS;
constexpr long OFF_EMB = OFF_CAS + (long)NPOS * CLS;

// ---------------- device scratch ----------------
// x planes: [stream*2 + p][padded row][1024], p = 0(hi),1(lo), fp16
__device__ __half g_xb[4][XROWS][CIN];
// w planes: [stream*2 + p][c][tau*1024+i], fp16, pre-scaled by 256
__device__ __half g_wb[4][CC][KW];
__device__ int   g_sel_idx[4 * BB * KNB];
__device__ float g_cls_mean[BB * CLS];

// ---------------- PTX helpers ----------------
__device__ __forceinline__ uint32_t s2u(const void* p) {
    uint32_t a;
    asm("{ .reg .u64 t; cvta.to.shared.u64 t, %1; cvt.u32.u64 %0, t; }" : "=r"(a) : "l"(p));
    return a;
}
__device__ __forceinline__ void cp16(uint32_t dst, const void* src, int srcsz) {
    asm volatile("cp.async.cg.shared.global [%0], [%1], 16, %2;"
                 :: "r"(dst), "l"(src), "r"(srcsz) : "memory");
}

#define LDSM4(r0, r1, r2, r3, addr)                                          \
    asm volatile("ldmatrix.sync.aligned.m8n8.x4.shared.b16 {%0,%1,%2,%3}, [%4];" \
        : "=r"(r0), "=r"(r1), "=r"(r2), "=r"(r3) : "r"(addr))

#define MMAH(D, A, B)                                                        \
    asm volatile("mma.sync.aligned.m16n8k16.row.col.f32.f16.f16.f32 "        \
        "{%0,%1,%2,%3}, {%4,%5,%6,%7}, {%8,%9}, {%0,%1,%2,%3};"              \
        : "+f"((D)[0]), "+f"((D)[1]), "+f"((D)[2]), "+f"((D)[3])             \
        : "r"((A)[0]), "r"((A)[1]), "r"((A)[2]), "r"((A)[3]),                \
          "r"((B)[0]), "r"((B)[1]))

// fresh accumulator: C = 0
#define MMAHZ(D, A, B)                                                       \
    asm volatile("mma.sync.aligned.m16n8k16.row.col.f32.f16.f16.f32 "        \
        "{%0,%1,%2,%3}, {%4,%5,%6,%7}, {%8,%9}, {%10,%10,%10,%10};"          \
        : "=f"((D)[0]), "=f"((D)[1]), "=f"((D)[2]), "=f"((D)[3])             \
        : "r"((A)[0]), "r"((A)[1]), "r"((A)[2]), "r"((A)[3]),                \
          "r"((B)[0]), "r"((B)[1]), "f"(0.f))

// BK=32 swizzle: 64B rows, 4 chunks of 16B, conflict-free for 8-row ldmatrix
#define SWZ(r, g) (((((g) ^ (((r) >> 1) & 3)) & 3) << 4))

// ---------------- split helpers ----------------
__device__ __forceinline__ void split2h(float v, __half& h0, __half& h1) {
    h0 = __float2half(v);
    h1 = __float2half(v - __half2float(h0));
}

// ---------------- pack x into 2 fp16 planes per stream ----------------
__global__ void pack_x_kernel(const float* __restrict__ x) {
    const int row = blockIdx.x;               // 0..12287
    const int b = row / TPAD, p = row % TPAD;
    const int t = p - 1;
    const bool valid = (t >= 0 && t < TT);
    const int c0 = threadIdx.x * 8;
    const int s = c0 >> 10, i0 = c0 & 1023;

    __half v0[8], v1[8];
    if (valid) {
        const float* src = x + ((long)(b * TT + t)) * CC + c0;
        float4 a = *(const float4*)src;
        float4 bb = *(const float4*)(src + 4);
        float v[8] = {a.x, a.y, a.z, a.w, bb.x, bb.y, bb.z, bb.w};
        #pragma unroll
        for (int j = 0; j < 8; ++j) split2h(v[j], v0[j], v1[j]);
    } else {
        #pragma unroll
        for (int j = 0; j < 8; ++j) { v0[j] = __float2half(0.f); v1[j] = v0[j]; }
    }
    *(uint4*)&g_xb[s * 2 + 0][row][i0] = *(uint4*)v0;
    *(uint4*)&g_xb[s * 2 + 1][row][i0] = *(uint4*)v1;
}

// ---------------- pack w (scaled by 256): w[c][i][tau] -> [c][tau*1024+i] --
__global__ void pack_w_kernel(const float* __restrict__ w, int str) {
    const int c = blockIdx.x;
    const float* src = w + (long)c * KW;
    for (int idx = threadIdx.x; idx < KW; idx += blockDim.x) {
        int tau = idx / CIN, i = idx % CIN;
        float v = src[i * 3 + tau] * 256.f;   // keep lo plane normal in fp16
        __half h0, h1;
        split2h(v, h0, h1);
        g_wb[str * 2 + 0][c][idx] = h0;
        g_wb[str * 2 + 1][c][idx] = h1;
    }
}

// ---------------- HMMA conv kernel: fp16 3-term split, per-k16 drain -------
// grid (96, 16), 256 threads. CTA tile: 128 pos x 128 chan, BK=32.
// Per k16, per frag: 3 term-MMAs into a FRESH accumulator (smallest first,
// dominant x0*w0 LAST), then RN FADD into main acc. Epilogue scales by 1/256.
constexpr int A_PLANE = 8192;             // 128*64B
constexpr int B_PLANE = 8192;             // 128*64B
constexpr int B_OFF   = 2 * A_PLANE;      // 16384
constexpr int STG     = B_OFF + 2 * B_PLANE;  // 32768
constexpr int NKB     = 96;               // 3 tau * 32 kblocks of 32

__device__ __forceinline__ void load_stage(uint32_t st, int kb, int b, int itile,
                                           int c0, int str, int tid) {
    const int tau = kb >> 5;
    const int k0  = (kb & 31) * 32;
    const int row0 = b * TPAD + itile * 128 + tau;
    #pragma unroll
    for (int p = 0; p < 2; ++p) {
        const __half* xp = &g_xb[str * 2 + p][0][0];
        #pragma unroll
        for (int n = 0; n < 2; ++n) {
            int q = n * 256 + tid;           // 0..511
            int r = q >> 2, g = q & 3;
            uint32_t dst = st + p * A_PLANE + r * 64 + SWZ(r, g);
            int grow = row0 + r;
            cp16(dst, xp + (long)grow * CIN + k0 + g * 8, grow < XROWS ? 16 : 0);
        }
    }
    #pragma unroll
    for (int p = 0; p < 2; ++p) {
        const __half* wp = &g_wb[str * 2 + p][0][0];
        #pragma unroll
        for (int n = 0; n < 2; ++n) {
            int q = n * 256 + tid;           // 0..511
            int r = q >> 2, g = q & 3;
            uint32_t dst = st + B_OFF + p * B_PLANE + r * 64 + SWZ(r, g);
            cp16(dst, wp + (long)(c0 + r) * KW + tau * CIN + k0 + g * 8, 16);
        }
    }
    asm volatile("cp.async.commit_group;" ::: "memory");
}

__global__ __launch_bounds__(256, 1)
void conv_mma_kernel(const float* __restrict__ bias, float* __restrict__ emb,
                     int str, int addMode) {
    extern __shared__ char dsm[];
    const uint32_t sb = (s2u(dsm) + 1023u) & ~1023u;

    const int tid = threadIdx.x, lane = tid & 31, wid = tid >> 5;
    const int ptile = blockIdx.x;          // 0..95
    const int b = ptile / 6, itile = ptile % 6;
    const int c0 = blockIdx.y * 128;
    const int m0 = (wid >> 2) * 64;        // warp tile: 64 x 32
    const int n0 = (wid & 3) * 32;

    float acc[4][4][4];
    #pragma unroll
    for (int i = 0; i < 4; ++i)
        #pragma unroll
        for (int j = 0; j < 4; ++j)
            #pragma unroll
            for (int k = 0; k < 4; ++k) acc[i][j][k] = 0.f;

    load_stage(sb, 0, b, itile, c0, str, tid);
    load_stage(sb + STG, 1, b, itile, c0, str, tid);

    for (int kb = 0; kb < NKB; ++kb) {
        const int s = kb & 1;
        if (kb < NKB - 1) asm volatile("cp.async.wait_group 1;" ::: "memory");
        else              asm volatile("cp.async.wait_group 0;" ::: "memory");
        __syncthreads();

        const uint32_t St = sb + s * STG;
        #pragma unroll
        for (int ks = 0; ks < 2; ++ks) {
            uint32_t a[2][4][4], bf[2][4][2];
            #pragma unroll
            for (int p = 0; p < 2; ++p) {
                #pragma unroll
                for (int f = 0; f < 4; ++f) {
                    int r = m0 + f * 16 + (lane & 15);
                    int g = ks * 2 + (lane >> 4);
                    uint32_t ad = St + p * A_PLANE + r * 64 + SWZ(r, g);
                    LDSM4(a[p][f][0], a[p][f][1], a[p][f][2], a[p][f][3], ad);
                }
                #pragma unroll
                for (int j = 0; j < 2; ++j) {
                    int r = n0 + (lane & 7) + ((lane >> 4) << 3) + j * 16;
                    int g = ks * 2 + ((lane >> 3) & 1);
                    uint32_t ad = St + B_OFF + p * B_PLANE + r * 64 + SWZ(r, g);
                    LDSM4(bf[p][j * 2][0], bf[p][j * 2][1],
                          bf[p][j * 2 + 1][0], bf[p][j * 2 + 1][1], ad);
                }
            }
            #pragma unroll
            for (int mi = 0; mi < 4; ++mi) {
                float accd[4][4];
                #pragma unroll
                for (int ni = 0; ni < 4; ++ni) {
                    // smallest terms first, dominant last (bias control)
                    MMAHZ(accd[ni], a[1][mi], bf[0][ni]);   // x1*w0
                    MMAH (accd[ni], a[0][mi], bf[1][ni]);   // x0*w1
                    MMAH (accd[ni], a[0][mi], bf[0][ni]);   // x0*w0 LAST
                }
                #pragma unroll
                for (int ni = 0; ni < 4; ++ni)
                    #pragma unroll
                    for (int q = 0; q < 4; ++q)
                        acc[mi][ni][q] += accd[ni][q];      // RN drain
            }
        }
        __syncthreads();
        if (kb + 2 < NKB) load_stage(sb + s * STG, kb + 2, b, itile, c0, str, tid);
    }

    // epilogue: undo the 256x weight scale (exact), bias + relu (+ add)
    constexpr float IS = 1.f / 256.f;
    #pragma unroll
    for (int ni = 0; ni < 4; ++ni) {
        const int col = c0 + n0 + ni * 8 + (lane & 3) * 2;
        const float b0v = bias[col], b1v = bias[col + 1];
        #pragma unroll
        for (int mi = 0; mi < 4; ++mi) {
            const int t0 = itile * 128 + m0 + mi * 16 + (lane >> 2);
            if (t0 < TT) {
                float2* p = (float2*)(emb + ((long)(b * TT + t0)) * CC + col);
                float2 v;
                v.x = fmaxf(acc[mi][ni][0] * IS + b0v, 0.f);
                v.y = fmaxf(acc[mi][ni][1] * IS + b1v, 0.f);
                if (addMode) { float2 o = *p; v.x += o.x; v.y += o.y; }
                *p = v;
            }
            const int t1 = t0 + 8;
            if (t1 < TT) {
                float2* p = (float2*)(emb + ((long)(b * TT + t1)) * CC + col);
                float2 v;
                v.x = fmaxf(acc[mi][ni][2] * IS + b0v, 0.f);
                v.y = fmaxf(acc[mi][ni][3] * IS + b1v, 0.f);
                if (addMode) { float2 o = *p; v.x += o.x; v.y += o.y; }
                *p = v;
            }
        }
    }
}

// ---------------- cas mini-GEMM: fp32 chunks + fp64 combine ----------------
constexpr int SE_S = 257, SW_S = 261;
__global__ __launch_bounds__(320)
void cas_gemm_kernel(const float* __restrict__ wcls, float* __restrict__ out) {
    __shared__ float se[16][SE_S];
    __shared__ float sw[CLS][SW_S];
    __shared__ float sc[16][CLS];
    const int tid = threadIdx.x;
    const int n0 = blockIdx.x * 16;
    const int p = tid / CLS, c = tid % CLS;
    const float* embg = out + OFF_EMB;

    double dacc = 0.0;
    for (int kc = 0; kc < 8; ++kc) {
        for (int i = tid; i < 16 * 256; i += 320) {
            int r = i >> 8, k = i & 255;
            se[r][k] = embg[(long)(n0 + r) * CC + kc * 256 + k];
        }
        for (int i = tid; i < CLS * 256; i += 320) {
            int r = i >> 8, k = i & 255;
            sw[r][k] = wcls[(long)r * CC + kc * 256 + k];
        }
        __syncthreads();
        #pragma unroll
        for (int sub = 0; sub < 8; ++sub) {
            float part = 0.f;
            #pragma unroll
            for (int k = 0; k < 32; ++k)
                part += se[p][sub * 32 + k] * sw[c][sub * 32 + k];
            dacc += (double)part;
        }
        __syncthreads();
    }
    float cv = (float)fmax(dacc, 0.0);
    out[OFF_CAS + (long)(n0 + p) * CLS + c] = cv;
    sc[p][c] = cv;
    __syncthreads();
    if (tid < 16) {
        double a = 0.0;
        #pragma unroll
        for (int j = 0; j < CLS; ++j) a += (double)sc[tid][j];
        out[OFF_ACT + n0 + tid] = (float)a;
    }
}

// ---------------- monotonic float <-> uint ----------------
__device__ __forceinline__ unsigned monof(float v) {
    unsigned b = __float_as_uint(v);
    return (b & 0x80000000u) ? ~b : (b | 0x80000000u);
}
__device__ __forceinline__ float unmonof(unsigned m) {
    unsigned b = (m & 0x80000000u) ? (m ^ 0x80000000u) : ~m;
    return __uint_as_float(b);
}

__device__ void sortkeys_desc(unsigned long long* s, int tid) {
    for (int k = 2; k <= 1024; k <<= 1) {
        for (int j = k >> 1; j > 0; j >>= 1) {
            __syncthreads();
            for (int i = tid; i < 1024; i += 256) {
                int ixj = i ^ j;
                if (ixj > i) {
                    bool up = ((i & k) == 0);
                    unsigned long long a = s[i], c = s[ixj];
                    if ((a < c) == up) { s[i] = c; s[ixj] = a; }
                }
            }
        }
    }
    __syncthreads();
}

// ---------------- per-batch analysis ----------------
__global__ void analysis_kernel(float* __restrict__ out) {
    __shared__ float act[TT];
    __shared__ float binv[TT];
    __shared__ unsigned long long keys[1024];
    __shared__ float s_med, s_max;

    const int b = blockIdx.x, tid = threadIdx.x;
    const float* actg = out + OFF_ACT + (long)b * TT;
    for (int t = tid; t < TT; t += 256) act[t] = actg[t];
    __syncthreads();

    for (int i = tid; i < 1024; i += 256)
        keys[i] = (i < TT) ? (((unsigned long long)monof(act[i]) << 32) | (unsigned)(1023 - i)) : 0ull;
    __syncthreads();
    sortkeys_desc(keys, tid);
    if (tid == 0) {
        s_max = unmonof((unsigned)(keys[0] >> 32));
        s_med = 0.5f * (unmonof((unsigned)(keys[374] >> 32)) +
                        unmonof((unsigned)(keys[375] >> 32)));
    }
    for (int r = tid; r < KNB; r += 256) {
        int t = 1023 - (int)(keys[r] & 1023u);
        g_sel_idx[(0 * BB + b) * KNB + r] = t;
        out[OFF_IDX + (long)b * KNB + r] = (float)t;
    }
    __syncthreads();
    const float med = s_med, mx = s_max;
    for (int t = tid; t < TT; t += 256) binv[t] = (act[t] > med) ? 1.f : 0.f;

    for (int i = tid; i < 1024; i += 256)
        keys[i] = (i < TT) ? (((unsigned long long)monof(mx - act[i]) << 32) | (unsigned)(1023 - i)) : 0ull;
    __syncthreads();
    sortkeys_desc(keys, tid);
    for (int r = tid; r < KNB; r += 256)
        g_sel_idx[(1 * BB + b) * KNB + r] = 1023 - (int)(keys[r] & 1023u);
    __syncthreads();

    for (int i = tid; i < 1024; i += 256) {
        float v = 0.f;
        if (i < TT) {
            int t = i;
            float e3 = 0.f, e6 = 0.f;
            if (t >= 1 && t <= TT - 2)
                e3 = fminf(binv[t - 1], fminf(binv[t], binv[t + 1]));
            if (t >= 3 && t <= TT - 3) {
                float m = binv[t - 3];
                m = fminf(m, binv[t - 2]); m = fminf(m, binv[t - 1]);
                m = fminf(m, binv[t]);     m = fminf(m, binv[t + 1]);
                m = fminf(m, binv[t + 2]);
                e6 = m;
            }
            v = act[t] * (e3 - e6);
        }
        keys[i] = (i < TT) ? (((unsigned long long)monof(v) << 32) | (unsigned)(1023 - i)) : 0ull;
    }
    __syncthreads();
    sortkeys_desc(keys, tid);
    for (int r = tid; r < KB2; r += 256)
        g_sel_idx[(2 * BB + b) * KNB + r] = 1023 - (int)(keys[r] & 1023u);
    __syncthreads();

    for (int i = tid; i < 1024; i += 256) {
        float v = 0.f;
        if (i < TT) {
            int t = i;
            float d3 = 0.f, d6 = 0.f;
            #pragma unroll
            for (int dt = -1; dt <= 1; ++dt) {
                int u = t + dt;
                if (u >= 0 && u < TT) d3 = fmaxf(d3, binv[u]);
            }
            #pragma unroll
            for (int dt = -2; dt <= 3; ++dt) {
                int u = t + dt;
                if (u >= 0 && u < TT) d6 = fmaxf(d6, binv[u]);
            }
            v = act[t] * (d6 - d3);
        }
        keys[i] = (i < TT) ? (((unsigned long long)monof(v) << 32) | (unsigned)(1023 - i)) : 0ull;
    }
    __syncthreads();
    sortkeys_desc(keys, tid);
    for (int r = tid; r < KB2; r += 256)
        g_sel_idx[(3 * BB + b) * KNB + r] = 1023 - (int)(keys[r] & 1023u);
}

// ---------------- gathers ----------------
__global__ void gather_kernel(float* __restrict__ out) {
    const int rowsPerB = KNB + KNB + KB2 + KB2;
    const int b = blockIdx.x / rowsPerB;
    int r = blockIdx.x % rowsPerB;
    int arr, rr; long dstOff; int kcnt;
    if (r < KNB)                { arr = 0; rr = r;                 dstOff = OFF_EA; kcnt = KNB; }
    else if (r < 2 * KNB)       { arr = 1; rr = r - KNB;           dstOff = OFF_EB; kcnt = KNB; }
    else if (r < 2 * KNB + KB2) { arr = 2; rr = r - 2 * KNB;       dstOff = OFF_HA; kcnt = KB2; }
    else                        { arr = 3; rr = r - 2 * KNB - KB2; dstOff = OFF_HB; kcnt = KB2; }
    const int tsel = g_sel_idx[(arr * BB + b) * KNB + rr];
    const float* src = out + OFF_EMB + ((long)b * TT + tsel) * CC;
    float* dst = out + dstOff + ((long)b * kcnt + rr) * CC;
    const int tid = threadIdx.x;
    for (int i = tid * 4; i < CC; i += 256 * 4) {
        *(float4*)(dst + i) = *(const float4*)(src + i);
    }
}

// ---------------- ascending bitonic float sort ----------------
__device__ inline void bitonic1024(float* s, int tid) {
    for (int k = 2; k <= 1024; k <<= 1) {
        for (int j = k >> 1; j > 0; j >>= 1) {
            __syncthreads();
            for (int i = tid; i < 1024; i += 256) {
                int ixj = i ^ j;
                if (ixj > i) {
                    bool up = ((i & k) == 0);
                    float a = s[i], c = s[ixj];
                    if ((a > c) == up) { s[i] = c; s[ixj] = a; }
                }
            }
        }
    }
    __syncthreads();
}

__global__ void cls_topk_kernel(const float* __restrict__ out) {
    __shared__ float sbuf[1024];
    __shared__ float rv[256];
    const int b = blockIdx.x / CLS, cls = blockIdx.x % CLS;
    const int tid = threadIdx.x;
    for (int i = tid; i < 1024; i += 256)
        sbuf[i] = (i < TT) ? out[OFF_CAS + ((long)(b * TT + i)) * CLS + cls] : -FLT_MAX;
    __syncthreads();
    bitonic1024(sbuf, tid);
    float s = 0.f;
    for (int i = 1024 - KNB + tid; i < 1024; i += 256) s += sbuf[i];
    rv[tid] = s;
    __syncthreads();
    for (int st = 128; st > 0; st >>= 1) {
        if (tid < st) rv[tid] += rv[tid + st];
        __syncthreads();
    }
    if (tid == 0) g_cls_mean[b * CLS + cls] = rv[0] / (float)KNB;
}

__global__ void softmax_kernel(float* __restrict__ out) {
    const int b = blockIdx.x;
    const int lane = threadIdx.x;
    float v = (lane < CLS) ? g_cls_mean[b * CLS + lane] : -FLT_MAX;
    float m = v;
    #pragma unroll
    for (int o = 16; o > 0; o >>= 1) m = fmaxf(m, __shfl_xor_sync(0xffffffffu, m, o));
    float e = (lane < CLS) ? expf(v - m) : 0.f;
    float s = e;
    #pragma unroll
    for (int o = 16; o > 0; o >>= 1) s += __shfl_xor_sync(0xffffffffu, s, o);
    if (lane < CLS) out[OFF_VS + b * CLS + lane] = e / s;
}

// ---------------- launch ----------------
extern "C" void kernel_launch(void* const* d_in, const int* in_sizes, int n_in,
                              void* d_out, int out_size) {
    const float* x      = (const float*)d_in[0];
    const float* w_rgb  = (const float*)d_in[1];
    const float* b_rgb  = (const float*)d_in[2];
    const float* w_flow = (const float*)d_in[3];
    const float* b_flow = (const float*)d_in[4];
    const float* w_cls  = (const float*)d_in[5];
    float* out = (float*)d_out;

    const int smem = 2 * STG + 1024;   // 66560
    cudaFuncSetAttribute(conv_mma_kernel,
                         cudaFuncAttributeMaxDynamicSharedMemorySize, smem);

    pack_x_kernel<<<XROWS, 256>>>(x);
    pack_w_kernel<<<CC, 256>>>(w_rgb, 0);
    pack_w_kernel<<<CC, 256>>>(w_flow, 1);

    dim3 cg(BB * 6, CC / 128);   // 96 x 16
    conv_mma_kernel<<<cg, 256, smem>>>(b_rgb,  out + OFF_EMB, 0, 0);
    conv_mma_kernel<<<cg, 256, smem>>>(b_flow, out + OFF_EMB, 1, 1);

    cas_gemm_kernel<<<NPOS / 16, 320>>>(w_cls, out);
    analysis_kernel<<<BB, 256>>>(out);
    gather_kernel<<<BB * (KNB + KNB + KB2 + KB2), 256>>>(out);
    cls_topk_kernel<<<BB * CLS, 256>>>(out);
    softmax_kernel<<<BB, 32>>>(out);
}

// round 11
// speedup vs baseline: 2.2228x; 1.0148x over previous
#include <cuda_runtime.h>
#include <cuda_fp16.h>
#include <float.h>
#include <math.h>
#include <stdint.h>

// ---------------- problem constants ----------------
constexpr int BB   = 16;
constexpr int TT   = 750;
constexpr int CC   = 2048;
constexpr int CIN  = 1024;
constexpr int CLS  = 20;
constexpr int NPOS = BB * TT;
constexpr int KNB  = 150;
constexpr int KB2  = 37;
constexpr int KW   = 3 * CIN;          // 3072
constexpr int TPAD = 768;
constexpr int XROWS = BB * TPAD;       // 12288

// output layout (concatenated f32)
constexpr long OFF_VS  = 0;
constexpr long OFF_EA  = OFF_VS  + (long)BB * CLS;
constexpr long OFF_EB  = OFF_EA  + (long)BB * KNB * CC;
constexpr long OFF_HA  = OFF_EB  + (long)BB * KNB * CC;
constexpr long OFF_HB  = OFF_HA  + (long)BB * KB2 * CC;
constexpr long OFF_IDX = OFF_HB  + (long)BB * KB2 * CC;
constexpr long OFF_ACT = OFF_IDX + (long)BB * KNB;
constexpr long OFF_CAS = OFF_ACT + (long)NPOS;
constexpr long OFF_EMB = OFF_CAS + (long)NPOS * CLS;

// ---------------- device scratch ----------------
// x planes: [stream*2 + p][padded row][1024], p = 0(hi),1(lo), fp16
__device__ __half g_xb[4][XROWS][CIN];
// w planes: [stream*2 + p][c][tau*1024+i], fp16, pre-scaled by 256
__device__ __half g_wb[4][CC][KW];
__device__ int   g_sel_idx[4 * BB * KNB];
__device__ float g_cls_mean[BB * CLS];

// ---------------- PTX helpers ----------------
__device__ __forceinline__ uint32_t s2u(const void* p) {
    uint32_t a;
    asm("{ .reg .u64 t; cvta.to.shared.u64 t, %1; cvt.u32.u64 %0, t; }" : "=r"(a) : "l"(p));
    return a;
}
__device__ __forceinline__ void cp16(uint32_t dst, const void* src, int srcsz) {
    asm volatile("cp.async.cg.shared.global [%0], [%1], 16, %2;"
                 :: "r"(dst), "l"(src), "r"(srcsz) : "memory");
}

#define LDSM4(r0, r1, r2, r3, addr)                                          \
    asm volatile("ldmatrix.sync.aligned.m8n8.x4.shared.b16 {%0,%1,%2,%3}, [%4];" \
        : "=r"(r0), "=r"(r1), "=r"(r2), "=r"(r3) : "r"(addr))

#define MMAH(D, A, B)                                                        \
    asm volatile("mma.sync.aligned.m16n8k16.row.col.f32.f16.f16.f32 "        \
        "{%0,%1,%2,%3}, {%4,%5,%6,%7}, {%8,%9}, {%0,%1,%2,%3};"              \
        : "+f"((D)[0]), "+f"((D)[1]), "+f"((D)[2]), "+f"((D)[3])             \
        : "r"((A)[0]), "r"((A)[1]), "r"((A)[2]), "r"((A)[3]),                \
          "r"((B)[0]), "r"((B)[1]))

// fresh accumulator: C = 0
#define MMAHZ(D, A, B)                                                       \
    asm volatile("mma.sync.aligned.m16n8k16.row.col.f32.f16.f16.f32 "        \
        "{%0,%1,%2,%3}, {%4,%5,%6,%7}, {%8,%9}, {%10,%10,%10,%10};"          \
        : "=f"((D)[0]), "=f"((D)[1]), "=f"((D)[2]), "=f"((D)[3])             \
        : "r"((A)[0]), "r"((A)[1]), "r"((A)[2]), "r"((A)[3]),                \
          "r"((B)[0]), "r"((B)[1]), "f"(0.f))

// BK=32 swizzle: 64B rows, 4 chunks of 16B, conflict-free for 8-row ldmatrix
#define SWZ(r, g) (((((g) ^ (((r) >> 1) & 3)) & 3) << 4))

// ---------------- split helpers ----------------
__device__ __forceinline__ void split2h(float v, __half& h0, __half& h1) {
    h0 = __float2half(v);
    h1 = __float2half(v - __half2float(h0));
}

// ---------------- pack x into 2 fp16 planes per stream ----------------
__global__ void pack_x_kernel(const float* __restrict__ x) {
    const int row = blockIdx.x;               // 0..12287
    const int b = row / TPAD, p = row % TPAD;
    const int t = p - 1;
    const bool valid = (t >= 0 && t < TT);
    const int c0 = threadIdx.x * 8;
    const int s = c0 >> 10, i0 = c0 & 1023;

    __half v0[8], v1[8];
    if (valid) {
        const float* src = x + ((long)(b * TT + t)) * CC + c0;
        float4 a = *(const float4*)src;
        float4 bb = *(const float4*)(src + 4);
        float v[8] = {a.x, a.y, a.z, a.w, bb.x, bb.y, bb.z, bb.w};
        #pragma unroll
        for (int j = 0; j < 8; ++j) split2h(v[j], v0[j], v1[j]);
    } else {
        #pragma unroll
        for (int j = 0; j < 8; ++j) { v0[j] = __float2half(0.f); v1[j] = v0[j]; }
    }
    *(uint4*)&g_xb[s * 2 + 0][row][i0] = *(uint4*)v0;
    *(uint4*)&g_xb[s * 2 + 1][row][i0] = *(uint4*)v1;
}

// ---------------- pack w (scaled by 256): w[c][i][tau] -> [c][tau*1024+i] --
__global__ void pack_w_kernel(const float* __restrict__ w, int str) {
    const int c = blockIdx.x;
    const float* src = w + (long)c * KW;
    for (int idx = threadIdx.x; idx < KW; idx += blockDim.x) {
        int tau = idx / CIN, i = idx % CIN;
        float v = src[i * 3 + tau] * 256.f;   // keep lo plane normal in fp16
        __half h0, h1;
        split2h(v, h0, h1);
        g_wb[str * 2 + 0][c][idx] = h0;
        g_wb[str * 2 + 1][c][idx] = h1;
    }
}

// ---------------- HMMA conv kernel: fp16 3-term split, per-k16 drain -------
// grid (96, 16), 256 threads. CTA tile: 128 pos x 128 chan, BK=32.
// 4-stage cp.async ring, ONE __syncthreads per iteration:
//   wait_group 2 -> sync -> issue load(kb+3) into freed stage -> compute kb.
constexpr int A_PLANE = 8192;             // 128*64B
constexpr int B_PLANE = 8192;             // 128*64B
constexpr int B_OFF   = 2 * A_PLANE;      // 16384
constexpr int STG     = B_OFF + 2 * B_PLANE;  // 32768
constexpr int NKB     = 96;               // 3 tau * 32 kblocks of 32
constexpr int NST     = 4;

__device__ __forceinline__ void load_stage(uint32_t st, int kb, int b, int itile,
                                           int c0, int str, int tid) {
    const int tau = kb >> 5;
    const int k0  = (kb & 31) * 32;
    const int row0 = b * TPAD + itile * 128 + tau;
    #pragma unroll
    for (int p = 0; p < 2; ++p) {
        const __half* xp = &g_xb[str * 2 + p][0][0];
        #pragma unroll
        for (int n = 0; n < 2; ++n) {
            int q = n * 256 + tid;           // 0..511
            int r = q >> 2, g = q & 3;
            uint32_t dst = st + p * A_PLANE + r * 64 + SWZ(r, g);
            int grow = row0 + r;
            cp16(dst, xp + (long)grow * CIN + k0 + g * 8, grow < XROWS ? 16 : 0);
        }
    }
    #pragma unroll
    for (int p = 0; p < 2; ++p) {
        const __half* wp = &g_wb[str * 2 + p][0][0];
        #pragma unroll
        for (int n = 0; n < 2; ++n) {
            int q = n * 256 + tid;           // 0..511
            int r = q >> 2, g = q & 3;
            uint32_t dst = st + B_OFF + p * B_PLANE + r * 64 + SWZ(r, g);
            cp16(dst, wp + (long)(c0 + r) * KW + tau * CIN + k0 + g * 8, 16);
        }
    }
    asm volatile("cp.async.commit_group;" ::: "memory");
}

__global__ __launch_bounds__(256, 1)
void conv_mma_kernel(const float* __restrict__ bias, float* __restrict__ emb,
                     int str, int addMode) {
    extern __shared__ char dsm[];
    const uint32_t sb = (s2u(dsm) + 1023u) & ~1023u;

    const int tid = threadIdx.x, lane = tid & 31, wid = tid >> 5;
    const int ptile = blockIdx.x;          // 0..95
    const int b = ptile / 6, itile = ptile % 6;
    const int c0 = blockIdx.y * 128;
    const int m0 = (wid >> 2) * 64;        // warp tile: 64 x 32
    const int n0 = (wid & 3) * 32;

    float acc[4][4][4];
    #pragma unroll
    for (int i = 0; i < 4; ++i)
        #pragma unroll
        for (int j = 0; j < 4; ++j)
            #pragma unroll
            for (int k = 0; k < 4; ++k) acc[i][j][k] = 0.f;

    load_stage(sb + 0 * STG, 0, b, itile, c0, str, tid);
    load_stage(sb + 1 * STG, 1, b, itile, c0, str, tid);
    load_stage(sb + 2 * STG, 2, b, itile, c0, str, tid);

    for (int kb = 0; kb < NKB; ++kb) {
        if (kb < NKB - 3) asm volatile("cp.async.wait_group 2;" ::: "memory");
        else              asm volatile("cp.async.wait_group 0;" ::: "memory");
        __syncthreads();   // stage kb ready everywhere; stage kb+3 slot free

        if (kb + 3 < NKB)
            load_stage(sb + ((kb + 3) & 3) * STG, kb + 3, b, itile, c0, str, tid);

        const uint32_t St = sb + (kb & 3) * STG;
        #pragma unroll
        for (int ks = 0; ks < 2; ++ks) {
            uint32_t a[2][4][4], bf[2][4][2];
            #pragma unroll
            for (int p = 0; p < 2; ++p) {
                #pragma unroll
                for (int f = 0; f < 4; ++f) {
                    int r = m0 + f * 16 + (lane & 15);
                    int g = ks * 2 + (lane >> 4);
                    uint32_t ad = St + p * A_PLANE + r * 64 + SWZ(r, g);
                    LDSM4(a[p][f][0], a[p][f][1], a[p][f][2], a[p][f][3], ad);
                }
                #pragma unroll
                for (int j = 0; j < 2; ++j) {
                    int r = n0 + (lane & 7) + ((lane >> 4) << 3) + j * 16;
                    int g = ks * 2 + ((lane >> 3) & 1);
                    uint32_t ad = St + B_OFF + p * B_PLANE + r * 64 + SWZ(r, g);
                    LDSM4(bf[p][j * 2][0], bf[p][j * 2][1],
                          bf[p][j * 2 + 1][0], bf[p][j * 2 + 1][1], ad);
                }
            }
            #pragma unroll
            for (int mi = 0; mi < 4; ++mi) {
                float accd[4][4];
                #pragma unroll
                for (int ni = 0; ni < 4; ++ni) {
                    // smallest terms first, dominant last (bias control)
                    MMAHZ(accd[ni], a[1][mi], bf[0][ni]);   // x1*w0
                    MMAH (accd[ni], a[0][mi], bf[1][ni]);   // x0*w1
                    MMAH (accd[ni], a[0][mi], bf[0][ni]);   // x0*w0 LAST
                }
                #pragma unroll
                for (int ni = 0; ni < 4; ++ni)
                    #pragma unroll
                    for (int q = 0; q < 4; ++q)
                        acc[mi][ni][q] += accd[ni][q];      // RN drain
            }
        }
    }

    // epilogue: undo the 256x weight scale (exact), bias + relu (+ add)
    constexpr float IS = 1.f / 256.f;
    #pragma unroll
    for (int ni = 0; ni < 4; ++ni) {
        const int col = c0 + n0 + ni * 8 + (lane & 3) * 2;
        const float b0v = bias[col], b1v = bias[col + 1];
        #pragma unroll
        for (int mi = 0; mi < 4; ++mi) {
            const int t0 = itile * 128 + m0 + mi * 16 + (lane >> 2);
            if (t0 < TT) {
                float2* p = (float2*)(emb + ((long)(b * TT + t0)) * CC + col);
                float2 v;
                v.x = fmaxf(acc[mi][ni][0] * IS + b0v, 0.f);
                v.y = fmaxf(acc[mi][ni][1] * IS + b1v, 0.f);
                if (addMode) { float2 o = *p; v.x += o.x; v.y += o.y; }
                *p = v;
            }
            const int t1 = t0 + 8;
            if (t1 < TT) {
                float2* p = (float2*)(emb + ((long)(b * TT + t1)) * CC + col);
                float2 v;
                v.x = fmaxf(acc[mi][ni][2] * IS + b0v, 0.f);
                v.y = fmaxf(acc[mi][ni][3] * IS + b1v, 0.f);
                if (addMode) { float2 o = *p; v.x += o.x; v.y += o.y; }
                *p = v;
            }
        }
    }
}

// ---------------- cas mini-GEMM: fp32 chunks + fp64 combine ----------------
constexpr int SE_S = 257, SW_S = 261;
__global__ __launch_bounds__(320)
void cas_gemm_kernel(const float* __restrict__ wcls, float* __restrict__ out) {
    __shared__ float se[16][SE_S];
    __shared__ float sw[CLS][SW_S];
    __shared__ float sc[16][CLS];
    const int tid = threadIdx.x;
    const int n0 = blockIdx.x * 16;
    const int p = tid / CLS, c = tid % CLS;
    const float* embg = out + OFF_EMB;

    double dacc = 0.0;
    for (int kc = 0; kc < 8; ++kc) {
        for (int i = tid; i < 16 * 256; i += 320) {
            int r = i >> 8, k = i & 255;
            se[r][k] = embg[(long)(n0 + r) * CC + kc * 256 + k];
        }
        for (int i = tid; i < CLS * 256; i += 320) {
            int r = i >> 8, k = i & 255;
            sw[r][k] = wcls[(long)r * CC + kc * 256 + k];
        }
        __syncthreads();
        #pragma unroll
        for (int sub = 0; sub < 8; ++sub) {
            float part = 0.f;
            #pragma unroll
            for (int k = 0; k < 32; ++k)
                part += se[p][sub * 32 + k] * sw[c][sub * 32 + k];
            dacc += (double)part;
        }
        __syncthreads();
    }
    float cv = (float)fmax(dacc, 0.0);
    out[OFF_CAS + (long)(n0 + p) * CLS + c] = cv;
    sc[p][c] = cv;
    __syncthreads();
    if (tid < 16) {
        double a = 0.0;
        #pragma unroll
        for (int j = 0; j < CLS; ++j) a += (double)sc[tid][j];
        out[OFF_ACT + n0 + tid] = (float)a;
    }
}

// ---------------- monotonic float <-> uint ----------------
__device__ __forceinline__ unsigned monof(float v) {
    unsigned b = __float_as_uint(v);
    return (b & 0x80000000u) ? ~b : (b | 0x80000000u);
}
__device__ __forceinline__ float unmonof(unsigned m) {
    unsigned b = (m & 0x80000000u) ? (m ^ 0x80000000u) : ~m;
    return __uint_as_float(b);
}

__device__ void sortkeys_desc(unsigned long long* s, int tid) {
    for (int k = 2; k <= 1024; k <<= 1) {
        for (int j = k >> 1; j > 0; j >>= 1) {
            __syncthreads();
            for (int i = tid; i < 1024; i += 256) {
                int ixj = i ^ j;
                if (ixj > i) {
                    bool up = ((i & k) == 0);
                    unsigned long long a = s[i], c = s[ixj];
                    if ((a < c) == up) { s[i] = c; s[ixj] = a; }
                }
            }
        }
    }
    __syncthreads();
}

// ---------------- per-batch analysis ----------------
__global__ void analysis_kernel(float* __restrict__ out) {
    __shared__ float act[TT];
    __shared__ float binv[TT];
    __shared__ unsigned long long keys[1024];
    __shared__ float s_med, s_max;

    const int b = blockIdx.x, tid = threadIdx.x;
    const float* actg = out + OFF_ACT + (long)b * TT;
    for (int t = tid; t < TT; t += 256) act[t] = actg[t];
    __syncthreads();

    for (int i = tid; i < 1024; i += 256)
        keys[i] = (i < TT) ? (((unsigned long long)monof(act[i]) << 32) | (unsigned)(1023 - i)) : 0ull;
    __syncthreads();
    sortkeys_desc(keys, tid);
    if (tid == 0) {
        s_max = unmonof((unsigned)(keys[0] >> 32));
        s_med = 0.5f * (unmonof((unsigned)(keys[374] >> 32)) +
                        unmonof((unsigned)(keys[375] >> 32)));
    }
    for (int r = tid; r < KNB; r += 256) {
        int t = 1023 - (int)(keys[r] & 1023u);
        g_sel_idx[(0 * BB + b) * KNB + r] = t;
        out[OFF_IDX + (long)b * KNB + r] = (float)t;
    }
    __syncthreads();
    const float med = s_med, mx = s_max;
    for (int t = tid; t < TT; t += 256) binv[t] = (act[t] > med) ? 1.f : 0.f;

    for (int i = tid; i < 1024; i += 256)
        keys[i] = (i < TT) ? (((unsigned long long)monof(mx - act[i]) << 32) | (unsigned)(1023 - i)) : 0ull;
    __syncthreads();
    sortkeys_desc(keys, tid);
    for (int r = tid; r < KNB; r += 256)
        g_sel_idx[(1 * BB + b) * KNB + r] = 1023 - (int)(keys[r] & 1023u);
    __syncthreads();

    for (int i = tid; i < 1024; i += 256) {
        float v = 0.f;
        if (i < TT) {
            int t = i;
            float e3 = 0.f, e6 = 0.f;
            if (t >= 1 && t <= TT - 2)
                e3 = fminf(binv[t - 1], fminf(binv[t], binv[t + 1]));
            if (t >= 3 && t <= TT - 3) {
                float m = binv[t - 3];
                m = fminf(m, binv[t - 2]); m = fminf(m, binv[t - 1]);
                m = fminf(m, binv[t]);     m = fminf(m, binv[t + 1]);
                m = fminf(m, binv[t + 2]);
                e6 = m;
            }
            v = act[t] * (e3 - e6);
        }
        keys[i] = (i < TT) ? (((unsigned long long)monof(v) << 32) | (unsigned)(1023 - i)) : 0ull;
    }
    __syncthreads();
    sortkeys_desc(keys, tid);
    for (int r = tid; r < KB2; r += 256)
        g_sel_idx[(2 * BB + b) * KNB + r] = 1023 - (int)(keys[r] & 1023u);
    __syncthreads();

    for (int i = tid; i < 1024; i += 256) {
        float v = 0.f;
        if (i < TT) {
            int t = i;
            float d3 = 0.f, d6 = 0.f;
            #pragma unroll
            for (int dt = -1; dt <= 1; ++dt) {
                int u = t + dt;
                if (u >= 0 && u < TT) d3 = fmaxf(d3, binv[u]);
            }
            #pragma unroll
            for (int dt = -2; dt <= 3; ++dt) {
                int u = t + dt;
                if (u >= 0 && u < TT) d6 = fmaxf(d6, binv[u]);
            }
            v = act[t] * (d6 - d3);
        }
        keys[i] = (i < TT) ? (((unsigned long long)monof(v) << 32) | (unsigned)(1023 - i)) : 0ull;
    }
    __syncthreads();
    sortkeys_desc(keys, tid);
    for (int r = tid; r < KB2; r += 256)
        g_sel_idx[(3 * BB + b) * KNB + r] = 1023 - (int)(keys[r] & 1023u);
}

// ---------------- gathers ----------------
__global__ void gather_kernel(float* __restrict__ out) {
    const int rowsPerB = KNB + KNB + KB2 + KB2;
    const int b = blockIdx.x / rowsPerB;
    int r = blockIdx.x % rowsPerB;
    int arr, rr; long dstOff; int kcnt;
    if (r < KNB)                { arr = 0; rr = r;                 dstOff = OFF_EA; kcnt = KNB; }
    else if (r < 2 * KNB)       { arr = 1; rr = r - KNB;           dstOff = OFF_EB; kcnt = KNB; }
    else if (r < 2 * KNB + KB2) { arr = 2; rr = r - 2 * KNB;       dstOff = OFF_HA; kcnt = KB2; }
    else                        { arr = 3; rr = r - 2 * KNB - KB2; dstOff = OFF_HB; kcnt = KB2; }
    const int tsel = g_sel_idx[(arr * BB + b) * KNB + rr];
    const float* src = out + OFF_EMB + ((long)b * TT + tsel) * CC;
    float* dst = out + dstOff + ((long)b * kcnt + rr) * CC;
    const int tid = threadIdx.x;
    for (int i = tid * 4; i < CC; i += 256 * 4) {
        *(float4*)(dst + i) = *(const float4*)(src + i);
    }
}

// ---------------- ascending bitonic float sort ----------------
__device__ inline void bitonic1024(float* s, int tid) {
    for (int k = 2; k <= 1024; k <<= 1) {
        for (int j = k >> 1; j > 0; j >>= 1) {
            __syncthreads();
            for (int i = tid; i < 1024; i += 256) {
                int ixj = i ^ j;
                if (ixj > i) {
                    bool up = ((i & k) == 0);
                    float a = s[i], c = s[ixj];
                    if ((a > c) == up) { s[i] = c; s[ixj] = a; }
                }
            }
        }
    }
    __syncthreads();
}

__global__ void cls_topk_kernel(const float* __restrict__ out) {
    __shared__ float sbuf[1024];
    __shared__ float rv[256];
    const int b = blockIdx.x / CLS, cls = blockIdx.x % CLS;
    const int tid = threadIdx.x;
    for (int i = tid; i < 1024; i += 256)
        sbuf[i] = (i < TT) ? out[OFF_CAS + ((long)(b * TT + i)) * CLS + cls] : -FLT_MAX;
    __syncthreads();
    bitonic1024(sbuf, tid);
    float s = 0.f;
    for (int i = 1024 - KNB + tid; i < 1024; i += 256) s += sbuf[i];
    rv[tid] = s;
    __syncthreads();
    for (int st = 128; st > 0; st >>= 1) {
        if (tid < st) rv[tid] += rv[tid + st];
        __syncthreads();
    }
    if (tid == 0) g_cls_mean[b * CLS + cls] = rv[0] / (float)KNB;
}

__global__ void softmax_kernel(float* __restrict__ out) {
    const int b = blockIdx.x;
    const int lane = threadIdx.x;
    float v = (lane < CLS) ? g_cls_mean[b * CLS + lane] : -FLT_MAX;
    float m = v;
    #pragma unroll
    for (int o = 16; o > 0; o >>= 1) m = fmaxf(m, __shfl_xor_sync(0xffffffffu, m, o));
    float e = (lane < CLS) ? expf(v - m) : 0.f;
    float s = e;
    #pragma unroll
    for (int o = 16; o > 0; o >>= 1) s += __shfl_xor_sync(0xffffffffu, s, o);
    if (lane < CLS) out[OFF_VS + b * CLS + lane] = e / s;
}

// ---------------- launch ----------------
extern "C" void kernel_launch(void* const* d_in, const int* in_sizes, int n_in,
                              void* d_out, int out_size) {
    const float* x      = (const float*)d_in[0];
    const float* w_rgb  = (const float*)d_in[1];
    const float* b_rgb  = (const float*)d_in[2];
    const float* w_flow = (const float*)d_in[3];
    const float* b_flow = (const float*)d_in[4];
    const float* w_cls  = (const float*)d_in[5];
    float* out = (float*)d_out;

    const int smem = NST * STG + 1024;   // 132096
    cudaFuncSetAttribute(conv_mma_kernel,
                         cudaFuncAttributeMaxDynamicSharedMemorySize, smem);

    pack_x_kernel<<<XROWS, 256>>>(x);
    pack_w_kernel<<<CC, 256>>>(w_rgb, 0);
    pack_w_kernel<<<CC, 256>>>(w_flow, 1);

    dim3 cg(BB * 6, CC / 128);   // 96 x 16
    conv_mma_kernel<<<cg, 256, smem>>>(b_rgb,  out + OFF_EMB, 0, 0);
    conv_mma_kernel<<<cg, 256, smem>>>(b_flow, out + OFF_EMB, 1, 1);

    cas_gemm_kernel<<<NPOS / 16, 320>>>(w_cls, out);
    analysis_kernel<<<BB, 256>>>(out);
    gather_kernel<<<BB * (KNB + KNB + KB2 + KB2), 256>>>(out);
    cls_topk_kernel<<<BB * CLS, 256>>>(out);
    softmax_kernel<<<BB, 32>>>(out);
}

// round 12
// speedup vs baseline: 2.2247x; 1.0009x over previous
#include <cuda_runtime.h>
#include <cuda_fp16.h>
#include <float.h>
#include <math.h>
#include <stdint.h>

// ---------------- problem constants ----------------
constexpr int BB   = 16;
constexpr int TT   = 750;
constexpr int CC   = 2048;
constexpr int CIN  = 1024;
constexpr int CLS  = 20;
constexpr int NPOS = BB * TT;
constexpr int KNB  = 150;
constexpr int KB2  = 37;
constexpr int KW   = 3 * CIN;          // 3072
constexpr int TPAD = 768;
constexpr int XROWS = BB * TPAD;       // 12288

// output layout (concatenated f32)
constexpr long OFF_VS  = 0;
constexpr long OFF_EA  = OFF_VS  + (long)BB * CLS;
constexpr long OFF_EB  = OFF_EA  + (long)BB * KNB * CC;
constexpr long OFF_HA  = OFF_EB  + (long)BB * KNB * CC;
constexpr long OFF_HB  = OFF_HA  + (long)BB * KB2 * CC;
constexpr long OFF_IDX = OFF_HB  + (long)BB * KB2 * CC;
constexpr long OFF_ACT = OFF_IDX + (long)BB * KNB;
constexpr long OFF_CAS = OFF_ACT + (long)NPOS;
constexpr long OFF_EMB = OFF_CAS + (long)NPOS * CLS;

// ---------------- device scratch ----------------
__device__ __half g_xb[4][XROWS][CIN];     // x planes: hi/lo per stream
__device__ __half g_wb[4][CC][KW];         // w planes: hi/lo per stream (x256)
__device__ int   g_sel_idx[4 * BB * KNB];
__device__ float g_cls_mean[BB * CLS];

// ---------------- PTX helpers ----------------
__device__ __forceinline__ uint32_t s2u(const void* p) {
    uint32_t a;
    asm("{ .reg .u64 t; cvta.to.shared.u64 t, %1; cvt.u32.u64 %0, t; }" : "=r"(a) : "l"(p));
    return a;
}
__device__ __forceinline__ void cp16(uint32_t dst, const void* src, int srcsz) {
    asm volatile("cp.async.cg.shared.global [%0], [%1], 16, %2;"
                 :: "r"(dst), "l"(src), "r"(srcsz) : "memory");
}

#define LDSM4(r0, r1, r2, r3, addr)                                          \
    asm volatile("ldmatrix.sync.aligned.m8n8.x4.shared.b16 {%0,%1,%2,%3}, [%4];" \
        : "=r"(r0), "=r"(r1), "=r"(r2), "=r"(r3) : "r"(addr))

#define MMAH(D, A, B)                                                        \
    asm volatile("mma.sync.aligned.m16n8k16.row.col.f32.f16.f16.f32 "        \
        "{%0,%1,%2,%3}, {%4,%5,%6,%7}, {%8,%9}, {%0,%1,%2,%3};"              \
        : "+f"((D)[0]), "+f"((D)[1]), "+f"((D)[2]), "+f"((D)[3])             \
        : "r"((A)[0]), "r"((A)[1]), "r"((A)[2]), "r"((A)[3]),                \
          "r"((B)[0]), "r"((B)[1]))

#define MMAHZ(D, A, B)                                                       \
    asm volatile("mma.sync.aligned.m16n8k16.row.col.f32.f16.f16.f32 "        \
        "{%0,%1,%2,%3}, {%4,%5,%6,%7}, {%8,%9}, {%10,%10,%10,%10};"          \
        : "=f"((D)[0]), "=f"((D)[1]), "=f"((D)[2]), "=f"((D)[3])             \
        : "r"((A)[0]), "r"((A)[1]), "r"((A)[2]), "r"((A)[3]),                \
          "r"((B)[0]), "r"((B)[1]), "f"(0.f))

#define SWZ(r, g) (((((g) ^ (((r) >> 1) & 3)) & 3) << 4))

// ---------------- split helpers ----------------
__device__ __forceinline__ void split2h(float v, __half& h0, __half& h1) {
    h0 = __float2half(v);
    h1 = __float2half(v - __half2float(h0));
}

// ---------------- pack x into 2 fp16 planes per stream ----------------
__global__ void pack_x_kernel(const float* __restrict__ x) {
    const int row = blockIdx.x;               // 0..12287
    const int b = row / TPAD, p = row % TPAD;
    const int t = p - 1;
    const bool valid = (t >= 0 && t < TT);
    const int c0 = threadIdx.x * 8;
    const int s = c0 >> 10, i0 = c0 & 1023;

    __half v0[8], v1[8];
    if (valid) {
        const float* src = x + ((long)(b * TT + t)) * CC + c0;
        float4 a = *(const float4*)src;
        float4 bb = *(const float4*)(src + 4);
        float v[8] = {a.x, a.y, a.z, a.w, bb.x, bb.y, bb.z, bb.w};
        #pragma unroll
        for (int j = 0; j < 8; ++j) split2h(v[j], v0[j], v1[j]);
    } else {
        #pragma unroll
        for (int j = 0; j < 8; ++j) { v0[j] = __float2half(0.f); v1[j] = v0[j]; }
    }
    *(uint4*)&g_xb[s * 2 + 0][row][i0] = *(uint4*)v0;
    *(uint4*)&g_xb[s * 2 + 1][row][i0] = *(uint4*)v1;
}

// ---------------- pack w (scaled by 256) ----------------
__global__ void pack_w_kernel(const float* __restrict__ w, int str) {
    const int c = blockIdx.x;
    const float* src = w + (long)c * KW;
    for (int idx = threadIdx.x; idx < KW; idx += blockDim.x) {
        int tau = idx / CIN, i = idx % CIN;
        float v = src[i * 3 + tau] * 256.f;
        __half h0, h1;
        split2h(v, h0, h1);
        g_wb[str * 2 + 0][c][idx] = h0;
        g_wb[str * 2 + 1][c][idx] = h1;
    }
}

// ---------------- HMMA conv kernel: fp16 3-term, pipelined drains ----------
// grid (96, 16), 256 threads. CTA tile: 128 pos x 128 chan, BK=32.
// 4-stage cp.async ring, one barrier per kb. Drain of group g-1's accd is
// issued AFTER group g's MMAs (double-buffered accd) -> FADDs never wait on
// in-flight MMAs. Same adds in same order per accumulator: bit-identical emb.
constexpr int A_PLANE = 8192;
constexpr int B_PLANE = 8192;
constexpr int B_OFF   = 2 * A_PLANE;      // 16384
constexpr int STG     = B_OFF + 2 * B_PLANE;  // 32768
constexpr int NKB     = 96;
constexpr int NST     = 4;

__device__ __forceinline__ void load_stage(uint32_t st, int kb, int b, int itile,
                                           int c0, int str, int tid) {
    const int tau = kb >> 5;
    const int k0  = (kb & 31) * 32;
    const int row0 = b * TPAD + itile * 128 + tau;
    #pragma unroll
    for (int p = 0; p < 2; ++p) {
        const __half* xp = &g_xb[str * 2 + p][0][0];
        #pragma unroll
        for (int n = 0; n < 2; ++n) {
            int q = n * 256 + tid;
            int r = q >> 2, g = q & 3;
            uint32_t dst = st + p * A_PLANE + r * 64 + SWZ(r, g);
            int grow = row0 + r;
            cp16(dst, xp + (long)grow * CIN + k0 + g * 8, grow < XROWS ? 16 : 0);
        }
    }
    #pragma unroll
    for (int p = 0; p < 2; ++p) {
        const __half* wp = &g_wb[str * 2 + p][0][0];
        #pragma unroll
        for (int n = 0; n < 2; ++n) {
            int q = n * 256 + tid;
            int r = q >> 2, g = q & 3;
            uint32_t dst = st + B_OFF + p * B_PLANE + r * 64 + SWZ(r, g);
            cp16(dst, wp + (long)(c0 + r) * KW + tau * CIN + k0 + g * 8, 16);
        }
    }
    asm volatile("cp.async.commit_group;" ::: "memory");
}

__global__ __launch_bounds__(256, 1)
void conv_mma_kernel(const float* __restrict__ bias, float* __restrict__ emb,
                     int str, int addMode) {
    extern __shared__ char dsm[];
    const uint32_t sb = (s2u(dsm) + 1023u) & ~1023u;

    const int tid = threadIdx.x, lane = tid & 31, wid = tid >> 5;
    const int ptile = blockIdx.x;          // 0..95
    const int b = ptile / 6, itile = ptile % 6;
    const int c0 = blockIdx.y * 128;
    const int m0 = (wid >> 2) * 64;        // warp tile: 64 x 32
    const int n0 = (wid & 3) * 32;

    float acc[4][4][4];
    #pragma unroll
    for (int i = 0; i < 4; ++i)
        #pragma unroll
        for (int j = 0; j < 4; ++j)
            #pragma unroll
            for (int k = 0; k < 4; ++k) acc[i][j][k] = 0.f;

    float accd[2][4][4];   // double-buffered per-group drain accumulators

    load_stage(sb + 0 * STG, 0, b, itile, c0, str, tid);
    load_stage(sb + 1 * STG, 1, b, itile, c0, str, tid);
    load_stage(sb + 2 * STG, 2, b, itile, c0, str, tid);

    for (int kb = 0; kb < NKB; ++kb) {
        if (kb < NKB - 3) asm volatile("cp.async.wait_group 2;" ::: "memory");
        else              asm volatile("cp.async.wait_group 0;" ::: "memory");
        __syncthreads();

        if (kb + 3 < NKB)
            load_stage(sb + ((kb + 3) & 3) * STG, kb + 3, b, itile, c0, str, tid);

        const uint32_t St = sb + (kb & 3) * STG;
        #pragma unroll
        for (int ks = 0; ks < 2; ++ks) {
            uint32_t bfr[2][4][2];
            #pragma unroll
            for (int p = 0; p < 2; ++p) {
                #pragma unroll
                for (int j = 0; j < 2; ++j) {
                    int r = n0 + (lane & 7) + ((lane >> 4) << 3) + j * 16;
                    int g = ks * 2 + ((lane >> 3) & 1);
                    uint32_t ad = St + B_OFF + p * B_PLANE + r * 64 + SWZ(r, g);
                    LDSM4(bfr[p][j * 2][0], bfr[p][j * 2][1],
                          bfr[p][j * 2 + 1][0], bfr[p][j * 2 + 1][1], ad);
                }
            }
            #pragma unroll
            for (int mi = 0; mi < 4; ++mi) {
                const int grp = ks * 4 + mi;          // 0..7, compile-time
                const int cur = grp & 1;
                uint32_t a0[4], a1[4];
                {
                    int r = m0 + mi * 16 + (lane & 15);
                    int g = ks * 2 + (lane >> 4);
                    uint32_t ad0 = St + 0 * A_PLANE + r * 64 + SWZ(r, g);
                    uint32_t ad1 = St + 1 * A_PLANE + r * 64 + SWZ(r, g);
                    LDSM4(a0[0], a0[1], a0[2], a0[3], ad0);
                    LDSM4(a1[0], a1[1], a1[2], a1[3], ad1);
                }
                #pragma unroll
                for (int ni = 0; ni < 4; ++ni) {
                    // smallest terms first, dominant last (bias control)
                    MMAHZ(accd[cur][ni], a1, bfr[0][ni]);   // x1*w0
                    MMAH (accd[cur][ni], a0, bfr[1][ni]);   // x0*w1
                    MMAH (accd[cur][ni], a0, bfr[0][ni]);   // x0*w0 LAST
                }
                if (grp > 0) {
                    const int pmi = (grp - 1) & 3;          // prev group's mi
                    #pragma unroll
                    for (int ni = 0; ni < 4; ++ni)
                        #pragma unroll
                        for (int q = 0; q < 4; ++q)
                            acc[pmi][ni][q] += accd[cur ^ 1][ni][q];  // RN drain
                }
            }
        }
        // drain last group of this kb (grp 7 -> mi 3, parity 1)
        #pragma unroll
        for (int ni = 0; ni < 4; ++ni)
            #pragma unroll
            for (int q = 0; q < 4; ++q)
                acc[3][ni][q] += accd[1][ni][q];
    }

    // epilogue: undo the 256x weight scale (exact), bias + relu (+ add)
    constexpr float IS = 1.f / 256.f;
    #pragma unroll
    for (int ni = 0; ni < 4; ++ni) {
        const int col = c0 + n0 + ni * 8 + (lane & 3) * 2;
        const float b0v = bias[col], b1v = bias[col + 1];
        #pragma unroll
        for (int mi = 0; mi < 4; ++mi) {
            const int t0 = itile * 128 + m0 + mi * 16 + (lane >> 2);
            if (t0 < TT) {
                float2* p = (float2*)(emb + ((long)(b * TT + t0)) * CC + col);
                float2 v;
                v.x = fmaxf(acc[mi][ni][0] * IS + b0v, 0.f);
                v.y = fmaxf(acc[mi][ni][1] * IS + b1v, 0.f);
                if (addMode) { float2 o = *p; v.x += o.x; v.y += o.y; }
                *p = v;
            }
            const int t1 = t0 + 8;
            if (t1 < TT) {
                float2* p = (float2*)(emb + ((long)(b * TT + t1)) * CC + col);
                float2 v;
                v.x = fmaxf(acc[mi][ni][2] * IS + b0v, 0.f);
                v.y = fmaxf(acc[mi][ni][3] * IS + b1v, 0.f);
                if (addMode) { float2 o = *p; v.x += o.x; v.y += o.y; }
                *p = v;
            }
        }
    }
}

// ---------------- cas mini-GEMM: fp32 chunks + fp64 combine ----------------
constexpr int SE_S = 257, SW_S = 261;
__global__ __launch_bounds__(320)
void cas_gemm_kernel(const float* __restrict__ wcls, float* __restrict__ out) {
    __shared__ float se[16][SE_S];
    __shared__ float sw[CLS][SW_S];
    __shared__ float sc[16][CLS];
    const int tid = threadIdx.x;
    const int n0 = blockIdx.x * 16;
    const int p = tid / CLS, c = tid % CLS;
    const float* embg = out + OFF_EMB;

    double dacc = 0.0;
    for (int kc = 0; kc < 8; ++kc) {
        for (int i = tid; i < 16 * 256; i += 320) {
            int r = i >> 8, k = i & 255;
            se[r][k] = embg[(long)(n0 + r) * CC + kc * 256 + k];
        }
        for (int i = tid; i < CLS * 256; i += 320) {
            int r = i >> 8, k = i & 255;
            sw[r][k] = wcls[(long)r * CC + kc * 256 + k];
        }
        __syncthreads();
        #pragma unroll
        for (int sub = 0; sub < 8; ++sub) {
            float part = 0.f;
            #pragma unroll
            for (int k = 0; k < 32; ++k)
                part += se[p][sub * 32 + k] * sw[c][sub * 32 + k];
            dacc += (double)part;
        }
        __syncthreads();
    }
    float cv = (float)fmax(dacc, 0.0);
    out[OFF_CAS + (long)(n0 + p) * CLS + c] = cv;
    sc[p][c] = cv;
    __syncthreads();
    if (tid < 16) {
        double a = 0.0;
        #pragma unroll
        for (int j = 0; j < CLS; ++j) a += (double)sc[tid][j];
        out[OFF_ACT + n0 + tid] = (float)a;
    }
}

// ---------------- monotonic float <-> uint ----------------
__device__ __forceinline__ unsigned monof(float v) {
    unsigned b = __float_as_uint(v);
    return (b & 0x80000000u) ? ~b : (b | 0x80000000u);
}
__device__ __forceinline__ float unmonof(unsigned m) {
    unsigned b = (m & 0x80000000u) ? (m ^ 0x80000000u) : ~m;
    return __uint_as_float(b);
}

__device__ void sortkeys_desc(unsigned long long* s, int tid) {
    for (int k = 2; k <= 1024; k <<= 1) {
        for (int j = k >> 1; j > 0; j >>= 1) {
            __syncthreads();
            for (int i = tid; i < 1024; i += 256) {
                int ixj = i ^ j;
                if (ixj > i) {
                    bool up = ((i & k) == 0);
                    unsigned long long a = s[i], c = s[ixj];
                    if ((a < c) == up) { s[i] = c; s[ixj] = a; }
                }
            }
        }
    }
    __syncthreads();
}

// ---------------- per-batch analysis ----------------
__global__ void analysis_kernel(float* __restrict__ out) {
    __shared__ float act[TT];
    __shared__ float binv[TT];
    __shared__ unsigned long long keys[1024];
    __shared__ float s_med, s_max;

    const int b = blockIdx.x, tid = threadIdx.x;
    const float* actg = out + OFF_ACT + (long)b * TT;
    for (int t = tid; t < TT; t += 256) act[t] = actg[t];
    __syncthreads();

    for (int i = tid; i < 1024; i += 256)
        keys[i] = (i < TT) ? (((unsigned long long)monof(act[i]) << 32) | (unsigned)(1023 - i)) : 0ull;
    __syncthreads();
    sortkeys_desc(keys, tid);
    if (tid == 0) {
        s_max = unmonof((unsigned)(keys[0] >> 32));
        s_med = 0.5f * (unmonof((unsigned)(keys[374] >> 32)) +
                        unmonof((unsigned)(keys[375] >> 32)));
    }
    for (int r = tid; r < KNB; r += 256) {
        int t = 1023 - (int)(keys[r] & 1023u);
        g_sel_idx[(0 * BB + b) * KNB + r] = t;
        out[OFF_IDX + (long)b * KNB + r] = (float)t;
    }
    __syncthreads();
    const float med = s_med, mx = s_max;
    for (int t = tid; t < TT; t += 256) binv[t] = (act[t] > med) ? 1.f : 0.f;

    for (int i = tid; i < 1024; i += 256)
        keys[i] = (i < TT) ? (((unsigned long long)monof(mx - act[i]) << 32) | (unsigned)(1023 - i)) : 0ull;
    __syncthreads();
    sortkeys_desc(keys, tid);
    for (int r = tid; r < KNB; r += 256)
        g_sel_idx[(1 * BB + b) * KNB + r] = 1023 - (int)(keys[r] & 1023u);
    __syncthreads();

    for (int i = tid; i < 1024; i += 256) {
        float v = 0.f;
        if (i < TT) {
            int t = i;
            float e3 = 0.f, e6 = 0.f;
            if (t >= 1 && t <= TT - 2)
                e3 = fminf(binv[t - 1], fminf(binv[t], binv[t + 1]));
            if (t >= 3 && t <= TT - 3) {
                float m = binv[t - 3];
                m = fminf(m, binv[t - 2]); m = fminf(m, binv[t - 1]);
                m = fminf(m, binv[t]);     m = fminf(m, binv[t + 1]);
                m = fminf(m, binv[t + 2]);
                e6 = m;
            }
            v = act[t] * (e3 - e6);
        }
        keys[i] = (i < TT) ? (((unsigned long long)monof(v) << 32) | (unsigned)(1023 - i)) : 0ull;
    }
    __syncthreads();
    sortkeys_desc(keys, tid);
    for (int r = tid; r < KB2; r += 256)
        g_sel_idx[(2 * BB + b) * KNB + r] = 1023 - (int)(keys[r] & 1023u);
    __syncthreads();

    for (int i = tid; i < 1024; i += 256) {
        float v = 0.f;
        if (i < TT) {
            int t = i;
            float d3 = 0.f, d6 = 0.f;
            #pragma unroll
            for (int dt = -1; dt <= 1; ++dt) {
                int u = t + dt;
                if (u >= 0 && u < TT) d3 = fmaxf(d3, binv[u]);
            }
            #pragma unroll
            for (int dt = -2; dt <= 3; ++dt) {
                int u = t + dt;
                if (u >= 0 && u < TT) d6 = fmaxf(d6, binv[u]);
            }
            v = act[t] * (d6 - d3);
        }
        keys[i] = (i < TT) ? (((unsigned long long)monof(v) << 32) | (unsigned)(1023 - i)) : 0ull;
    }
    __syncthreads();
    sortkeys_desc(keys, tid);
    for (int r = tid; r < KB2; r += 256)
        g_sel_idx[(3 * BB + b) * KNB + r] = 1023 - (int)(keys[r] & 1023u);
}

// ---------------- gathers ----------------
__global__ void gather_kernel(float* __restrict__ out) {
    const int rowsPerB = KNB + KNB + KB2 + KB2;
    const int b = blockIdx.x / rowsPerB;
    int r = blockIdx.x % rowsPerB;
    int arr, rr; long dstOff; int kcnt;
    if (r < KNB)                { arr = 0; rr = r;                 dstOff = OFF_EA; kcnt = KNB; }
    else if (r < 2 * KNB)       { arr = 1; rr = r - KNB;           dstOff = OFF_EB; kcnt = KNB; }
    else if (r < 2 * KNB + KB2) { arr = 2; rr = r - 2 * KNB;       dstOff = OFF_HA; kcnt = KB2; }
    else                        { arr = 3; rr = r - 2 * KNB - KB2; dstOff = OFF_HB; kcnt = KB2; }
    const int tsel = g_sel_idx[(arr * BB + b) * KNB + rr];
    const float* src = out + OFF_EMB + ((long)b * TT + tsel) * CC;
    float* dst = out + dstOff + ((long)b * kcnt + rr) * CC;
    const int tid = threadIdx.x;
    for (int i = tid * 4; i < CC; i += 256 * 4) {
        *(float4*)(dst + i) = *(const float4*)(src + i);
    }
}

// ---------------- ascending bitonic float sort ----------------
__device__ inline void bitonic1024(float* s, int tid) {
    for (int k = 2; k <= 1024; k <<= 1) {
        for (int j = k >> 1; j > 0; j >>= 1) {
            __syncthreads();
            for (int i = tid; i < 1024; i += 256) {
                int ixj = i ^ j;
                if (ixj > i) {
                    bool up = ((i & k) == 0);
                    float a = s[i], c = s[ixj];
                    if ((a > c) == up) { s[i] = c; s[ixj] = a; }
                }
            }
        }
    }
    __syncthreads();
}

__global__ void cls_topk_kernel(const float* __restrict__ out) {
    __shared__ float sbuf[1024];
    __shared__ float rv[256];
    const int b = blockIdx.x / CLS, cls = blockIdx.x % CLS;
    const int tid = threadIdx.x;
    for (int i = tid; i < 1024; i += 256)
        sbuf[i] = (i < TT) ? out[OFF_CAS + ((long)(b * TT + i)) * CLS + cls] : -FLT_MAX;
    __syncthreads();
    bitonic1024(sbuf, tid);
    float s = 0.f;
    for (int i = 1024 - KNB + tid; i < 1024; i += 256) s += sbuf[i];
    rv[tid] = s;
    __syncthreads();
    for (int st = 128; st > 0; st >>= 1) {
        if (tid < st) rv[tid] += rv[tid + st];
        __syncthreads();
    }
    if (tid == 0) g_cls_mean[b * CLS + cls] = rv[0] / (float)KNB;
}

__global__ void softmax_kernel(float* __restrict__ out) {
    const int b = blockIdx.x;
    const int lane = threadIdx.x;
    float v = (lane < CLS) ? g_cls_mean[b * CLS + lane] : -FLT_MAX;
    float m = v;
    #pragma unroll
    for (int o = 16; o > 0; o >>= 1) m = fmaxf(m, __shfl_xor_sync(0xffffffffu, m, o));
    float e = (lane < CLS) ? expf(v - m) : 0.f;
    float s = e;
    #pragma unroll
    for (int o = 16; o > 0; o >>= 1) s += __shfl_xor_sync(0xffffffffu, s, o);
    if (lane < CLS) out[OFF_VS + b * CLS + lane] = e / s;
}

// ---------------- launch ----------------
extern "C" void kernel_launch(void* const* d_in, const int* in_sizes, int n_in,
                              void* d_out, int out_size) {
    const float* x      = (const float*)d_in[0];
    const float* w_rgb  = (const float*)d_in[1];
    const float* b_rgb  = (const float*)d_in[2];
    const float* w_flow = (const float*)d_in[3];
    const float* b_flow = (const float*)d_in[4];
    const float* w_cls  = (const float*)d_in[5];
    float* out = (float*)d_out;

    const int smem = NST * STG + 1024;   // 132096
    cudaFuncSetAttribute(conv_mma_kernel,
                         cudaFuncAttributeMaxDynamicSharedMemorySize, smem);

    pack_x_kernel<<<XROWS, 256>>>(x);
    pack_w_kernel<<<CC, 256>>>(w_rgb, 0);
    pack_w_kernel<<<CC, 256>>>(w_flow, 1);

    dim3 cg(BB * 6, CC / 128);   // 96 x 16
    conv_mma_kernel<<<cg, 256, smem>>>(b_rgb,  out + OFF_EMB, 0, 0);
    conv_mma_kernel<<<cg, 256, smem>>>(b_flow, out + OFF_EMB, 1, 1);

    cas_gemm_kernel<<<NPOS / 16, 320>>>(w_cls, out);
    analysis_kernel<<<BB, 256>>>(out);
    gather_kernel<<<BB * (KNB + KNB + KB2 + KB2), 256>>>(out);
    cls_topk_kernel<<<BB * CLS, 256>>>(out);
    softmax_kernel<<<BB, 32>>>(out);
}

// round 13
// speedup vs baseline: 2.2262x; 1.0007x over previous
#include <cuda_runtime.h>
#include <cuda_fp16.h>
#include <float.h>
#include <math.h>
#include <stdint.h>

// ---------------- problem constants ----------------
constexpr int BB   = 16;
constexpr int TT   = 750;
constexpr int CC   = 2048;
constexpr int CIN  = 1024;
constexpr int CLS  = 20;
constexpr int NPOS = BB * TT;
constexpr int KNB  = 150;
constexpr int KB2  = 37;
constexpr int KW   = 3 * CIN;          // 3072
constexpr int TPAD = 768;
constexpr int XROWS = BB * TPAD;       // 12288

// output layout (concatenated f32)
constexpr long OFF_VS  = 0;
constexpr long OFF_EA  = OFF_VS  + (long)BB * CLS;
constexpr long OFF_EB  = OFF_EA  + (long)BB * KNB * CC;
constexpr long OFF_HA  = OFF_EB  + (long)BB * KNB * CC;
constexpr long OFF_HB  = OFF_HA  + (long)BB * KB2 * CC;
constexpr long OFF_IDX = OFF_HB  + (long)BB * KB2 * CC;
constexpr long OFF_ACT = OFF_IDX + (long)BB * KNB;
constexpr long OFF_CAS = OFF_ACT + (long)NPOS;
constexpr long OFF_EMB = OFF_CAS + (long)NPOS * CLS;

// ---------------- device scratch ----------------
__device__ __half g_xb[4][XROWS][CIN];     // x planes: hi/lo per stream
__device__ __half g_wb[4][CC][KW];         // w planes: hi/lo per stream (x256)
__device__ int   g_sel_idx[4 * BB * KNB];
__device__ float g_cls_mean[BB * CLS];

// ---------------- PTX helpers ----------------
__device__ __forceinline__ uint32_t s2u(const void* p) {
    uint32_t a;
    asm("{ .reg .u64 t; cvta.to.shared.u64 t, %1; cvt.u32.u64 %0, t; }" : "=r"(a) : "l"(p));
    return a;
}
__device__ __forceinline__ void cp16(uint32_t dst, const void* src, int srcsz) {
    asm volatile("cp.async.cg.shared.global [%0], [%1], 16, %2;"
                 :: "r"(dst), "l"(src), "r"(srcsz) : "memory");
}

#define LDSM4(r0, r1, r2, r3, addr)                                          \
    asm volatile("ldmatrix.sync.aligned.m8n8.x4.shared.b16 {%0,%1,%2,%3}, [%4];" \
        : "=r"(r0), "=r"(r1), "=r"(r2), "=r"(r3) : "r"(addr))

#define MMAH(D, A, B)                                                        \
    asm volatile("mma.sync.aligned.m16n8k16.row.col.f32.f16.f16.f32 "        \
        "{%0,%1,%2,%3}, {%4,%5,%6,%7}, {%8,%9}, {%0,%1,%2,%3};"              \
        : "+f"((D)[0]), "+f"((D)[1]), "+f"((D)[2]), "+f"((D)[3])             \
        : "r"((A)[0]), "r"((A)[1]), "r"((A)[2]), "r"((A)[3]),                \
          "r"((B)[0]), "r"((B)[1]))

#define MMAHZ(D, A, B)                                                       \
    asm volatile("mma.sync.aligned.m16n8k16.row.col.f32.f16.f16.f32 "        \
        "{%0,%1,%2,%3}, {%4,%5,%6,%7}, {%8,%9}, {%10,%10,%10,%10};"          \
        : "=f"((D)[0]), "=f"((D)[1]), "=f"((D)[2]), "=f"((D)[3])             \
        : "r"((A)[0]), "r"((A)[1]), "r"((A)[2]), "r"((A)[3]),                \
          "r"((B)[0]), "r"((B)[1]), "f"(0.f))

#define SWZ(r, g) (((((g) ^ (((r) >> 1) & 3)) & 3) << 4))

// ---------------- split helpers ----------------
__device__ __forceinline__ void split2h(float v, __half& h0, __half& h1) {
    h0 = __float2half(v);
    h1 = __float2half(v - __half2float(h0));
}

// ---------------- pack x into 2 fp16 planes per stream ----------------
__global__ void pack_x_kernel(const float* __restrict__ x) {
    const int row = blockIdx.x;               // 0..12287
    const int b = row / TPAD, p = row % TPAD;
    const int t = p - 1;
    const bool valid = (t >= 0 && t < TT);
    const int c0 = threadIdx.x * 8;
    const int s = c0 >> 10, i0 = c0 & 1023;

    __half v0[8], v1[8];
    if (valid) {
        const float* src = x + ((long)(b * TT + t)) * CC + c0;
        float4 a = *(const float4*)src;
        float4 bb = *(const float4*)(src + 4);
        float v[8] = {a.x, a.y, a.z, a.w, bb.x, bb.y, bb.z, bb.w};
        #pragma unroll
        for (int j = 0; j < 8; ++j) split2h(v[j], v0[j], v1[j]);
    } else {
        #pragma unroll
        for (int j = 0; j < 8; ++j) { v0[j] = __float2half(0.f); v1[j] = v0[j]; }
    }
    *(uint4*)&g_xb[s * 2 + 0][row][i0] = *(uint4*)v0;
    *(uint4*)&g_xb[s * 2 + 1][row][i0] = *(uint4*)v1;
}

// ---------------- pack w (scaled by 256) ----------------
__global__ void pack_w_kernel(const float* __restrict__ w, int str) {
    const int c = blockIdx.x;
    const float* src = w + (long)c * KW;
    for (int idx = threadIdx.x; idx < KW; idx += blockDim.x) {
        int tau = idx / CIN, i = idx % CIN;
        float v = src[i * 3 + tau] * 256.f;
        __half h0, h1;
        split2h(v, h0, h1);
        g_wb[str * 2 + 0][c][idx] = h0;
        g_wb[str * 2 + 1][c][idx] = h1;
    }
}

// ---------------- HMMA conv kernel: fp16 3-term, 16 warps (TLP) -----------
// grid (96, 16), 512 threads. CTA tile: 128 pos x 128 chan, BK=32.
// Warp tile 32x32 (4m x 4n warp grid) -> 4 warps/SMSP hide HMMA latency.
// 4-stage cp.async ring, one barrier per kb. Per-accumulator math order
// unchanged -> emb bit-identical to round-10/11/12 kernels.
constexpr int A_PLANE = 8192;
constexpr int B_PLANE = 8192;
constexpr int B_OFF   = 2 * A_PLANE;      // 16384
constexpr int STG     = B_OFF + 2 * B_PLANE;  // 32768
constexpr int NKB     = 96;
constexpr int NST     = 4;

__device__ __forceinline__ void load_stage(uint32_t st, int kb, int b, int itile,
                                           int c0, int str, int tid) {
    const int tau = kb >> 5;
    const int k0  = (kb & 31) * 32;
    const int row0 = b * TPAD + itile * 128 + tau;
    const int r = tid >> 2, g = tid & 3;   // 512 threads: one chunk per plane
    #pragma unroll
    for (int p = 0; p < 2; ++p) {
        const __half* xp = &g_xb[str * 2 + p][0][0];
        uint32_t dst = st + p * A_PLANE + r * 64 + SWZ(r, g);
        int grow = row0 + r;
        cp16(dst, xp + (long)grow * CIN + k0 + g * 8, grow < XROWS ? 16 : 0);
    }
    #pragma unroll
    for (int p = 0; p < 2; ++p) {
        const __half* wp = &g_wb[str * 2 + p][0][0];
        uint32_t dst = st + B_OFF + p * B_PLANE + r * 64 + SWZ(r, g);
        cp16(dst, wp + (long)(c0 + r) * KW + tau * CIN + k0 + g * 8, 16);
    }
    asm volatile("cp.async.commit_group;" ::: "memory");
}

__global__ __launch_bounds__(512, 1)
void conv_mma_kernel(const float* __restrict__ bias, float* __restrict__ emb,
                     int str, int addMode) {
    extern __shared__ char dsm[];
    const uint32_t sb = (s2u(dsm) + 1023u) & ~1023u;

    const int tid = threadIdx.x, lane = tid & 31, wid = tid >> 5;
    const int ptile = blockIdx.x;          // 0..95
    const int b = ptile / 6, itile = ptile % 6;
    const int c0 = blockIdx.y * 128;
    const int m0 = (wid >> 2) * 32;        // warp tile: 32 x 32 (4m x 4n)
    const int n0 = (wid & 3) * 32;

    float acc[2][4][4];
    #pragma unroll
    for (int i = 0; i < 2; ++i)
        #pragma unroll
        for (int j = 0; j < 4; ++j)
            #pragma unroll
            for (int k = 0; k < 4; ++k) acc[i][j][k] = 0.f;

    load_stage(sb + 0 * STG, 0, b, itile, c0, str, tid);
    load_stage(sb + 1 * STG, 1, b, itile, c0, str, tid);
    load_stage(sb + 2 * STG, 2, b, itile, c0, str, tid);

    for (int kb = 0; kb < NKB; ++kb) {
        if (kb < NKB - 3) asm volatile("cp.async.wait_group 2;" ::: "memory");
        else              asm volatile("cp.async.wait_group 0;" ::: "memory");
        __syncthreads();

        if (kb + 3 < NKB)
            load_stage(sb + ((kb + 3) & 3) * STG, kb + 3, b, itile, c0, str, tid);

        const uint32_t St = sb + (kb & 3) * STG;
        #pragma unroll
        for (int ks = 0; ks < 2; ++ks) {
            uint32_t bfr[2][4][2];
            #pragma unroll
            for (int p = 0; p < 2; ++p) {
                #pragma unroll
                for (int j = 0; j < 2; ++j) {
                    int r = n0 + (lane & 7) + ((lane >> 4) << 3) + j * 16;
                    int g = ks * 2 + ((lane >> 3) & 1);
                    uint32_t ad = St + B_OFF + p * B_PLANE + r * 64 + SWZ(r, g);
                    LDSM4(bfr[p][j * 2][0], bfr[p][j * 2][1],
                          bfr[p][j * 2 + 1][0], bfr[p][j * 2 + 1][1], ad);
                }
            }
            #pragma unroll
            for (int mi = 0; mi < 2; ++mi) {
                uint32_t a0[4], a1[4];
                {
                    int r = m0 + mi * 16 + (lane & 15);
                    int g = ks * 2 + (lane >> 4);
                    uint32_t ad0 = St + 0 * A_PLANE + r * 64 + SWZ(r, g);
                    uint32_t ad1 = St + 1 * A_PLANE + r * 64 + SWZ(r, g);
                    LDSM4(a0[0], a0[1], a0[2], a0[3], ad0);
                    LDSM4(a1[0], a1[1], a1[2], a1[3], ad1);
                }
                float accd[4][4];
                #pragma unroll
                for (int ni = 0; ni < 4; ++ni) {
                    // smallest terms first, dominant last (bias control)
                    MMAHZ(accd[ni], a1, bfr[0][ni]);   // x1*w0
                    MMAH (accd[ni], a0, bfr[1][ni]);   // x0*w1
                    MMAH (accd[ni], a0, bfr[0][ni]);   // x0*w0 LAST
                }
                #pragma unroll
                for (int ni = 0; ni < 4; ++ni)
                    #pragma unroll
                    for (int q = 0; q < 4; ++q)
                        acc[mi][ni][q] += accd[ni][q];  // RN drain
            }
        }
    }

    // epilogue: undo the 256x weight scale (exact), bias + relu (+ add)
    constexpr float IS = 1.f / 256.f;
    #pragma unroll
    for (int ni = 0; ni < 4; ++ni) {
        const int col = c0 + n0 + ni * 8 + (lane & 3) * 2;
        const float b0v = bias[col], b1v = bias[col + 1];
        #pragma unroll
        for (int mi = 0; mi < 2; ++mi) {
            const int t0 = itile * 128 + m0 + mi * 16 + (lane >> 2);
            if (t0 < TT) {
                float2* p = (float2*)(emb + ((long)(b * TT + t0)) * CC + col);
                float2 v;
                v.x = fmaxf(acc[mi][ni][0] * IS + b0v, 0.f);
                v.y = fmaxf(acc[mi][ni][1] * IS + b1v, 0.f);
                if (addMode) { float2 o = *p; v.x += o.x; v.y += o.y; }
                *p = v;
            }
            const int t1 = t0 + 8;
            if (t1 < TT) {
                float2* p = (float2*)(emb + ((long)(b * TT + t1)) * CC + col);
                float2 v;
                v.x = fmaxf(acc[mi][ni][2] * IS + b0v, 0.f);
                v.y = fmaxf(acc[mi][ni][3] * IS + b1v, 0.f);
                if (addMode) { float2 o = *p; v.x += o.x; v.y += o.y; }
                *p = v;
            }
        }
    }
}

// ---------------- cas mini-GEMM: fp32 chunks + fp64 combine ----------------
constexpr int SE_S = 257, SW_S = 261;
__global__ __launch_bounds__(320)
void cas_gemm_kernel(const float* __restrict__ wcls, float* __restrict__ out) {
    __shared__ float se[16][SE_S];
    __shared__ float sw[CLS][SW_S];
    __shared__ float sc[16][CLS];
    const int tid = threadIdx.x;
    const int n0 = blockIdx.x * 16;
    const int p = tid / CLS, c = tid % CLS;
    const float* embg = out + OFF_EMB;

    double dacc = 0.0;
    for (int kc = 0; kc < 8; ++kc) {
        for (int i = tid; i < 16 * 256; i += 320) {
            int r = i >> 8, k = i & 255;
            se[r][k] = embg[(long)(n0 + r) * CC + kc * 256 + k];
        }
        for (int i = tid; i < CLS * 256; i += 320) {
            int r = i >> 8, k = i & 255;
            sw[r][k] = wcls[(long)r * CC + kc * 256 + k];
        }
        __syncthreads();
        #pragma unroll
        for (int sub = 0; sub < 8; ++sub) {
            float part = 0.f;
            #pragma unroll
            for (int k = 0; k < 32; ++k)
                part += se[p][sub * 32 + k] * sw[c][sub * 32 + k];
            dacc += (double)part;
        }
        __syncthreads();
    }
    float cv = (float)fmax(dacc, 0.0);
    out[OFF_CAS + (long)(n0 + p) * CLS + c] = cv;
    sc[p][c] = cv;
    __syncthreads();
    if (tid < 16) {
        double a = 0.0;
        #pragma unroll
        for (int j = 0; j < CLS; ++j) a += (double)sc[tid][j];
        out[OFF_ACT + n0 + tid] = (float)a;
    }
}

// ---------------- monotonic float <-> uint ----------------
__device__ __forceinline__ unsigned monof(float v) {
    unsigned b = __float_as_uint(v);
    return (b & 0x80000000u) ? ~b : (b | 0x80000000u);
}
__device__ __forceinline__ float unmonof(unsigned m) {
    unsigned b = (m & 0x80000000u) ? (m ^ 0x80000000u) : ~m;
    return __uint_as_float(b);
}

__device__ void sortkeys_desc(unsigned long long* s, int tid) {
    for (int k = 2; k <= 1024; k <<= 1) {
        for (int j = k >> 1; j > 0; j >>= 1) {
            __syncthreads();
            for (int i = tid; i < 1024; i += 256) {
                int ixj = i ^ j;
                if (ixj > i) {
                    bool up = ((i & k) == 0);
                    unsigned long long a = s[i], c = s[ixj];
                    if ((a < c) == up) { s[i] = c; s[ixj] = a; }
                }
            }
        }
    }
    __syncthreads();
}

// ---------------- per-batch analysis ----------------
__global__ void analysis_kernel(float* __restrict__ out) {
    __shared__ float act[TT];
    __shared__ float binv[TT];
    __shared__ unsigned long long keys[1024];
    __shared__ float s_med, s_max;

    const int b = blockIdx.x, tid = threadIdx.x;
    const float* actg = out + OFF_ACT + (long)b * TT;
    for (int t = tid; t < TT; t += 256) act[t] = actg[t];
    __syncthreads();

    for (int i = tid; i < 1024; i += 256)
        keys[i] = (i < TT) ? (((unsigned long long)monof(act[i]) << 32) | (unsigned)(1023 - i)) : 0ull;
    __syncthreads();
    sortkeys_desc(keys, tid);
    if (tid == 0) {
        s_max = unmonof((unsigned)(keys[0] >> 32));
        s_med = 0.5f * (unmonof((unsigned)(keys[374] >> 32)) +
                        unmonof((unsigned)(keys[375] >> 32)));
    }
    for (int r = tid; r < KNB; r += 256) {
        int t = 1023 - (int)(keys[r] & 1023u);
        g_sel_idx[(0 * BB + b) * KNB + r] = t;
        out[OFF_IDX + (long)b * KNB + r] = (float)t;
    }
    __syncthreads();
    const float med = s_med, mx = s_max;
    for (int t = tid; t < TT; t += 256) binv[t] = (act[t] > med) ? 1.f : 0.f;

    for (int i = tid; i < 1024; i += 256)
        keys[i] = (i < TT) ? (((unsigned long long)monof(mx - act[i]) << 32) | (unsigned)(1023 - i)) : 0ull;
    __syncthreads();
    sortkeys_desc(keys, tid);
    for (int r = tid; r < KNB; r += 256)
        g_sel_idx[(1 * BB + b) * KNB + r] = 1023 - (int)(keys[r] & 1023u);
    __syncthreads();

    for (int i = tid; i < 1024; i += 256) {
        float v = 0.f;
        if (i < TT) {
            int t = i;
            float e3 = 0.f, e6 = 0.f;
            if (t >= 1 && t <= TT - 2)
                e3 = fminf(binv[t - 1], fminf(binv[t], binv[t + 1]));
            if (t >= 3 && t <= TT - 3) {
                float m = binv[t - 3];
                m = fminf(m, binv[t - 2]); m = fminf(m, binv[t - 1]);
                m = fminf(m, binv[t]);     m = fminf(m, binv[t + 1]);
                m = fminf(m, binv[t + 2]);
                e6 = m;
            }
            v = act[t] * (e3 - e6);
        }
        keys[i] = (i < TT) ? (((unsigned long long)monof(v) << 32) | (unsigned)(1023 - i)) : 0ull;
    }
    __syncthreads();
    sortkeys_desc(keys, tid);
    for (int r = tid; r < KB2; r += 256)
        g_sel_idx[(2 * BB + b) * KNB + r] = 1023 - (int)(keys[r] & 1023u);
    __syncthreads();

    for (int i = tid; i < 1024; i += 256) {
        float v = 0.f;
        if (i < TT) {
            int t = i;
            float d3 = 0.f, d6 = 0.f;
            #pragma unroll
            for (int dt = -1; dt <= 1; ++dt) {
                int u = t + dt;
                if (u >= 0 && u < TT) d3 = fmaxf(d3, binv[u]);
            }
            #pragma unroll
            for (int dt = -2; dt <= 3; ++dt) {
                int u = t + dt;
                if (u >= 0 && u < TT) d6 = fmaxf(d6, binv[u]);
            }
            v = act[t] * (d6 - d3);
        }
        keys[i] = (i < TT) ? (((unsigned long long)monof(v) << 32) | (unsigned)(1023 - i)) : 0ull;
    }
    __syncthreads();
    sortkeys_desc(keys, tid);
    for (int r = tid; r < KB2; r += 256)
        g_sel_idx[(3 * BB + b) * KNB + r] = 1023 - (int)(keys[r] & 1023u);
}

// ---------------- gathers ----------------
__global__ void gather_kernel(float* __restrict__ out) {
    const int rowsPerB = KNB + KNB + KB2 + KB2;
    const int b = blockIdx.x / rowsPerB;
    int r = blockIdx.x % rowsPerB;
    int arr, rr; long dstOff; int kcnt;
    if (r < KNB)                { arr = 0; rr = r;                 dstOff = OFF_EA; kcnt = KNB; }
    else if (r < 2 * KNB)       { arr = 1; rr = r - KNB;           dstOff = OFF_EB; kcnt = KNB; }
    else if (r < 2 * KNB + KB2) { arr = 2; rr = r - 2 * KNB;       dstOff = OFF_HA; kcnt = KB2; }
    else                        { arr = 3; rr = r - 2 * KNB - KB2; dstOff = OFF_HB; kcnt = KB2; }
    const int tsel = g_sel_idx[(arr * BB + b) * KNB + rr];
    const float* src = out + OFF_EMB + ((long)b * TT + tsel) * CC;
    float* dst = out + dstOff + ((long)b * kcnt + rr) * CC;
    const int tid = threadIdx.x;
    for (int i = tid * 4; i < CC; i += 256 * 4) {
        *(float4*)(dst + i) = *(const float4*)(src + i);
    }
}

// ---------------- ascending bitonic float sort ----------------
__device__ inline void bitonic1024(float* s, int tid) {
    for (int k = 2; k <= 1024; k <<= 1) {
        for (int j = k >> 1; j > 0; j >>= 1) {
            __syncthreads();
            for (int i = tid; i < 1024; i += 256) {
                int ixj = i ^ j;
                if (ixj > i) {
                    bool up = ((i & k) == 0);
                    float a = s[i], c = s[ixj];
                    if ((a > c) == up) { s[i] = c; s[ixj] = a; }
                }
            }
        }
    }
    __syncthreads();
}

__global__ void cls_topk_kernel(const float* __restrict__ out) {
    __shared__ float sbuf[1024];
    __shared__ float rv[256];
    const int b = blockIdx.x / CLS, cls = blockIdx.x % CLS;
    const int tid = threadIdx.x;
    for (int i = tid; i < 1024; i += 256)
        sbuf[i] = (i < TT) ? out[OFF_CAS + ((long)(b * TT + i)) * CLS + cls] : -FLT_MAX;
    __syncthreads();
    bitonic1024(sbuf, tid);
    float s = 0.f;
    for (int i = 1024 - KNB + tid; i < 1024; i += 256) s += sbuf[i];
    rv[tid] = s;
    __syncthreads();
    for (int st = 128; st > 0; st >>= 1) {
        if (tid < st) rv[tid] += rv[tid + st];
        __syncthreads();
    }
    if (tid == 0) g_cls_mean[b * CLS + cls] = rv[0] / (float)KNB;
}

__global__ void softmax_kernel(float* __restrict__ out) {
    const int b = blockIdx.x;
    const int lane = threadIdx.x;
    float v = (lane < CLS) ? g_cls_mean[b * CLS + lane] : -FLT_MAX;
    float m = v;
    #pragma unroll
    for (int o = 16; o > 0; o >>= 1) m = fmaxf(m, __shfl_xor_sync(0xffffffffu, m, o));
    float e = (lane < CLS) ? expf(v - m) : 0.f;
    float s = e;
    #pragma unroll
    for (int o = 16; o > 0; o >>= 1) s += __shfl_xor_sync(0xffffffffu, s, o);
    if (lane < CLS) out[OFF_VS + b * CLS + lane] = e / s;
}

// ---------------- launch ----------------
extern "C" void kernel_launch(void* const* d_in, const int* in_sizes, int n_in,
                              void* d_out, int out_size) {
    const float* x      = (const float*)d_in[0];
    const float* w_rgb  = (const float*)d_in[1];
    const float* b_rgb  = (const float*)d_in[2];
    const float* w_flow = (const float*)d_in[3];
    const float* b_flow = (const float*)d_in[4];
    const float* w_cls  = (const float*)d_in[5];
    float* out = (float*)d_out;

    const int smem = NST * STG + 1024;   // 132096
    cudaFuncSetAttribute(conv_mma_kernel,
                         cudaFuncAttributeMaxDynamicSharedMemorySize, smem);

    pack_x_kernel<<<XROWS, 256>>>(x);
    pack_w_kernel<<<CC, 256>>>(w_rgb, 0);
    pack_w_kernel<<<CC, 256>>>(w_flow, 1);

    dim3 cg(BB * 6, CC / 128);   // 96 x 16
    conv_mma_kernel<<<cg, 512, smem>>>(b_rgb,  out + OFF_EMB, 0, 0);
    conv_mma_kernel<<<cg, 512, smem>>>(b_flow, out + OFF_EMB, 1, 1);

    cas_gemm_kernel<<<NPOS / 16, 320>>>(w_cls, out);
    analysis_kernel<<<BB, 256>>>(out);
    gather_kernel<<<BB * (KNB + KNB + KB2 + KB2), 256>>>(out);
    cls_topk_kernel<<<BB * CLS, 256>>>(out);
    softmax_kernel<<<BB, 32>>>(out);
}

// round 16
// speedup vs baseline: 2.2440x; 1.0080x over previous
#include <cuda_runtime.h>
#include <cuda_fp16.h>
#include <float.h>
#include <math.h>
#include <stdint.h>

// ---------------- problem constants ----------------
constexpr int BB   = 16;
constexpr int TT   = 750;
constexpr int CC   = 2048;
constexpr int CIN  = 1024;
constexpr int CLS  = 20;
constexpr int NPOS = BB * TT;
constexpr int KNB  = 150;
constexpr int KB2  = 37;
constexpr int KW   = 3 * CIN;          // 3072
constexpr int TPAD = 768;
constexpr int XROWS = BB * TPAD;       // 12288

// output layout (concatenated f32)
constexpr long OFF_VS  = 0;
constexpr long OFF_EA  = OFF_VS  + (long)BB * CLS;
constexpr long OFF_EB  = OFF_EA  + (long)BB * KNB * CC;
constexpr long OFF_HA  = OFF_EB  + (long)BB * KNB * CC;
constexpr long OFF_HB  = OFF_HA  + (long)BB * KB2 * CC;
constexpr long OFF_IDX = OFF_HB  + (long)BB * KB2 * CC;
constexpr long OFF_ACT = OFF_IDX + (long)BB * KNB;
constexpr long OFF_CAS = OFF_ACT + (long)NPOS;
constexpr long OFF_EMB = OFF_CAS + (long)NPOS * CLS;

// ---------------- device scratch ----------------
__device__ __half g_xb[4][XROWS][CIN];     // x planes: hi/lo per stream
__device__ __half g_wb[4][CC][KW];         // w planes: hi/lo per stream (x256)
__device__ int   g_sel_idx[4 * BB * KNB];
__device__ float g_cls_mean[BB * CLS];

// ---------------- PTX helpers ----------------
__device__ __forceinline__ uint32_t s2u(const void* p) {
    uint32_t a;
    asm("{ .reg .u64 t; cvta.to.shared.u64 t, %1; cvt.u32.u64 %0, t; }" : "=r"(a) : "l"(p));
    return a;
}
__device__ __forceinline__ void cp16(uint32_t dst, const void* src, int srcsz) {
    asm volatile("cp.async.cg.shared.global [%0], [%1], 16, %2;"
                 :: "r"(dst), "l"(src), "r"(srcsz) : "memory");
}

#define LDSM4(r0, r1, r2, r3, addr)                                          \
    asm volatile("ldmatrix.sync.aligned.m8n8.x4.shared.b16 {%0,%1,%2,%3}, [%4];" \
        : "=r"(r0), "=r"(r1), "=r"(r2), "=r"(r3) : "r"(addr))

#define MMAH(D, A, B)                                                        \
    asm volatile("mma.sync.aligned.m16n8k16.row.col.f32.f16.f16.f32 "        \
        "{%0,%1,%2,%3}, {%4,%5,%6,%7}, {%8,%9}, {%0,%1,%2,%3};"              \
        : "+f"((D)[0]), "+f"((D)[1]), "+f"((D)[2]), "+f"((D)[3])             \
        : "r"((A)[0]), "r"((A)[1]), "r"((A)[2]), "r"((A)[3]),                \
          "r"((B)[0]), "r"((B)[1]))

#define MMAHZ(D, A, B)                                                       \
    asm volatile("mma.sync.aligned.m16n8k16.row.col.f32.f16.f16.f32 "        \
        "{%0,%1,%2,%3}, {%4,%5,%6,%7}, {%8,%9}, {%10,%10,%10,%10};"          \
        : "=f"((D)[0]), "=f"((D)[1]), "=f"((D)[2]), "=f"((D)[3])             \
        : "r"((A)[0]), "r"((A)[1]), "r"((A)[2]), "r"((A)[3]),                \
          "r"((B)[0]), "r"((B)[1]), "f"(0.f))

#define SWZ(r, g) (((((g) ^ (((r) >> 1) & 3)) & 3) << 4))

// ---------------- split helpers ----------------
__device__ __forceinline__ void split2h(float v, __half& h0, __half& h1) {
    h0 = __float2half(v);
    h1 = __float2half(v - __half2float(h0));
}

// ---------------- pack x into 2 fp16 planes per stream ----------------
__global__ void pack_x_kernel(const float* __restrict__ x) {
    const int row = blockIdx.x;               // 0..12287
    const int b = row / TPAD, p = row % TPAD;
    const int t = p - 1;
    const bool valid = (t >= 0 && t < TT);
    const int c0 = threadIdx.x * 8;
    const int s = c0 >> 10, i0 = c0 & 1023;

    __half v0[8], v1[8];
    if (valid) {
        const float* src = x + ((long)(b * TT + t)) * CC + c0;
        float4 a = *(const float4*)src;
        float4 bb = *(const float4*)(src + 4);
        float v[8] = {a.x, a.y, a.z, a.w, bb.x, bb.y, bb.z, bb.w};
        #pragma unroll
        for (int j = 0; j < 8; ++j) split2h(v[j], v0[j], v1[j]);
    } else {
        #pragma unroll
        for (int j = 0; j < 8; ++j) { v0[j] = __float2half(0.f); v1[j] = v0[j]; }
    }
    *(uint4*)&g_xb[s * 2 + 0][row][i0] = *(uint4*)v0;
    *(uint4*)&g_xb[s * 2 + 1][row][i0] = *(uint4*)v1;
}

// ---------------- pack w (scaled by 256) ----------------
__global__ void pack_w_kernel(const float* __restrict__ w, int str) {
    const int c = blockIdx.x;
    const float* src = w + (long)c * KW;
    for (int idx = threadIdx.x; idx < KW; idx += blockDim.x) {
        int tau = idx / CIN, i = idx % CIN;
        float v = src[i * 3 + tau] * 256.f;
        __half h0, h1;
        split2h(v, h0, h1);
        g_wb[str * 2 + 0][c][idx] = h0;
        g_wb[str * 2 + 1][c][idx] = h1;
    }
}

// ---------------- HMMA conv kernel: fp16 3-term fp32-acc (R13 proven) -----
// grid (96, 16), 512 threads. CTA tile: 128 pos x 128 chan, BK=32.
// 4-stage cp.async ring, one barrier per kb. Warp tile 32x32 (4m x 4n).
constexpr int A_PLANE = 8192;
constexpr int B_PLANE = 8192;
constexpr int B_OFF   = 2 * A_PLANE;      // 16384
constexpr int STG     = B_OFF + 2 * B_PLANE;  // 32768
constexpr int NKB     = 96;
constexpr int NST     = 4;

__device__ __forceinline__ void load_stage(uint32_t st, int kb, int b, int itile,
                                           int c0, int str, int tid) {
    const int tau = kb >> 5;
    const int k0  = (kb & 31) * 32;
    const int row0 = b * TPAD + itile * 128 + tau;
    const int r = tid >> 2, g = tid & 3;   // 512 threads: one chunk per plane
    #pragma unroll
    for (int p = 0; p < 2; ++p) {
        const __half* xp = &g_xb[str * 2 + p][0][0];
        uint32_t dst = st + p * A_PLANE + r * 64 + SWZ(r, g);
        int grow = row0 + r;
        cp16(dst, xp + (long)grow * CIN + k0 + g * 8, grow < XROWS ? 16 : 0);
    }
    #pragma unroll
    for (int p = 0; p < 2; ++p) {
        const __half* wp = &g_wb[str * 2 + p][0][0];
        uint32_t dst = st + B_OFF + p * B_PLANE + r * 64 + SWZ(r, g);
        cp16(dst, wp + (long)(c0 + r) * KW + tau * CIN + k0 + g * 8, 16);
    }
    asm volatile("cp.async.commit_group;" ::: "memory");
}

__global__ __launch_bounds__(512, 1)
void conv_mma_kernel(const float* __restrict__ bias, float* __restrict__ emb,
                     int str, int addMode) {
    extern __shared__ char dsm[];
    const uint32_t sb = (s2u(dsm) + 1023u) & ~1023u;

    const int tid = threadIdx.x, lane = tid & 31, wid = tid >> 5;
    const int ptile = blockIdx.x;          // 0..95
    const int b = ptile / 6, itile = ptile % 6;
    const int c0 = blockIdx.y * 128;
    const int m0 = (wid >> 2) * 32;        // warp tile: 32 x 32 (4m x 4n)
    const int n0 = (wid & 3) * 32;

    float acc[2][4][4];
    #pragma unroll
    for (int i = 0; i < 2; ++i)
        #pragma unroll
        for (int j = 0; j < 4; ++j)
            #pragma unroll
            for (int k = 0; k < 4; ++k) acc[i][j][k] = 0.f;

    load_stage(sb + 0 * STG, 0, b, itile, c0, str, tid);
    load_stage(sb + 1 * STG, 1, b, itile, c0, str, tid);
    load_stage(sb + 2 * STG, 2, b, itile, c0, str, tid);

    for (int kb = 0; kb < NKB; ++kb) {
        if (kb < NKB - 3) asm volatile("cp.async.wait_group 2;" ::: "memory");
        else              asm volatile("cp.async.wait_group 0;" ::: "memory");
        __syncthreads();

        if (kb + 3 < NKB)
            load_stage(sb + ((kb + 3) & 3) * STG, kb + 3, b, itile, c0, str, tid);

        const uint32_t St = sb + (kb & 3) * STG;
        #pragma unroll
        for (int ks = 0; ks < 2; ++ks) {
            uint32_t bfr[2][4][2];
            #pragma unroll
            for (int p = 0; p < 2; ++p) {
                #pragma unroll
                for (int j = 0; j < 2; ++j) {
                    int r = n0 + (lane & 7) + ((lane >> 4) << 3) + j * 16;
                    int g = ks * 2 + ((lane >> 3) & 1);
                    uint32_t ad = St + B_OFF + p * B_PLANE + r * 64 + SWZ(r, g);
                    LDSM4(bfr[p][j * 2][0], bfr[p][j * 2][1],
                          bfr[p][j * 2 + 1][0], bfr[p][j * 2 + 1][1], ad);
                }
            }
            #pragma unroll
            for (int mi = 0; mi < 2; ++mi) {
                uint32_t a0[4], a1[4];
                {
                    int r = m0 + mi * 16 + (lane & 15);
                    int g = ks * 2 + (lane >> 4);
                    uint32_t ad0 = St + 0 * A_PLANE + r * 64 + SWZ(r, g);
                    uint32_t ad1 = St + 1 * A_PLANE + r * 64 + SWZ(r, g);
                    LDSM4(a0[0], a0[1], a0[2], a0[3], ad0);
                    LDSM4(a1[0], a1[1], a1[2], a1[3], ad1);
                }
                float accd[4][4];
                #pragma unroll
                for (int ni = 0; ni < 4; ++ni) {
                    // smallest terms first, dominant last (bias control)
                    MMAHZ(accd[ni], a1, bfr[0][ni]);   // x1*w0
                    MMAH (accd[ni], a0, bfr[1][ni]);   // x0*w1
                    MMAH (accd[ni], a0, bfr[0][ni]);   // x0*w0 LAST
                }
                #pragma unroll
                for (int ni = 0; ni < 4; ++ni)
                    #pragma unroll
                    for (int q = 0; q < 4; ++q)
                        acc[mi][ni][q] += accd[ni][q];  // RN drain
            }
        }
    }

    // epilogue: undo the 256x weight scale (exact), bias + relu (+ add)
    constexpr float IS = 1.f / 256.f;
    #pragma unroll
    for (int ni = 0; ni < 4; ++ni) {
        const int col = c0 + n0 + ni * 8 + (lane & 3) * 2;
        const float b0v = bias[col], b1v = bias[col + 1];
        #pragma unroll
        for (int mi = 0; mi < 2; ++mi) {
            const int t0 = itile * 128 + m0 + mi * 16 + (lane >> 2);
            if (t0 < TT) {
                float2* p = (float2*)(emb + ((long)(b * TT + t0)) * CC + col);
                float2 v;
                v.x = fmaxf(acc[mi][ni][0] * IS + b0v, 0.f);
                v.y = fmaxf(acc[mi][ni][1] * IS + b1v, 0.f);
                if (addMode) { float2 o = *p; v.x += o.x; v.y += o.y; }
                *p = v;
            }
            const int t1 = t0 + 8;
            if (t1 < TT) {
                float2* p = (float2*)(emb + ((long)(b * TT + t1)) * CC + col);
                float2 v;
                v.x = fmaxf(acc[mi][ni][2] * IS + b0v, 0.f);
                v.y = fmaxf(acc[mi][ni][3] * IS + b1v, 0.f);
                if (addMode) { float2 o = *p; v.x += o.x; v.y += o.y; }
                *p = v;
            }
        }
    }
}

// ---------------- cas mini-GEMM: fp32 chunks + fp64 combine ----------------
constexpr int SE_S = 257, SW_S = 261;
__global__ __launch_bounds__(320)
void cas_gemm_kernel(const float* __restrict__ wcls, float* __restrict__ out) {
    __shared__ float se[16][SE_S];
    __shared__ float sw[CLS][SW_S];
    __shared__ float sc[16][CLS];
    const int tid = threadIdx.x;
    const int n0 = blockIdx.x * 16;
    const int p = tid / CLS, c = tid % CLS;
    const float* embg = out + OFF_EMB;

    double dacc = 0.0;
    for (int kc = 0; kc < 8; ++kc) {
        for (int i = tid; i < 16 * 256; i += 320) {
            int r = i >> 8, k = i & 255;
            se[r][k] = embg[(long)(n0 + r) * CC + kc * 256 + k];
        }
        for (int i = tid; i < CLS * 256; i += 320) {
            int r = i >> 8, k = i & 255;
            sw[r][k] = wcls[(long)r * CC + kc * 256 + k];
        }
        __syncthreads();
        #pragma unroll
        for (int sub = 0; sub < 8; ++sub) {
            float part = 0.f;
            #pragma unroll
            for (int k = 0; k < 32; ++k)
                part += se[p][sub * 32 + k] * sw[c][sub * 32 + k];
            dacc += (double)part;
        }
        __syncthreads();
    }
    float cv = (float)fmax(dacc, 0.0);
    out[OFF_CAS + (long)(n0 + p) * CLS + c] = cv;
    sc[p][c] = cv;
    __syncthreads();
    if (tid < 16) {
        double a = 0.0;
        #pragma unroll
        for (int j = 0; j < CLS; ++j) a += (double)sc[tid][j];
        out[OFF_ACT + n0 + tid] = (float)a;
    }
}

// ---------------- monotonic float <-> uint ----------------
__device__ __forceinline__ unsigned monof(float v) {
    unsigned b = __float_as_uint(v);
    return (b & 0x80000000u) ? ~b : (b | 0x80000000u);
}
__device__ __forceinline__ float unmonof(unsigned m) {
    unsigned b = (m & 0x80000000u) ? (m ^ 0x80000000u) : ~m;
    return __uint_as_float(b);
}

// descending bitonic sort of 1024 u64 keys; thread-count-agnostic network
__device__ void sortkeys_desc(unsigned long long* s, int tid, int nthr) {
    for (int k = 2; k <= 1024; k <<= 1) {
        for (int j = k >> 1; j > 0; j >>= 1) {
            __syncthreads();
            for (int i = tid; i < 1024; i += nthr) {
                int ixj = i ^ j;
                if (ixj > i) {
                    bool up = ((i & k) == 0);
                    unsigned long long a = s[i], c = s[ixj];
                    if ((a < c) == up) { s[i] = c; s[ixj] = a; }
                }
            }
        }
    }
    __syncthreads();
}

// ---------------- per-batch analysis (512 threads) ----------------
__global__ __launch_bounds__(512)
void analysis_kernel(float* __restrict__ out) {
    __shared__ float act[TT];
    __shared__ float binv[TT];
    __shared__ unsigned long long keys[1024];
    __shared__ float s_med, s_max;

    const int b = blockIdx.x, tid = threadIdx.x;
    const int NT = 512;
    const float* actg = out + OFF_ACT + (long)b * TT;
    for (int t = tid; t < TT; t += NT) act[t] = actg[t];
    __syncthreads();

    for (int i = tid; i < 1024; i += NT)
        keys[i] = (i < TT) ? (((unsigned long long)monof(act[i]) << 32) | (unsigned)(1023 - i)) : 0ull;
    __syncthreads();
    sortkeys_desc(keys, tid, NT);
    if (tid == 0) {
        s_max = unmonof((unsigned)(keys[0] >> 32));
        s_med = 0.5f * (unmonof((unsigned)(keys[374] >> 32)) +
                        unmonof((unsigned)(keys[375] >> 32)));
    }
    for (int r = tid; r < KNB; r += NT) {
        int t = 1023 - (int)(keys[r] & 1023u);
        g_sel_idx[(0 * BB + b) * KNB + r] = t;
        out[OFF_IDX + (long)b * KNB + r] = (float)t;
    }
    __syncthreads();
    const float med = s_med, mx = s_max;
    for (int t = tid; t < TT; t += NT) binv[t] = (act[t] > med) ? 1.f : 0.f;

    for (int i = tid; i < 1024; i += NT)
        keys[i] = (i < TT) ? (((unsigned long long)monof(mx - act[i]) << 32) | (unsigned)(1023 - i)) : 0ull;
    __syncthreads();
    sortkeys_desc(keys, tid, NT);
    for (int r = tid; r < KNB; r += NT)
        g_sel_idx[(1 * BB + b) * KNB + r] = 1023 - (int)(keys[r] & 1023u);
    __syncthreads();

    for (int i = tid; i < 1024; i += NT) {
        float v = 0.f;
        if (i < TT) {
            int t = i;
            float e3 = 0.f, e6 = 0.f;
            if (t >= 1 && t <= TT - 2)
                e3 = fminf(binv[t - 1], fminf(binv[t], binv[t + 1]));
            if (t >= 3 && t <= TT - 3) {
                float m = binv[t - 3];
                m = fminf(m, binv[t - 2]); m = fminf(m, binv[t - 1]);
                m = fminf(m, binv[t]);     m = fminf(m, binv[t + 1]);
                m = fminf(m, binv[t + 2]);
                e6 = m;
            }
            v = act[t] * (e3 - e6);
        }
        keys[i] = (i < TT) ? (((unsigned long long)monof(v) << 32) | (unsigned)(1023 - i)) : 0ull;
    }
    __syncthreads();
    sortkeys_desc(keys, tid, NT);
    for (int r = tid; r < KB2; r += NT)
        g_sel_idx[(2 * BB + b) * KNB + r] = 1023 - (int)(keys[r] & 1023u);
    __syncthreads();

    for (int i = tid; i < 1024; i += NT) {
        float v = 0.f;
        if (i < TT) {
            int t = i;
            float d3 = 0.f, d6 = 0.f;
            #pragma unroll
            for (int dt = -1; dt <= 1; ++dt) {
                int u = t + dt;
                if (u >= 0 && u < TT) d3 = fmaxf(d3, binv[u]);
            }
            #pragma unroll
            for (int dt = -2; dt <= 3; ++dt) {
                int u = t + dt;
                if (u >= 0 && u < TT) d6 = fmaxf(d6, binv[u]);
            }
            v = act[t] * (d6 - d3);
        }
        keys[i] = (i < TT) ? (((unsigned long long)monof(v) << 32) | (unsigned)(1023 - i)) : 0ull;
    }
    __syncthreads();
    sortkeys_desc(keys, tid, NT);
    for (int r = tid; r < KB2; r += NT)
        g_sel_idx[(3 * BB + b) * KNB + r] = 1023 - (int)(keys[r] & 1023u);
}

// ---------------- gathers ----------------
__global__ void gather_kernel(float* __restrict__ out) {
    const int rowsPerB = KNB + KNB + KB2 + KB2;
    const int b = blockIdx.x / rowsPerB;
    int r = blockIdx.x % rowsPerB;
    int arr, rr; long dstOff; int kcnt;
    if (r < KNB)                { arr = 0; rr = r;                 dstOff = OFF_EA; kcnt = KNB; }
    else if (r < 2 * KNB)       { arr = 1; rr = r - KNB;           dstOff = OFF_EB; kcnt = KNB; }
    else if (r < 2 * KNB + KB2) { arr = 2; rr = r - 2 * KNB;       dstOff = OFF_HA; kcnt = KB2; }
    else                        { arr = 3; rr = r - 2 * KNB - KB2; dstOff = OFF_HB; kcnt = KB2; }
    const int tsel = g_sel_idx[(arr * BB + b) * KNB + rr];
    const float* src = out + OFF_EMB + ((long)b * TT + tsel) * CC;
    float* dst = out + dstOff + ((long)b * kcnt + rr) * CC;
    const int tid = threadIdx.x;
    for (int i = tid * 4; i < CC; i += 256 * 4) {
        *(float4*)(dst + i) = *(const float4*)(src + i);
    }
}

// ---------------- ascending bitonic float sort (thread-agnostic) ----------
__device__ inline void bitonic1024(float* s, int tid, int nthr) {
    for (int k = 2; k <= 1024; k <<= 1) {
        for (int j = k >> 1; j > 0; j >>= 1) {
            __syncthreads();
            for (int i = tid; i < 1024; i += nthr) {
                int ixj = i ^ j;
                if (ixj > i) {
                    bool up = ((i & k) == 0);
                    float a = s[i], c = s[ixj];
                    if ((a > c) == up) { s[i] = c; s[ixj] = a; }
                }
            }
        }
    }
    __syncthreads();
}

__global__ __launch_bounds__(512)
void cls_topk_kernel(const float* __restrict__ out) {
    __shared__ float sbuf[1024];
    __shared__ float rv[512];
    const int b = blockIdx.x / CLS, cls = blockIdx.x % CLS;
    const int tid = threadIdx.x;
    const int NT = 512;
    for (int i = tid; i < 1024; i += NT)
        sbuf[i] = (i < TT) ? out[OFF_CAS + ((long)(b * TT + i)) * CLS + cls] : -FLT_MAX;
    __syncthreads();
    bitonic1024(sbuf, tid, NT);
    float s = 0.f;
    for (int i = 1024 - KNB + tid; i < 1024; i += NT) s += sbuf[i];
    rv[tid] = s;
    __syncthreads();
    for (int st = 256; st > 0; st >>= 1) {
        if (tid < st) rv[tid] += rv[tid + st];
        __syncthreads();
    }
    if (tid == 0) g_cls_mean[b * CLS + cls] = rv[0] / (float)KNB;
}

__global__ void softmax_kernel(float* __restrict__ out) {
    const int b = blockIdx.x;
    const int lane = threadIdx.x;
    float v = (lane < CLS) ? g_cls_mean[b * CLS + lane] : -FLT_MAX;
    float m = v;
    #pragma unroll
    for (int o = 16; o > 0; o >>= 1) m = fmaxf(m, __shfl_xor_sync(0xffffffffu, m, o));
    float e = (lane < CLS) ? expf(v - m) : 0.f;
    float s = e;
    #pragma unroll
    for (int o = 16; o > 0; o >>= 1) s += __shfl_xor_sync(0xffffffffu, s, o);
    if (lane < CLS) out[OFF_VS + b * CLS + lane] = e / s;
}

// ---------------- launch ----------------
extern "C" void kernel_launch(void* const* d_in, const int* in_sizes, int n_in,
                              void* d_out, int out_size) {
    const float* x      = (const float*)d_in[0];
    const float* w_rgb  = (const float*)d_in[1];
    const float* b_rgb  = (const float*)d_in[2];
    const float* w_flow = (const float*)d_in[3];
    const float* b_flow = (const float*)d_in[4];
    const float* w_cls  = (const float*)d_in[5];
    float* out = (float*)d_out;

    const int smem = NST * STG + 1024;   // 132096
    cudaFuncSetAttribute(conv_mma_kernel,
                         cudaFuncAttributeMaxDynamicSharedMemorySize, smem);

    pack_x_kernel<<<XROWS, 256>>>(x);
    pack_w_kernel<<<CC, 256>>>(w_rgb, 0);
    pack_w_kernel<<<CC, 256>>>(w_flow, 1);

    dim3 cg(BB * 6, CC / 128);   // 96 x 16
    conv_mma_kernel<<<cg, 512, smem>>>(b_rgb,  out + OFF_EMB, 0, 0);
    conv_mma_kernel<<<cg, 512, smem>>>(b_flow, out + OFF_EMB, 1, 1);

    cas_gemm_kernel<<<NPOS / 16, 320>>>(w_cls, out);
    analysis_kernel<<<BB, 512>>>(out);
    gather_kernel<<<BB * (KNB + KNB + KB2 + KB2), 256>>>(out);
    cls_topk_kernel<<<BB * CLS, 512>>>(out);
    softmax_kernel<<<BB, 32>>>(out);
}

// round 17
// speedup vs baseline: 2.3229x; 1.0352x over previous
#include <cuda_runtime.h>
#include <cuda_fp16.h>
#include <float.h>
#include <math.h>
#include <stdint.h>

// ---------------- problem constants ----------------
constexpr int BB   = 16;
constexpr int TT   = 750;
constexpr int CC   = 2048;
constexpr int CIN  = 1024;
constexpr int CLS  = 20;
constexpr int NPOS = BB * TT;
constexpr int KNB  = 150;
constexpr int KB2  = 37;
constexpr int KW   = 3 * CIN;          // 3072
constexpr int TPAD = 768;
constexpr int XROWS = BB * TPAD;       // 12288

// output layout (concatenated f32)
constexpr long OFF_VS  = 0;
constexpr long OFF_EA  = OFF_VS  + (long)BB * CLS;
constexpr long OFF_EB  = OFF_EA  + (long)BB * KNB * CC;
constexpr long OFF_HA  = OFF_EB  + (long)BB * KNB * CC;
constexpr long OFF_HB  = OFF_HA  + (long)BB * KB2 * CC;
constexpr long OFF_IDX = OFF_HB  + (long)BB * KB2 * CC;
constexpr long OFF_ACT = OFF_IDX + (long)BB * KNB;
constexpr long OFF_CAS = OFF_ACT + (long)NPOS;
constexpr long OFF_EMB = OFF_CAS + (long)NPOS * CLS;

// ---------------- device scratch ----------------
__device__ __half g_xb[4][XROWS][CIN];     // x planes: hi/lo per stream
__device__ __half g_wb[4][CC][KW];         // w planes: hi/lo per stream (x256)
__device__ int   g_sel_idx[4 * BB * KNB];
__device__ float g_cls_mean[BB * CLS];

// ---------------- PTX helpers ----------------
__device__ __forceinline__ uint32_t s2u(const void* p) {
    uint32_t a;
    asm("{ .reg .u64 t; cvta.to.shared.u64 t, %1; cvt.u32.u64 %0, t; }" : "=r"(a) : "l"(p));
    return a;
}
__device__ __forceinline__ void cp16(uint32_t dst, const void* src, int srcsz) {
    asm volatile("cp.async.cg.shared.global [%0], [%1], 16, %2;"
                 :: "r"(dst), "l"(src), "r"(srcsz) : "memory");
}

#define LDSM4(r0, r1, r2, r3, addr)                                          \
    asm volatile("ldmatrix.sync.aligned.m8n8.x4.shared.b16 {%0,%1,%2,%3}, [%4];" \
        : "=r"(r0), "=r"(r1), "=r"(r2), "=r"(r3) : "r"(addr))

#define MMAH(D, A, B)                                                        \
    asm volatile("mma.sync.aligned.m16n8k16.row.col.f32.f16.f16.f32 "        \
        "{%0,%1,%2,%3}, {%4,%5,%6,%7}, {%8,%9}, {%0,%1,%2,%3};"              \
        : "+f"((D)[0]), "+f"((D)[1]), "+f"((D)[2]), "+f"((D)[3])             \
        : "r"((A)[0]), "r"((A)[1]), "r"((A)[2]), "r"((A)[3]),                \
          "r"((B)[0]), "r"((B)[1]))

#define MMAHZ(D, A, B)                                                       \
    asm volatile("mma.sync.aligned.m16n8k16.row.col.f32.f16.f16.f32 "        \
        "{%0,%1,%2,%3}, {%4,%5,%6,%7}, {%8,%9}, {%10,%10,%10,%10};"          \
        : "=f"((D)[0]), "=f"((D)[1]), "=f"((D)[2]), "=f"((D)[3])             \
        : "r"((A)[0]), "r"((A)[1]), "r"((A)[2]), "r"((A)[3]),                \
          "r"((B)[0]), "r"((B)[1]), "f"(0.f))

#define SWZ(r, g) (((((g) ^ (((r) >> 1) & 3)) & 3) << 4))

// ---------------- split helpers ----------------
__device__ __forceinline__ void split2h(float v, __half& h0, __half& h1) {
    h0 = __float2half(v);
    h1 = __float2half(v - __half2float(h0));
}

// ---------------- pack x into 2 fp16 planes per stream ----------------
__global__ void pack_x_kernel(const float* __restrict__ x) {
    const int row = blockIdx.x;               // 0..12287
    const int b = row / TPAD, p = row % TPAD;
    const int t = p - 1;
    const bool valid = (t >= 0 && t < TT);
    const int c0 = threadIdx.x * 8;
    const int s = c0 >> 10, i0 = c0 & 1023;

    __half v0[8], v1[8];
    if (valid) {
        const float* src = x + ((long)(b * TT + t)) * CC + c0;
        float4 a = *(const float4*)src;
        float4 bb = *(const float4*)(src + 4);
        float v[8] = {a.x, a.y, a.z, a.w, bb.x, bb.y, bb.z, bb.w};
        #pragma unroll
        for (int j = 0; j < 8; ++j) split2h(v[j], v0[j], v1[j]);
    } else {
        #pragma unroll
        for (int j = 0; j < 8; ++j) { v0[j] = __float2half(0.f); v1[j] = v0[j]; }
    }
    *(uint4*)&g_xb[s * 2 + 0][row][i0] = *(uint4*)v0;
    *(uint4*)&g_xb[s * 2 + 1][row][i0] = *(uint4*)v1;
}

// ---------------- pack w (scaled by 256), both streams in one launch ------
__global__ void pack_w_kernel(const float* __restrict__ w_rgb,
                              const float* __restrict__ w_flow) {
    const int blk = blockIdx.x;               // 0..2*CC-1
    const int str = blk >> 11, c = blk & 2047;
    const float* src = (str ? w_flow : w_rgb) + (long)c * KW;
    for (int idx = threadIdx.x; idx < KW; idx += blockDim.x) {
        int tau = idx / CIN, i = idx % CIN;
        float v = src[i * 3 + tau] * 256.f;
        __half h0, h1;
        split2h(v, h0, h1);
        g_wb[str * 2 + 0][c][idx] = h0;
        g_wb[str * 2 + 1][c][idx] = h1;
    }
}

// ---------------- zero the emb region (prep for atomic accumulation) ------
__global__ void zero_emb_kernel(float* __restrict__ emb) {
    const long i = ((long)blockIdx.x * 256 + threadIdx.x) * 4;
    if (i < (long)NPOS * CC)
        *(float4*)(emb + i) = make_float4(0.f, 0.f, 0.f, 0.f);
}

// ---------------- HMMA conv kernel: both streams in ONE launch ------------
// grid (96, 16, 2), 512 threads. z = stream. Epilogue: atomicAdd of
// relu(acc/256 + bias) into zero-initialized emb — exactly two commutative
// adds per element onto exact zero => bitwise identical to store-then-add.
constexpr int A_PLANE = 8192;
constexpr int B_PLANE = 8192;
constexpr int B_OFF   = 2 * A_PLANE;      // 16384
constexpr int STG     = B_OFF + 2 * B_PLANE;  // 32768
constexpr int NKB     = 96;
constexpr int NST     = 4;

__device__ __forceinline__ void load_stage(uint32_t st, int kb, int b, int itile,
                                           int c0, int str, int tid) {
    const int tau = kb >> 5;
    const int k0  = (kb & 31) * 32;
    const int row0 = b * TPAD + itile * 128 + tau;
    const int r = tid >> 2, g = tid & 3;   // 512 threads: one chunk per plane
    #pragma unroll
    for (int p = 0; p < 2; ++p) {
        const __half* xp = &g_xb[str * 2 + p][0][0];
        uint32_t dst = st + p * A_PLANE + r * 64 + SWZ(r, g);
        int grow = row0 + r;
        cp16(dst, xp + (long)grow * CIN + k0 + g * 8, grow < XROWS ? 16 : 0);
    }
    #pragma unroll
    for (int p = 0; p < 2; ++p) {
        const __half* wp = &g_wb[str * 2 + p][0][0];
        uint32_t dst = st + B_OFF + p * B_PLANE + r * 64 + SWZ(r, g);
        cp16(dst, wp + (long)(c0 + r) * KW + tau * CIN + k0 + g * 8, 16);
    }
    asm volatile("cp.async.commit_group;" ::: "memory");
}

__global__ __launch_bounds__(512, 1)
void conv_mma_kernel(const float* __restrict__ brgb, const float* __restrict__ bflow,
                     float* __restrict__ emb) {
    extern __shared__ char dsm[];
    const uint32_t sb = (s2u(dsm) + 1023u) & ~1023u;

    const int tid = threadIdx.x, lane = tid & 31, wid = tid >> 5;
    const int ptile = blockIdx.x;          // 0..95
    const int b = ptile / 6, itile = ptile % 6;
    const int c0 = blockIdx.y * 128;
    const int str = blockIdx.z;
    const float* bias = str ? bflow : brgb;
    const int m0 = (wid >> 2) * 32;        // warp tile: 32 x 32 (4m x 4n)
    const int n0 = (wid & 3) * 32;

    float acc[2][4][4];
    #pragma unroll
    for (int i = 0; i < 2; ++i)
        #pragma unroll
        for (int j = 0; j < 4; ++j)
            #pragma unroll
            for (int k = 0; k < 4; ++k) acc[i][j][k] = 0.f;

    load_stage(sb + 0 * STG, 0, b, itile, c0, str, tid);
    load_stage(sb + 1 * STG, 1, b, itile, c0, str, tid);
    load_stage(sb + 2 * STG, 2, b, itile, c0, str, tid);

    for (int kb = 0; kb < NKB; ++kb) {
        if (kb < NKB - 3) asm volatile("cp.async.wait_group 2;" ::: "memory");
        else              asm volatile("cp.async.wait_group 0;" ::: "memory");
        __syncthreads();

        if (kb + 3 < NKB)
            load_stage(sb + ((kb + 3) & 3) * STG, kb + 3, b, itile, c0, str, tid);

        const uint32_t St = sb + (kb & 3) * STG;
        #pragma unroll
        for (int ks = 0; ks < 2; ++ks) {
            uint32_t bfr[2][4][2];
            #pragma unroll
            for (int p = 0; p < 2; ++p) {
                #pragma unroll
                for (int j = 0; j < 2; ++j) {
                    int r = n0 + (lane & 7) + ((lane >> 4) << 3) + j * 16;
                    int g = ks * 2 + ((lane >> 3) & 1);
                    uint32_t ad = St + B_OFF + p * B_PLANE + r * 64 + SWZ(r, g);
                    LDSM4(bfr[p][j * 2][0], bfr[p][j * 2][1],
                          bfr[p][j * 2 + 1][0], bfr[p][j * 2 + 1][1], ad);
                }
            }
            #pragma unroll
            for (int mi = 0; mi < 2; ++mi) {
                uint32_t a0[4], a1[4];
                {
                    int r = m0 + mi * 16 + (lane & 15);
                    int g = ks * 2 + (lane >> 4);
                    uint32_t ad0 = St + 0 * A_PLANE + r * 64 + SWZ(r, g);
                    uint32_t ad1 = St + 1 * A_PLANE + r * 64 + SWZ(r, g);
                    LDSM4(a0[0], a0[1], a0[2], a0[3], ad0);
                    LDSM4(a1[0], a1[1], a1[2], a1[3], ad1);
                }
                float accd[4][4];
                #pragma unroll
                for (int ni = 0; ni < 4; ++ni) {
                    // smallest terms first, dominant last (bias control)
                    MMAHZ(accd[ni], a1, bfr[0][ni]);   // x1*w0
                    MMAH (accd[ni], a0, bfr[1][ni]);   // x0*w1
                    MMAH (accd[ni], a0, bfr[0][ni]);   // x0*w0 LAST
                }
                #pragma unroll
                for (int ni = 0; ni < 4; ++ni)
                    #pragma unroll
                    for (int q = 0; q < 4; ++q)
                        acc[mi][ni][q] += accd[ni][q];  // RN drain
            }
        }
    }

    // epilogue: relu(acc/256 + bias) atomically added into zeroed emb
    constexpr float IS = 1.f / 256.f;
    #pragma unroll
    for (int ni = 0; ni < 4; ++ni) {
        const int col = c0 + n0 + ni * 8 + (lane & 3) * 2;
        const float b0v = bias[col], b1v = bias[col + 1];
        #pragma unroll
        for (int mi = 0; mi < 2; ++mi) {
            const int t0 = itile * 128 + m0 + mi * 16 + (lane >> 2);
            if (t0 < TT) {
                float* p = emb + ((long)(b * TT + t0)) * CC + col;
                atomicAdd(p,     fmaxf(acc[mi][ni][0] * IS + b0v, 0.f));
                atomicAdd(p + 1, fmaxf(acc[mi][ni][1] * IS + b1v, 0.f));
            }
            const int t1 = t0 + 8;
            if (t1 < TT) {
                float* p = emb + ((long)(b * TT + t1)) * CC + col;
                atomicAdd(p,     fmaxf(acc[mi][ni][2] * IS + b0v, 0.f));
                atomicAdd(p + 1, fmaxf(acc[mi][ni][3] * IS + b1v, 0.f));
            }
        }
    }
}

// ---------------- cas mini-GEMM: fp32 chunks + fp64 combine ----------------
constexpr int SE_S = 257, SW_S = 261;
__global__ __launch_bounds__(320)
void cas_gemm_kernel(const float* __restrict__ wcls, float* __restrict__ out) {
    __shared__ float se[16][SE_S];
    __shared__ float sw[CLS][SW_S];
    __shared__ float sc[16][CLS];
    const int tid = threadIdx.x;
    const int n0 = blockIdx.x * 16;
    const int p = tid / CLS, c = tid % CLS;
    const float* embg = out + OFF_EMB;

    double dacc = 0.0;
    for (int kc = 0; kc < 8; ++kc) {
        for (int i = tid; i < 16 * 256; i += 320) {
            int r = i >> 8, k = i & 255;
            se[r][k] = embg[(long)(n0 + r) * CC + kc * 256 + k];
        }
        for (int i = tid; i < CLS * 256; i += 320) {
            int r = i >> 8, k = i & 255;
            sw[r][k] = wcls[(long)r * CC + kc * 256 + k];
        }
        __syncthreads();
        #pragma unroll
        for (int sub = 0; sub < 8; ++sub) {
            float part = 0.f;
            #pragma unroll
            for (int k = 0; k < 32; ++k)
                part += se[p][sub * 32 + k] * sw[c][sub * 32 + k];
            dacc += (double)part;
        }
        __syncthreads();
    }
    float cv = (float)fmax(dacc, 0.0);
    out[OFF_CAS + (long)(n0 + p) * CLS + c] = cv;
    sc[p][c] = cv;
    __syncthreads();
    if (tid < 16) {
        double a = 0.0;
        #pragma unroll
        for (int j = 0; j < CLS; ++j) a += (double)sc[tid][j];
        out[OFF_ACT + n0 + tid] = (float)a;
    }
}

// ---------------- monotonic float <-> uint ----------------
__device__ __forceinline__ unsigned monof(float v) {
    unsigned b = __float_as_uint(v);
    return (b & 0x80000000u) ? ~b : (b | 0x80000000u);
}
__device__ __forceinline__ float unmonof(unsigned m) {
    unsigned b = (m & 0x80000000u) ? (m ^ 0x80000000u) : ~m;
    return __uint_as_float(b);
}

// descending bitonic sort of 1024 u64 keys; thread-count-agnostic network
__device__ void sortkeys_desc(unsigned long long* s, int tid, int nthr) {
    for (int k = 2; k <= 1024; k <<= 1) {
        for (int j = k >> 1; j > 0; j >>= 1) {
            __syncthreads();
            for (int i = tid; i < 1024; i += nthr) {
                int ixj = i ^ j;
                if (ixj > i) {
                    bool up = ((i & k) == 0);
                    unsigned long long a = s[i], c = s[ixj];
                    if ((a < c) == up) { s[i] = c; s[ixj] = a; }
                }
            }
        }
    }
    __syncthreads();
}

// ---------------- per-batch analysis (512 threads) ----------------
__global__ __launch_bounds__(512)
void analysis_kernel(float* __restrict__ out) {
    __shared__ float act[TT];
    __shared__ float binv[TT];
    __shared__ unsigned long long keys[1024];
    __shared__ float s_med, s_max;

    const int b = blockIdx.x, tid = threadIdx.x;
    const int NT = 512;
    const float* actg = out + OFF_ACT + (long)b * TT;
    for (int t = tid; t < TT; t += NT) act[t] = actg[t];
    __syncthreads();

    for (int i = tid; i < 1024; i += NT)
        keys[i] = (i < TT) ? (((unsigned long long)monof(act[i]) << 32) | (unsigned)(1023 - i)) : 0ull;
    __syncthreads();
    sortkeys_desc(keys, tid, NT);
    if (tid == 0) {
        s_max = unmonof((unsigned)(keys[0] >> 32));
        s_med = 0.5f * (unmonof((unsigned)(keys[374] >> 32)) +
                        unmonof((unsigned)(keys[375] >> 32)));
    }
    for (int r = tid; r < KNB; r += NT) {
        int t = 1023 - (int)(keys[r] & 1023u);
        g_sel_idx[(0 * BB + b) * KNB + r] = t;
        out[OFF_IDX + (long)b * KNB + r] = (float)t;
    }
    __syncthreads();
    const float med = s_med, mx = s_max;
    for (int t = tid; t < TT; t += NT) binv[t] = (act[t] > med) ? 1.f : 0.f;

    for (int i = tid; i < 1024; i += NT)
        keys[i] = (i < TT) ? (((unsigned long long)monof(mx - act[i]) << 32) | (unsigned)(1023 - i)) : 0ull;
    __syncthreads();
    sortkeys_desc(keys, tid, NT);
    for (int r = tid; r < KNB; r += NT)
        g_sel_idx[(1 * BB + b) * KNB + r] = 1023 - (int)(keys[r] & 1023u);
    __syncthreads();

    for (int i = tid; i < 1024; i += NT) {
        float v = 0.f;
        if (i < TT) {
            int t = i;
            float e3 = 0.f, e6 = 0.f;
            if (t >= 1 && t <= TT - 2)
                e3 = fminf(binv[t - 1], fminf(binv[t], binv[t + 1]));
            if (t >= 3 && t <= TT - 3) {
                float m = binv[t - 3];
                m = fminf(m, binv[t - 2]); m = fminf(m, binv[t - 1]);
                m = fminf(m, binv[t]);     m = fminf(m, binv[t + 1]);
                m = fminf(m, binv[t + 2]);
                e6 = m;
            }
            v = act[t] * (e3 - e6);
        }
        keys[i] = (i < TT) ? (((unsigned long long)monof(v) << 32) | (unsigned)(1023 - i)) : 0ull;
    }
    __syncthreads();
    sortkeys_desc(keys, tid, NT);
    for (int r = tid; r < KB2; r += NT)
        g_sel_idx[(2 * BB + b) * KNB + r] = 1023 - (int)(keys[r] & 1023u);
    __syncthreads();

    for (int i = tid; i < 1024; i += NT) {
        float v = 0.f;
        if (i < TT) {
            int t = i;
            float d3 = 0.f, d6 = 0.f;
            #pragma unroll
            for (int dt = -1; dt <= 1; ++dt) {
                int u = t + dt;
                if (u >= 0 && u < TT) d3 = fmaxf(d3, binv[u]);
            }
            #pragma unroll
            for (int dt = -2; dt <= 3; ++dt) {
                int u = t + dt;
                if (u >= 0 && u < TT) d6 = fmaxf(d6, binv[u]);
            }
            v = act[t] * (d6 - d3);
        }
        keys[i] = (i < TT) ? (((unsigned long long)monof(v) << 32) | (unsigned)(1023 - i)) : 0ull;
    }
    __syncthreads();
    sortkeys_desc(keys, tid, NT);
    for (int r = tid; r < KB2; r += NT)
        g_sel_idx[(3 * BB + b) * KNB + r] = 1023 - (int)(keys[r] & 1023u);
}

// ---------------- gathers ----------------
__global__ void gather_kernel(float* __restrict__ out) {
    const int rowsPerB = KNB + KNB + KB2 + KB2;
    const int b = blockIdx.x / rowsPerB;
    int r = blockIdx.x % rowsPerB;
    int arr, rr; long dstOff; int kcnt;
    if (r < KNB)                { arr = 0; rr = r;                 dstOff = OFF_EA; kcnt = KNB; }
    else if (r < 2 * KNB)       { arr = 1; rr = r - KNB;           dstOff = OFF_EB; kcnt = KNB; }
    else if (r < 2 * KNB + KB2) { arr = 2; rr = r - 2 * KNB;       dstOff = OFF_HA; kcnt = KB2; }
    else                        { arr = 3; rr = r - 2 * KNB - KB2; dstOff = OFF_HB; kcnt = KB2; }
    const int tsel = g_sel_idx[(arr * BB + b) * KNB + rr];
    const float* src = out + OFF_EMB + ((long)b * TT + tsel) * CC;
    float* dst = out + dstOff + ((long)b * kcnt + rr) * CC;
    const int tid = threadIdx.x;
    for (int i = tid * 4; i < CC; i += 256 * 4) {
        *(float4*)(dst + i) = *(const float4*)(src + i);
    }
}

// ---------------- ascending bitonic float sort (thread-agnostic) ----------
__device__ inline void bitonic1024(float* s, int tid, int nthr) {
    for (int k = 2; k <= 1024; k <<= 1) {
        for (int j = k >> 1; j > 0; j >>= 1) {
            __syncthreads();
            for (int i = tid; i < 1024; i += nthr) {
                int ixj = i ^ j;
                if (ixj > i) {
                    bool up = ((i & k) == 0);
                    float a = s[i], c = s[ixj];
                    if ((a > c) == up) { s[i] = c; s[ixj] = a; }
                }
            }
        }
    }
    __syncthreads();
}

__global__ __launch_bounds__(512)
void cls_topk_kernel(const float* __restrict__ out) {
    __shared__ float sbuf[1024];
    __shared__ float rv[512];
    const int b = blockIdx.x / CLS, cls = blockIdx.x % CLS;
    const int tid = threadIdx.x;
    const int NT = 512;
    for (int i = tid; i < 1024; i += NT)
        sbuf[i] = (i < TT) ? out[OFF_CAS + ((long)(b * TT + i)) * CLS + cls] : -FLT_MAX;
    __syncthreads();
    bitonic1024(sbuf, tid, NT);
    float s = 0.f;
    for (int i = 1024 - KNB + tid; i < 1024; i += NT) s += sbuf[i];
    rv[tid] = s;
    __syncthreads();
    for (int st = 256; st > 0; st >>= 1) {
        if (tid < st) rv[tid] += rv[tid + st];
        __syncthreads();
    }
    if (tid == 0) g_cls_mean[b * CLS + cls] = rv[0] / (float)KNB;
}

__global__ void softmax_kernel(float* __restrict__ out) {
    const int b = blockIdx.x;
    const int lane = threadIdx.x;
    float v = (lane < CLS) ? g_cls_mean[b * CLS + lane] : -FLT_MAX;
    float m = v;
    #pragma unroll
    for (int o = 16; o > 0; o >>= 1) m = fmaxf(m, __shfl_xor_sync(0xffffffffu, m, o));
    float e = (lane < CLS) ? expf(v - m) : 0.f;
    float s = e;
    #pragma unroll
    for (int o = 16; o > 0; o >>= 1) s += __shfl_xor_sync(0xffffffffu, s, o);
    if (lane < CLS) out[OFF_VS + b * CLS + lane] = e / s;
}

// ---------------- launch ----------------
extern "C" void kernel_launch(void* const* d_in, const int* in_sizes, int n_in,
                              void* d_out, int out_size) {
    const float* x      = (const float*)d_in[0];
    const float* w_rgb  = (const float*)d_in[1];
    const float* b_rgb  = (const float*)d_in[2];
    const float* w_flow = (const float*)d_in[3];
    const float* b_flow = (const float*)d_in[4];
    const float* w_cls  = (const float*)d_in[5];
    float* out = (float*)d_out;

    const int smem = NST * STG + 1024;   // 132096
    cudaFuncSetAttribute(conv_mma_kernel,
                         cudaFuncAttributeMaxDynamicSharedMemorySize, smem);

    pack_x_kernel<<<XROWS, 256>>>(x);
    pack_w_kernel<<<2 * CC, 256>>>(w_rgb, w_flow);
    zero_emb_kernel<<<(int)(((long)NPOS * CC / 4 + 255) / 256), 256>>>(out + OFF_EMB);

    dim3 cg(BB * 6, CC / 128, 2);   // 96 x 16 x 2 — both streams, one launch
    conv_mma_kernel<<<cg, 512, smem>>>(b_rgb, b_flow, out + OFF_EMB);

    cas_gemm_kernel<<<NPOS / 16, 320>>>(w_cls, out);
    analysis_kernel<<<BB, 512>>>(out);
    gather_kernel<<<BB * (KNB + KNB + KB2 + KB2), 256>>>(out);
    cls_topk_kernel<<<BB * CLS, 512>>>(out);
    softmax_kernel<<<BB, 32>>>(out);
}